// round 2
// baseline (speedup 1.0000x reference)
#include <cuda_runtime.h>
#include <math.h>

#define NTOT 46080
#define DMODEL 192
#define MTOK 256
#define BDIM 256
#define NHEAD 8
#define DHEAD 24
#define DFFN 2048
#define LN_EPS 1e-5f

// ---------------- scratch (device globals; no allocation allowed) ----------------
__device__ float g_K[MTOK * DMODEL];
__device__ float g_V[MTOK * DMODEL];
__device__ float g_Q[NTOT * DMODEL];
__device__ float g_CTX[NTOT * DMODEL];
__device__ float g_X1[NTOT * DMODEL];

__device__ __forceinline__ float nan_to_num_f(float x) {
    if (isnan(x)) return 0.0f;
    if (isinf(x)) return x > 0.0f ? 3.402823466e38f : -3.402823466e38f;
    return x;
}

// ============================================================================
// Kernel 1: K = (box_feature + box_pos) @ Wk^T + bk ; V = box_feature @ Wv^T + bv
// ============================================================================
__global__ __launch_bounds__(256) void kv_kernel(
    const float* __restrict__ boxf, const float* __restrict__ boxp,
    const float* __restrict__ Wk, const float* __restrict__ bk,
    const float* __restrict__ Wv, const float* __restrict__ bv)
{
    __shared__ float Asf[64 * 17];
    __shared__ float Asp[64 * 17];
    __shared__ float Bsk[16 * 193];
    __shared__ float Bsv[16 * 193];
    const int t = threadIdx.x;
    const int m0 = blockIdx.x * 64;
    const int tx = t & 15, ty = t >> 4;

    float ak[4][12], av[4][12];
#pragma unroll
    for (int i = 0; i < 4; i++)
#pragma unroll
        for (int j = 0; j < 12; j++) { ak[i][j] = 0.f; av[i][j] = 0.f; }

    for (int kt = 0; kt < BDIM; kt += 16) {
        __syncthreads();
        for (int i = t; i < 64 * 16; i += 256) {
            int r = i >> 4, k = i & 15;
            Asf[r * 17 + k] = boxf[(m0 + r) * BDIM + kt + k];
            Asp[r * 17 + k] = boxp[(m0 + r) * BDIM + kt + k];
        }
        for (int i = t; i < 16 * DMODEL; i += 256) {
            int d = i >> 4, k = i & 15;
            Bsk[k * 193 + d] = Wk[d * BDIM + kt + k];
            Bsv[k * 193 + d] = Wv[d * BDIM + kt + k];
        }
        __syncthreads();
#pragma unroll
        for (int k = 0; k < 16; k++) {
            float af[4], aa[4], wkr[12], wvr[12];
#pragma unroll
            for (int i = 0; i < 4; i++) {
                af[i] = Asf[(ty * 4 + i) * 17 + k];
                aa[i] = af[i] + Asp[(ty * 4 + i) * 17 + k];
            }
#pragma unroll
            for (int j = 0; j < 12; j++) {
                wkr[j] = Bsk[k * 193 + tx * 12 + j];
                wvr[j] = Bsv[k * 193 + tx * 12 + j];
            }
#pragma unroll
            for (int i = 0; i < 4; i++)
#pragma unroll
                for (int j = 0; j < 12; j++) {
                    ak[i][j] = fmaf(aa[i], wkr[j], ak[i][j]);
                    av[i][j] = fmaf(af[i], wvr[j], av[i][j]);
                }
        }
    }
#pragma unroll
    for (int i = 0; i < 4; i++) {
        int m = m0 + ty * 4 + i;
#pragma unroll
        for (int j = 0; j < 12; j++) {
            int d = tx * 12 + j;
            g_K[m * DMODEL + d] = ak[i][j] + bk[d];
            g_V[m * DMODEL + d] = av[i][j] + bv[d];
        }
    }
}

// ============================================================================
// Kernel 2: Q = gather(src+pos) @ Wq^T + bq
// ============================================================================
__global__ __launch_bounds__(256) void qproj_kernel(
    const float* __restrict__ src, const float* __restrict__ pos,
    const int* __restrict__ vinds,
    const float* __restrict__ Wq, const float* __restrict__ bq)
{
    extern __shared__ float sm[];
    float* As = sm;                       // 64*193
    float* Bs = sm + 64 * 193;            // 32*193
    int* gI = (int*)(sm + 64 * 193 + 32 * 193); // 64
    const int t = threadIdx.x;
    const int r0 = blockIdx.x * 64;
    if (t < 64) gI[t] = vinds[r0 + t];
    __syncthreads();
    for (int i = t; i < 64 * DMODEL; i += 256) {
        int r = i / DMODEL, c = i % DMODEL;
        int g = gI[r];
        As[r * 193 + c] = src[g * DMODEL + c] + pos[g * DMODEL + c];
    }
    const int tx = t & 15, ty = t >> 4;
    float acc[4][12];
#pragma unroll
    for (int i = 0; i < 4; i++)
#pragma unroll
        for (int j = 0; j < 12; j++) acc[i][j] = 0.f;

    for (int kt = 0; kt < DMODEL; kt += 32) {
        __syncthreads();
        for (int i = t; i < 32 * DMODEL; i += 256) {
            int d = i >> 5, k = i & 31;
            Bs[k * 193 + d] = Wq[d * DMODEL + kt + k];
        }
        __syncthreads();
#pragma unroll 8
        for (int k = 0; k < 32; k++) {
            float a[4], b[12];
#pragma unroll
            for (int i = 0; i < 4; i++) a[i] = As[(ty * 4 + i) * 193 + kt + k];
#pragma unroll
            for (int j = 0; j < 12; j++) b[j] = Bs[k * 193 + tx * 12 + j];
#pragma unroll
            for (int i = 0; i < 4; i++)
#pragma unroll
                for (int j = 0; j < 12; j++)
                    acc[i][j] = fmaf(a[i], b[j], acc[i][j]);
        }
    }
#pragma unroll
    for (int i = 0; i < 4; i++) {
        int r = r0 + ty * 4 + i;
#pragma unroll
        for (int j = 0; j < 12; j++) {
            int d = tx * 12 + j;
            g_Q[r * DMODEL + d] = acc[i][j] + bq[d];
        }
    }
}

// ============================================================================
// Kernel 3: attention per (32-query tile, head).
// ============================================================================
__global__ __launch_bounds__(256) void attn_kernel(
    const int* __restrict__ vinds, const int* __restrict__ vcrd,
    const int* __restrict__ bcrd)
{
    extern __shared__ float sm[];
    float* Qs  = sm;                 // 32*25
    float* Khs = sm + 800;           // 256*25
    float* Vhs = sm + 800 + 6400;    // 256*25
    float* Ss  = sm + 800 + 12800;   // 32*257
    float* part = sm + 800 + 12800 + 8224; // 4*32*24
    int* qb = (int*)(sm + 800 + 12800 + 8224 + 3072); // 32
    int* bb = qb + 32;               // 256

    const int t = threadIdx.x;
    const int q0 = blockIdx.x * 32;
    const int h = blockIdx.y;

    if (t < 32) { int g = vinds[q0 + t]; qb[t] = vcrd[g * 4]; }
    // FIX (R1): all 256 threads cover all 256 box tokens (was t-32 -> bb[224..255] garbage)
    bb[t] = bcrd[t * 4];
    for (int i = t; i < 32 * DHEAD; i += 256) {
        int q = i / DHEAD, d = i % DHEAD;
        Qs[q * 25 + d] = g_Q[(q0 + q) * DMODEL + h * DHEAD + d];
    }
    for (int i = t; i < MTOK * DHEAD; i += 256) {
        int m = i / DHEAD, d = i % DHEAD;
        Khs[m * 25 + d] = g_K[m * DMODEL + h * DHEAD + d];
        Vhs[m * 25 + d] = g_V[m * DMODEL + h * DHEAD + d];
    }
    __syncthreads();

    // ---- phase B: scores (32x256), microtile 4q x 8m ----
    const int mg = t & 31, qg = t >> 5;
    float sc[4][8];
#pragma unroll
    for (int i = 0; i < 4; i++)
#pragma unroll
        for (int j = 0; j < 8; j++) sc[i][j] = 0.f;
#pragma unroll
    for (int k = 0; k < DHEAD; k++) {
        float a[4], b[8];
#pragma unroll
        for (int i = 0; i < 4; i++) a[i] = Qs[(qg * 4 + i) * 25 + k];
#pragma unroll
        for (int j = 0; j < 8; j++) b[j] = Khs[(mg + j * 32) * 25 + k];
#pragma unroll
        for (int i = 0; i < 4; i++)
#pragma unroll
            for (int j = 0; j < 8; j++) sc[i][j] = fmaf(a[i], b[j], sc[i][j]);
    }
    const float scale = 0.20412414523193154f; // 24^-0.5
    const float NEG_INF = -__int_as_float(0x7f800000);
#pragma unroll
    for (int i = 0; i < 4; i++) {
        int q = qg * 4 + i;
#pragma unroll
        for (int j = 0; j < 8; j++) {
            int m = mg + j * 32;
            float s = sc[i][j] * scale;
            if (qb[q] != bb[m]) s = NEG_INF;
            Ss[q * 257 + m] = s;
        }
    }
    __syncthreads();

    // ---- phase C: softmax per row (8 warps x 4 rows) ----
    {
        const int w = t >> 5, lane = t & 31;
        for (int rr = 0; rr < 4; rr++) {
            int q = w * 4 + rr;
            float v[8]; float mx = NEG_INF;
#pragma unroll
            for (int j = 0; j < 8; j++) {
                v[j] = Ss[q * 257 + lane + j * 32];
                mx = fmaxf(mx, v[j]);
            }
#pragma unroll
            for (int o = 16; o; o >>= 1) mx = fmaxf(mx, __shfl_xor_sync(0xffffffffu, mx, o));
            float ssum = 0.f;
#pragma unroll
            for (int j = 0; j < 8; j++) { v[j] = __expf(v[j] - mx); ssum += v[j]; }
#pragma unroll
            for (int o = 16; o; o >>= 1) ssum += __shfl_xor_sync(0xffffffffu, ssum, o);
            float inv = 1.0f / ssum;   // all-masked: NaN propagates like jax softmax
#pragma unroll
            for (int j = 0; j < 8; j++) Ss[q * 257 + lane + j * 32] = v[j] * inv;
        }
    }
    __syncthreads();

    // ---- phase D: ctx = P @ Vh ----
    {
        const int grp = t >> 6, u = t & 63;
        const int qg2 = u >> 2, dg = u & 3;
        float c2[2][6];
#pragma unroll
        for (int i = 0; i < 2; i++)
#pragma unroll
            for (int j = 0; j < 6; j++) c2[i][j] = 0.f;
        for (int mm = 0; mm < 64; mm++) {
            int m = grp * 64 + mm;
            float p0 = Ss[(qg2 * 2 + 0) * 257 + m];
            float p1 = Ss[(qg2 * 2 + 1) * 257 + m];
            float vv[6];
#pragma unroll
            for (int j = 0; j < 6; j++) vv[j] = Vhs[m * 25 + dg * 6 + j];
#pragma unroll
            for (int j = 0; j < 6; j++) {
                c2[0][j] = fmaf(p0, vv[j], c2[0][j]);
                c2[1][j] = fmaf(p1, vv[j], c2[1][j]);
            }
        }
#pragma unroll
        for (int i = 0; i < 2; i++)
#pragma unroll
            for (int j = 0; j < 6; j++)
                part[(grp * 32 + qg2 * 2 + i) * 24 + dg * 6 + j] = c2[i][j];
    }
    __syncthreads();
    for (int o = t; o < 32 * 24; o += 256) {
        int q = o / 24, d = o % 24;
        float s = part[q * 24 + d] + part[(32 + q) * 24 + d]
                + part[(64 + q) * 24 + d] + part[(96 + q) * 24 + d];
        g_CTX[(q0 + q) * DMODEL + h * DHEAD + d] = s;
    }
}

// ============================================================================
// Kernel 4: X1 = LN1( src + nan_to_num(CTX @ Wo^T + bo) ), scattered by vinds
// ============================================================================
__global__ __launch_bounds__(256) void oproj_ln1_kernel(
    const float* __restrict__ src, const int* __restrict__ vinds,
    const float* __restrict__ Wo, const float* __restrict__ bo,
    const float* __restrict__ ln1g, const float* __restrict__ ln1b)
{
    extern __shared__ float sm[];
    float* As = sm;                       // 64*193
    float* Bs = sm + 64 * 193;            // 32*193
    int* gI = (int*)(sm + 64 * 193 + 32 * 193);
    const int t = threadIdx.x;
    const int r0 = blockIdx.x * 64;
    if (t < 64) gI[t] = vinds[r0 + t];
    for (int i = t; i < 64 * DMODEL; i += 256) {
        int r = i / DMODEL, c = i % DMODEL;
        As[r * 193 + c] = g_CTX[(r0 + r) * DMODEL + c];
    }
    const int tx = t & 15, ty = t >> 4;
    float acc[4][12];
#pragma unroll
    for (int i = 0; i < 4; i++)
#pragma unroll
        for (int j = 0; j < 12; j++) acc[i][j] = 0.f;

    for (int kt = 0; kt < DMODEL; kt += 32) {
        __syncthreads();
        for (int i = t; i < 32 * DMODEL; i += 256) {
            int d = i >> 5, k = i & 31;
            Bs[k * 193 + d] = Wo[d * DMODEL + kt + k];
        }
        __syncthreads();
#pragma unroll 8
        for (int k = 0; k < 32; k++) {
            float a[4], b[12];
#pragma unroll
            for (int i = 0; i < 4; i++) a[i] = As[(ty * 4 + i) * 193 + kt + k];
#pragma unroll
            for (int j = 0; j < 12; j++) b[j] = Bs[k * 193 + tx * 12 + j];
#pragma unroll
            for (int i = 0; i < 4; i++)
#pragma unroll
                for (int j = 0; j < 12; j++)
                    acc[i][j] = fmaf(a[i], b[j], acc[i][j]);
        }
    }
    __syncthreads();
#pragma unroll
    for (int i = 0; i < 4; i++) {
        int r = ty * 4 + i;
#pragma unroll
        for (int j = 0; j < 12; j++) {
            int d = tx * 12 + j;
            As[r * 193 + d] = nan_to_num_f(acc[i][j] + bo[d]);
        }
    }
    __syncthreads();
    const int w = t >> 5, lane = t & 31;
    for (int rr = 0; rr < 8; rr++) {
        int r = w * 8 + rr;
        int g = gI[r];
        float v[6];
#pragma unroll
        for (int c = 0; c < 6; c++)
            v[c] = As[r * 193 + lane * 6 + c] + src[g * DMODEL + lane * 6 + c];
        float s = 0.f;
#pragma unroll
        for (int c = 0; c < 6; c++) s += v[c];
#pragma unroll
        for (int o = 16; o; o >>= 1) s += __shfl_xor_sync(0xffffffffu, s, o);
        float mean = s * (1.0f / 192.0f);
        float vs = 0.f;
#pragma unroll
        for (int c = 0; c < 6; c++) { float d0 = v[c] - mean; vs += d0 * d0; }
#pragma unroll
        for (int o = 16; o; o >>= 1) vs += __shfl_xor_sync(0xffffffffu, vs, o);
        float inv = rsqrtf(vs * (1.0f / 192.0f) + LN_EPS);
#pragma unroll
        for (int c = 0; c < 6; c++) {
            int d = lane * 6 + c;
            g_X1[g * DMODEL + d] = (v[c] - mean) * inv * ln1g[d] + ln1b[d];
        }
    }
}

// ============================================================================
// Kernel 5: out = LN2( x + relu(x @ W1^T + b1) @ W2^T + b2 )
// ============================================================================
__global__ __launch_bounds__(256) void ffn_ln2_kernel(
    const float* __restrict__ W1, const float* __restrict__ b1,
    const float* __restrict__ W2, const float* __restrict__ b2,
    const float* __restrict__ ln2g, const float* __restrict__ ln2b,
    float* __restrict__ out)
{
    extern __shared__ float sm[];
    float* Xs = sm;                   // 64*193
    float* Ws = sm + 64 * 193;        // 64*193
    float* Hs = sm + 2 * 64 * 193;    // 64*65
    const int t = threadIdx.x;
    const int r0 = blockIdx.x * 64;
    const int tx = t & 15, ty = t >> 4;

    for (int i = t; i < 64 * DMODEL; i += 256) {
        int r = i / DMODEL, c = i % DMODEL;
        Xs[r * 193 + c] = g_X1[(r0 + r) * DMODEL + c];
    }

    float y[4][12];
#pragma unroll
    for (int i = 0; i < 4; i++)
#pragma unroll
        for (int j = 0; j < 12; j++) y[i][j] = 0.f;

    for (int fc = 0; fc < DFFN; fc += 64) {
        __syncthreads();
        for (int i = t; i < 64 * DMODEL; i += 256) {
            int f = i / DMODEL, k = i % DMODEL;
            Ws[f * 193 + k] = W1[(fc + f) * DMODEL + k];
        }
        __syncthreads();
        float hacc[4][4];
#pragma unroll
        for (int i = 0; i < 4; i++)
#pragma unroll
            for (int j = 0; j < 4; j++) hacc[i][j] = 0.f;
#pragma unroll 8
        for (int k = 0; k < DMODEL; k++) {
            float a[4], b[4];
#pragma unroll
            for (int i = 0; i < 4; i++) a[i] = Xs[(ty * 4 + i) * 193 + k];
#pragma unroll
            for (int j = 0; j < 4; j++) b[j] = Ws[(tx * 4 + j) * 193 + k];
#pragma unroll
            for (int i = 0; i < 4; i++)
#pragma unroll
                for (int j = 0; j < 4; j++)
                    hacc[i][j] = fmaf(a[i], b[j], hacc[i][j]);
        }
#pragma unroll
        for (int i = 0; i < 4; i++)
#pragma unroll
            for (int j = 0; j < 4; j++)
                Hs[(ty * 4 + i) * 65 + tx * 4 + j] =
                    fmaxf(hacc[i][j] + b1[fc + tx * 4 + j], 0.f);
        __syncthreads();
        for (int i = t; i < 64 * DMODEL; i += 256) {
            int d = i >> 6, f = i & 63;
            Ws[f * 193 + d] = W2[d * DFFN + fc + f];
        }
        __syncthreads();
#pragma unroll 8
        for (int f = 0; f < 64; f++) {
            float hh[4], wv[12];
#pragma unroll
            for (int i = 0; i < 4; i++) hh[i] = Hs[(ty * 4 + i) * 65 + f];
#pragma unroll
            for (int j = 0; j < 12; j++) wv[j] = Ws[f * 193 + tx * 12 + j];
#pragma unroll
            for (int i = 0; i < 4; i++)
#pragma unroll
                for (int j = 0; j < 12; j++)
                    y[i][j] = fmaf(hh[i], wv[j], y[i][j]);
        }
    }
    __syncthreads();
#pragma unroll
    for (int i = 0; i < 4; i++) {
        int r = ty * 4 + i;
#pragma unroll
        for (int j = 0; j < 12; j++) {
            int d = tx * 12 + j;
            Ws[r * 193 + d] = y[i][j] + b2[d] + Xs[r * 193 + d];
        }
    }
    __syncthreads();
    const int w = t >> 5, lane = t & 31;
    for (int rr = 0; rr < 8; rr++) {
        int r = w * 8 + rr;
        float v[6];
#pragma unroll
        for (int c = 0; c < 6; c++) v[c] = Ws[r * 193 + lane * 6 + c];
        float s = 0.f;
#pragma unroll
        for (int c = 0; c < 6; c++) s += v[c];
#pragma unroll
        for (int o = 16; o; o >>= 1) s += __shfl_xor_sync(0xffffffffu, s, o);
        float mean = s * (1.0f / 192.0f);
        float vs = 0.f;
#pragma unroll
        for (int c = 0; c < 6; c++) { float d0 = v[c] - mean; vs += d0 * d0; }
#pragma unroll
        for (int o = 16; o; o >>= 1) vs += __shfl_xor_sync(0xffffffffu, vs, o);
        float inv = rsqrtf(vs * (1.0f / 192.0f) + LN_EPS);
#pragma unroll
        for (int c = 0; c < 6; c++) {
            int d = lane * 6 + c;
            out[(r0 + r) * DMODEL + d] = (v[c] - mean) * inv * ln2g[d] + ln2b[d];
        }
    }
}

// ============================================================================
extern "C" void kernel_launch(void* const* d_in, const int* in_sizes, int n_in,
                              void* d_out, int out_size)
{
    const float* src  = (const float*)d_in[0];
    const int*   vcrd = (const int*)d_in[1];
    const float* boxf = (const float*)d_in[2];
    const int*   bcrd = (const int*)d_in[3];
    const float* pos  = (const float*)d_in[4];
    const float* boxp = (const float*)d_in[5];
    const int*   vind = (const int*)d_in[6];
    const float* Wq = (const float*)d_in[7];
    const float* bq = (const float*)d_in[8];
    const float* Wk = (const float*)d_in[9];
    const float* bk = (const float*)d_in[10];
    const float* Wv = (const float*)d_in[11];
    const float* bv = (const float*)d_in[12];
    const float* Wo = (const float*)d_in[13];
    const float* bo = (const float*)d_in[14];
    const float* W1 = (const float*)d_in[15];
    const float* b1 = (const float*)d_in[16];
    const float* W2 = (const float*)d_in[17];
    const float* b2 = (const float*)d_in[18];
    const float* g1 = (const float*)d_in[19];
    const float* lb1 = (const float*)d_in[20];
    const float* g2 = (const float*)d_in[21];
    const float* lb2 = (const float*)d_in[22];
    float* out = (float*)d_out;

    const int SMEM_PROJ = (64 * 193 + 32 * 193) * 4 + 64 * 4;
    const int SMEM_ATTN = (800 + 6400 + 6400 + 8224 + 3072) * 4 + 288 * 4;
    const int SMEM_FFN  = (2 * 64 * 193 + 64 * 65) * 4;

    cudaFuncSetAttribute(qproj_kernel, cudaFuncAttributeMaxDynamicSharedMemorySize, SMEM_PROJ);
    cudaFuncSetAttribute(oproj_ln1_kernel, cudaFuncAttributeMaxDynamicSharedMemorySize, SMEM_PROJ);
    cudaFuncSetAttribute(attn_kernel, cudaFuncAttributeMaxDynamicSharedMemorySize, SMEM_ATTN);
    cudaFuncSetAttribute(ffn_ln2_kernel, cudaFuncAttributeMaxDynamicSharedMemorySize, SMEM_FFN);

    kv_kernel<<<MTOK / 64, 256>>>(boxf, boxp, Wk, bk, Wv, bv);
    qproj_kernel<<<NTOT / 64, 256, SMEM_PROJ>>>(src, pos, vind, Wq, bq);
    attn_kernel<<<dim3(NTOT / 32, NHEAD), 256, SMEM_ATTN>>>(vind, vcrd, bcrd);
    oproj_ln1_kernel<<<NTOT / 64, 256, SMEM_PROJ>>>(src, vind, Wo, bo, g1, lb1);
    ffn_ln2_kernel<<<NTOT / 64, 256, SMEM_FFN>>>(W1, b1, W2, b2, g2, lb2, out);
}

// round 5
// speedup vs baseline: 1.2535x; 1.2535x over previous
#include <cuda_runtime.h>
#include <cuda_bf16.h>
#include <math.h>
#include <stdint.h>

#define NTOT 46080
#define DMODEL 192
#define MTOK 256
#define BDIM 256
#define NHEAD 8
#define DHEAD 24
#define DFFN 2048
#define LN_EPS 1e-5f

// ---------------- scratch (device globals; no allocation allowed) ----------------
__device__ float g_K[MTOK * DMODEL];
__device__ float g_V[MTOK * DMODEL];
__device__ float g_Q[NTOT * DMODEL];
__device__ float g_CTX[NTOT * DMODEL];
__device__ float g_X1[NTOT * DMODEL];

// bf16 hi/lo split weights (prepared each launch by split_weights_kernel)
__device__ __nv_bfloat16 g_Wqh[DMODEL * DMODEL], g_Wql[DMODEL * DMODEL];
__device__ __nv_bfloat16 g_Woh[DMODEL * DMODEL], g_Wol[DMODEL * DMODEL];
__device__ __nv_bfloat16 g_W1h[DFFN * DMODEL],  g_W1l[DFFN * DMODEL];
__device__ __nv_bfloat16 g_W2h[DMODEL * DFFN],  g_W2l[DMODEL * DFFN];

__device__ __forceinline__ float nan_to_num_f(float x) {
    if (isnan(x)) return 0.0f;
    if (isinf(x)) return x > 0.0f ? 3.402823466e38f : -3.402823466e38f;
    return x;
}

__device__ __forceinline__ void mma16816(float* d,
    uint32_t a0, uint32_t a1, uint32_t a2, uint32_t a3,
    uint32_t b0, uint32_t b1)
{
    asm volatile(
        "mma.sync.aligned.m16n8k16.row.col.f32.bf16.bf16.f32 "
        "{%0,%1,%2,%3}, {%4,%5,%6,%7}, {%8,%9}, {%0,%1,%2,%3};\n"
        : "+f"(d[0]), "+f"(d[1]), "+f"(d[2]), "+f"(d[3])
        : "r"(a0), "r"(a1), "r"(a2), "r"(a3), "r"(b0), "r"(b1));
}

__device__ __forceinline__ uint32_t ld_u32(const __nv_bfloat16* p) {
    return *(const uint32_t*)p;
}
__device__ __forceinline__ uint32_t pack_bf2(__nv_bfloat16 lo, __nv_bfloat16 hi) {
    uint32_t a = (uint32_t)__bfloat16_as_ushort(lo);
    uint32_t b = (uint32_t)__bfloat16_as_ushort(hi);
    return a | (b << 16);
}

// ============================================================================
// Kernel 0: split fp32 weights into bf16 hi/lo pairs
// ============================================================================
__global__ __launch_bounds__(256) void split_weights_kernel(
    const float* __restrict__ Wq, const float* __restrict__ Wo,
    const float* __restrict__ W1, const float* __restrict__ W2)
{
    const int NQ = DMODEL * DMODEL;   // 36864
    const int N1 = DFFN * DMODEL;     // 393216
    int i = blockIdx.x * 256 + threadIdx.x;
    float v; __nv_bfloat16 *ph, *pl;
    if (i < NQ)                { v = Wq[i];              ph = g_Wqh + i;           pl = g_Wql + i; }
    else if (i < 2*NQ)         { int j = i - NQ;         v = Wo[j]; ph = g_Woh + j; pl = g_Wol + j; }
    else if (i < 2*NQ + N1)    { int j = i - 2*NQ;       v = W1[j]; ph = g_W1h + j; pl = g_W1l + j; }
    else if (i < 2*NQ + 2*N1)  { int j = i - 2*NQ - N1;  v = W2[j]; ph = g_W2h + j; pl = g_W2l + j; }
    else return;
    __nv_bfloat16 h = __float2bfloat16(v);
    *ph = h;
    *pl = __float2bfloat16(v - __bfloat162float(h));
}

// ============================================================================
// Kernel 1: K/V projections (small, fp32 SIMT)
// ============================================================================
__global__ __launch_bounds__(256) void kv_kernel(
    const float* __restrict__ boxf, const float* __restrict__ boxp,
    const float* __restrict__ Wk, const float* __restrict__ bk,
    const float* __restrict__ Wv, const float* __restrict__ bv)
{
    __shared__ float Asf[64 * 17];
    __shared__ float Asp[64 * 17];
    __shared__ float Bsk[16 * 193];
    __shared__ float Bsv[16 * 193];
    const int t = threadIdx.x;
    const int m0 = blockIdx.x * 64;
    const int tx = t & 15, ty = t >> 4;

    float ak[4][12], av[4][12];
#pragma unroll
    for (int i = 0; i < 4; i++)
#pragma unroll
        for (int j = 0; j < 12; j++) { ak[i][j] = 0.f; av[i][j] = 0.f; }

    for (int kt = 0; kt < BDIM; kt += 16) {
        __syncthreads();
        for (int i = t; i < 64 * 16; i += 256) {
            int r = i >> 4, k = i & 15;
            Asf[r * 17 + k] = boxf[(m0 + r) * BDIM + kt + k];
            Asp[r * 17 + k] = boxp[(m0 + r) * BDIM + kt + k];
        }
        for (int i = t; i < 16 * DMODEL; i += 256) {
            int d = i >> 4, k = i & 15;
            Bsk[k * 193 + d] = Wk[d * BDIM + kt + k];
            Bsv[k * 193 + d] = Wv[d * BDIM + kt + k];
        }
        __syncthreads();
#pragma unroll
        for (int k = 0; k < 16; k++) {
            float af[4], aa[4], wkr[12], wvr[12];
#pragma unroll
            for (int i = 0; i < 4; i++) {
                af[i] = Asf[(ty * 4 + i) * 17 + k];
                aa[i] = af[i] + Asp[(ty * 4 + i) * 17 + k];
            }
#pragma unroll
            for (int j = 0; j < 12; j++) {
                wkr[j] = Bsk[k * 193 + tx * 12 + j];
                wvr[j] = Bsv[k * 193 + tx * 12 + j];
            }
#pragma unroll
            for (int i = 0; i < 4; i++)
#pragma unroll
                for (int j = 0; j < 12; j++) {
                    ak[i][j] = fmaf(aa[i], wkr[j], ak[i][j]);
                    av[i][j] = fmaf(af[i], wvr[j], av[i][j]);
                }
        }
    }
#pragma unroll
    for (int i = 0; i < 4; i++) {
        int m = m0 + ty * 4 + i;
#pragma unroll
        for (int j = 0; j < 12; j++) {
            int d = tx * 12 + j;
            g_K[m * DMODEL + d] = ak[i][j] + bk[d];
            g_V[m * DMODEL + d] = av[i][j] + bv[d];
        }
    }
}

// ============================================================================
// Kernel 2: Q = gather(src+pos) @ Wq^T + bq   — bf16x3 mma.sync
// ============================================================================
#define SA 200
__global__ __launch_bounds__(256) void qproj_mma_kernel(
    const float* __restrict__ src, const float* __restrict__ pos,
    const int* __restrict__ vinds, const float* __restrict__ bq)
{
    extern __shared__ char smc[];
    __nv_bfloat16* Ah = (__nv_bfloat16*)smc;                  // 25600 B
    __nv_bfloat16* Al = (__nv_bfloat16*)(smc + 25600);
    __nv_bfloat16* Bh = (__nv_bfloat16*)(smc + 51200);        // 76800 B
    __nv_bfloat16* Bl = (__nv_bfloat16*)(smc + 128000);
    int* gI = (int*)(smc + 204800);
    const int t = threadIdx.x;
    const int r0g = blockIdx.x * 64;
    if (t < 64) gI[t] = vinds[r0g + t];
    __syncthreads();
    for (int i = t; i < 64 * DMODEL; i += 256) {
        int r = i / DMODEL, c = i % DMODEL;
        int g = gI[r];
        float x = src[g * DMODEL + c] + pos[g * DMODEL + c];
        __nv_bfloat16 h = __float2bfloat16(x);
        Ah[r * SA + c] = h;
        Al[r * SA + c] = __float2bfloat16(x - __bfloat162float(h));
    }
    for (int i = t; i < DMODEL * 96; i += 256) {
        int d = i / 96, kp = i % 96;
        *(uint32_t*)&Bh[d * SA + kp * 2] = ((const uint32_t*)g_Wqh)[d * 96 + kp];
        *(uint32_t*)&Bl[d * SA + kp * 2] = ((const uint32_t*)g_Wql)[d * 96 + kp];
    }
    __syncthreads();

    const int w = t >> 5, lane = t & 31;
    const int r0 = (w & 3) * 16, c0 = (w >> 2) * 96;
    const int lr = lane >> 2, lk = (lane & 3) * 2;
    float acc[12][4];
#pragma unroll
    for (int n = 0; n < 12; n++)
#pragma unroll
        for (int q = 0; q < 4; q++) acc[n][q] = 0.f;

    const __nv_bfloat16* As[3] = {Ah, Ah, Al};
    const __nv_bfloat16* Bs[3] = {Bh, Bl, Bh};
#pragma unroll 1
    for (int s = 0; s < 3; s++) {
        const __nv_bfloat16* A = As[s];
        const __nv_bfloat16* B = Bs[s];
#pragma unroll 1
        for (int kk = 0; kk < 12; kk++) {
            int kb = kk * 16;
            uint32_t a0 = ld_u32(&A[(r0 + lr) * SA + kb + lk]);
            uint32_t a1 = ld_u32(&A[(r0 + lr + 8) * SA + kb + lk]);
            uint32_t a2 = ld_u32(&A[(r0 + lr) * SA + kb + lk + 8]);
            uint32_t a3 = ld_u32(&A[(r0 + lr + 8) * SA + kb + lk + 8]);
#pragma unroll
            for (int nt = 0; nt < 12; nt++) {
                uint32_t b0 = ld_u32(&B[(c0 + nt * 8 + lr) * SA + kb + lk]);
                uint32_t b1 = ld_u32(&B[(c0 + nt * 8 + lr) * SA + kb + lk + 8]);
                mma16816(acc[nt], a0, a1, a2, a3, b0, b1);
            }
        }
    }
#pragma unroll
    for (int nt = 0; nt < 12; nt++) {
        int col = c0 + nt * 8 + lk;
        int row = r0g + r0 + lr;
        float2 v0 = make_float2(acc[nt][0] + bq[col], acc[nt][1] + bq[col + 1]);
        float2 v1 = make_float2(acc[nt][2] + bq[col], acc[nt][3] + bq[col + 1]);
        *(float2*)&g_Q[row * DMODEL + col] = v0;
        *(float2*)&g_Q[(row + 8) * DMODEL + col] = v1;
    }
}

// ============================================================================
// Kernel 3: attention per (32-query tile, head) — fp32 SIMT
// ============================================================================
__global__ __launch_bounds__(256) void attn_kernel(
    const int* __restrict__ vinds, const int* __restrict__ vcrd,
    const int* __restrict__ bcrd)
{
    extern __shared__ float sm[];
    float* Qs  = sm;                 // 32*25
    float* Khs = sm + 800;           // 256*25
    float* Vhs = sm + 800 + 6400;    // 256*25
    float* Ss  = sm + 800 + 12800;   // 32*257
    float* part = sm + 800 + 12800 + 8224; // 4*32*24
    int* qb = (int*)(sm + 800 + 12800 + 8224 + 3072);
    int* bb = qb + 32;

    const int t = threadIdx.x;
    const int q0 = blockIdx.x * 32;
    const int h = blockIdx.y;

    if (t < 32) { int g = vinds[q0 + t]; qb[t] = vcrd[g * 4]; }
    bb[t] = bcrd[t * 4];
    for (int i = t; i < 32 * DHEAD; i += 256) {
        int q = i / DHEAD, d = i % DHEAD;
        Qs[q * 25 + d] = g_Q[(q0 + q) * DMODEL + h * DHEAD + d];
    }
    for (int i = t; i < MTOK * DHEAD; i += 256) {
        int m = i / DHEAD, d = i % DHEAD;
        Khs[m * 25 + d] = g_K[m * DMODEL + h * DHEAD + d];
        Vhs[m * 25 + d] = g_V[m * DMODEL + h * DHEAD + d];
    }
    __syncthreads();

    const int mg = t & 31, qg = t >> 5;
    float sc[4][8];
#pragma unroll
    for (int i = 0; i < 4; i++)
#pragma unroll
        for (int j = 0; j < 8; j++) sc[i][j] = 0.f;
#pragma unroll
    for (int k = 0; k < DHEAD; k++) {
        float a[4], b[8];
#pragma unroll
        for (int i = 0; i < 4; i++) a[i] = Qs[(qg * 4 + i) * 25 + k];
#pragma unroll
        for (int j = 0; j < 8; j++) b[j] = Khs[(mg + j * 32) * 25 + k];
#pragma unroll
        for (int i = 0; i < 4; i++)
#pragma unroll
            for (int j = 0; j < 8; j++) sc[i][j] = fmaf(a[i], b[j], sc[i][j]);
    }
    const float scale = 0.20412414523193154f;
    const float NEG_INF = -__int_as_float(0x7f800000);
#pragma unroll
    for (int i = 0; i < 4; i++) {
        int q = qg * 4 + i;
#pragma unroll
        for (int j = 0; j < 8; j++) {
            int m = mg + j * 32;
            float s = sc[i][j] * scale;
            if (qb[q] != bb[m]) s = NEG_INF;
            Ss[q * 257 + m] = s;
        }
    }
    __syncthreads();

    {
        const int w = t >> 5, lane = t & 31;
        for (int rr = 0; rr < 4; rr++) {
            int q = w * 4 + rr;
            float v[8]; float mx = NEG_INF;
#pragma unroll
            for (int j = 0; j < 8; j++) {
                v[j] = Ss[q * 257 + lane + j * 32];
                mx = fmaxf(mx, v[j]);
            }
#pragma unroll
            for (int o = 16; o; o >>= 1) mx = fmaxf(mx, __shfl_xor_sync(0xffffffffu, mx, o));
            float ssum = 0.f;
#pragma unroll
            for (int j = 0; j < 8; j++) { v[j] = __expf(v[j] - mx); ssum += v[j]; }
#pragma unroll
            for (int o = 16; o; o >>= 1) ssum += __shfl_xor_sync(0xffffffffu, ssum, o);
            float inv = 1.0f / ssum;
#pragma unroll
            for (int j = 0; j < 8; j++) Ss[q * 257 + lane + j * 32] = v[j] * inv;
        }
    }
    __syncthreads();

    {
        const int grp = t >> 6, u = t & 63;
        const int qg2 = u >> 2, dg = u & 3;
        float c2[2][6];
#pragma unroll
        for (int i = 0; i < 2; i++)
#pragma unroll
            for (int j = 0; j < 6; j++) c2[i][j] = 0.f;
        for (int mm = 0; mm < 64; mm++) {
            int m = grp * 64 + mm;
            float p0 = Ss[(qg2 * 2 + 0) * 257 + m];
            float p1 = Ss[(qg2 * 2 + 1) * 257 + m];
            float vv[6];
#pragma unroll
            for (int j = 0; j < 6; j++) vv[j] = Vhs[m * 25 + dg * 6 + j];
#pragma unroll
            for (int j = 0; j < 6; j++) {
                c2[0][j] = fmaf(p0, vv[j], c2[0][j]);
                c2[1][j] = fmaf(p1, vv[j], c2[1][j]);
            }
        }
#pragma unroll
        for (int i = 0; i < 2; i++)
#pragma unroll
            for (int j = 0; j < 6; j++)
                part[(grp * 32 + qg2 * 2 + i) * 24 + dg * 6 + j] = c2[i][j];
    }
    __syncthreads();
    for (int o = t; o < 32 * 24; o += 256) {
        int q = o / 24, d = o % 24;
        float s = part[q * 24 + d] + part[(32 + q) * 24 + d]
                + part[(64 + q) * 24 + d] + part[(96 + q) * 24 + d];
        g_CTX[(q0 + q) * DMODEL + h * DHEAD + d] = s;
    }
}

// ============================================================================
// Kernel 4: O-proj + residual + LN1 — bf16x3 mma.sync
// ============================================================================
__global__ __launch_bounds__(256) void oproj_mma_kernel(
    const float* __restrict__ src, const int* __restrict__ vinds,
    const float* __restrict__ bo,
    const float* __restrict__ ln1g, const float* __restrict__ ln1b)
{
    extern __shared__ char smc[];
    __nv_bfloat16* Ah = (__nv_bfloat16*)smc;
    __nv_bfloat16* Al = (__nv_bfloat16*)(smc + 25600);
    __nv_bfloat16* Bh = (__nv_bfloat16*)(smc + 51200);
    __nv_bfloat16* Bl = (__nv_bfloat16*)(smc + 128000);
    int* gI = (int*)(smc + 204800);
    float* Ys = (float*)(smc + 51200);   // reuses B region after GEMM (stride 200)
    const int t = threadIdx.x;
    const int r0g = blockIdx.x * 64;
    if (t < 64) gI[t] = vinds[r0g + t];
    for (int i = t; i < 64 * DMODEL; i += 256) {
        int r = i / DMODEL, c = i % DMODEL;
        float x = g_CTX[(r0g + r) * DMODEL + c];
        __nv_bfloat16 h = __float2bfloat16(x);
        Ah[r * SA + c] = h;
        Al[r * SA + c] = __float2bfloat16(x - __bfloat162float(h));
    }
    for (int i = t; i < DMODEL * 96; i += 256) {
        int d = i / 96, kp = i % 96;
        *(uint32_t*)&Bh[d * SA + kp * 2] = ((const uint32_t*)g_Woh)[d * 96 + kp];
        *(uint32_t*)&Bl[d * SA + kp * 2] = ((const uint32_t*)g_Wol)[d * 96 + kp];
    }
    __syncthreads();

    const int w = t >> 5, lane = t & 31;
    const int r0 = (w & 3) * 16, c0 = (w >> 2) * 96;
    const int lr = lane >> 2, lk = (lane & 3) * 2;
    float acc[12][4];
#pragma unroll
    for (int n = 0; n < 12; n++)
#pragma unroll
        for (int q = 0; q < 4; q++) acc[n][q] = 0.f;

    const __nv_bfloat16* As[3] = {Ah, Ah, Al};
    const __nv_bfloat16* Bs[3] = {Bh, Bl, Bh};
#pragma unroll 1
    for (int s = 0; s < 3; s++) {
        const __nv_bfloat16* A = As[s];
        const __nv_bfloat16* B = Bs[s];
#pragma unroll 1
        for (int kk = 0; kk < 12; kk++) {
            int kb = kk * 16;
            uint32_t a0 = ld_u32(&A[(r0 + lr) * SA + kb + lk]);
            uint32_t a1 = ld_u32(&A[(r0 + lr + 8) * SA + kb + lk]);
            uint32_t a2 = ld_u32(&A[(r0 + lr) * SA + kb + lk + 8]);
            uint32_t a3 = ld_u32(&A[(r0 + lr + 8) * SA + kb + lk + 8]);
#pragma unroll
            for (int nt = 0; nt < 12; nt++) {
                uint32_t b0 = ld_u32(&B[(c0 + nt * 8 + lr) * SA + kb + lk]);
                uint32_t b1 = ld_u32(&B[(c0 + nt * 8 + lr) * SA + kb + lk + 8]);
                mma16816(acc[nt], a0, a1, a2, a3, b0, b1);
            }
        }
    }
    __syncthreads();   // all warps done reading B before Ys overwrite
#pragma unroll
    for (int nt = 0; nt < 12; nt++) {
        int col = c0 + nt * 8 + lk;
        int row = r0 + lr;
        Ys[row * SA + col]           = nan_to_num_f(acc[nt][0] + bo[col]);
        Ys[row * SA + col + 1]       = nan_to_num_f(acc[nt][1] + bo[col + 1]);
        Ys[(row + 8) * SA + col]     = nan_to_num_f(acc[nt][2] + bo[col]);
        Ys[(row + 8) * SA + col + 1] = nan_to_num_f(acc[nt][3] + bo[col + 1]);
    }
    __syncthreads();
    for (int rr = 0; rr < 8; rr++) {
        int r = w * 8 + rr;
        int g = gI[r];
        float v[6];
#pragma unroll
        for (int c = 0; c < 6; c++)
            v[c] = Ys[r * SA + lane * 6 + c] + src[g * DMODEL + lane * 6 + c];
        float s = 0.f;
#pragma unroll
        for (int c = 0; c < 6; c++) s += v[c];
#pragma unroll
        for (int o = 16; o; o >>= 1) s += __shfl_xor_sync(0xffffffffu, s, o);
        float mean = s * (1.0f / 192.0f);
        float vs = 0.f;
#pragma unroll
        for (int c = 0; c < 6; c++) { float d0 = v[c] - mean; vs += d0 * d0; }
#pragma unroll
        for (int o = 16; o; o >>= 1) vs += __shfl_xor_sync(0xffffffffu, vs, o);
        float inv = rsqrtf(vs * (1.0f / 192.0f) + LN_EPS);
#pragma unroll
        for (int c = 0; c < 6; c++) {
            int d = lane * 6 + c;
            g_X1[g * DMODEL + d] = (v[c] - mean) * inv * ln1g[d] + ln1b[d];
        }
    }
}

// ============================================================================
// Kernel 5: FFN + residual + LN2 — bf16x3 mma.sync
// ============================================================================
#define SH 72
__global__ __launch_bounds__(256) void ffn_mma_kernel(
    const float* __restrict__ b1, const float* __restrict__ b2,
    const float* __restrict__ ln2g, const float* __restrict__ ln2b,
    float* __restrict__ out)
{
    extern __shared__ char smc[];
    __nv_bfloat16* Xh = (__nv_bfloat16*)smc;                  // [64][200] 25600
    __nv_bfloat16* Xl = (__nv_bfloat16*)(smc + 25600);
    char* WU = smc + 51200;                                   // 55296 union
    __nv_bfloat16* W1h = (__nv_bfloat16*)WU;                  // [64][200]
    __nv_bfloat16* W1l = (__nv_bfloat16*)(WU + 25600);
    __nv_bfloat16* W2h = (__nv_bfloat16*)WU;                  // [192][72]
    __nv_bfloat16* W2l = (__nv_bfloat16*)(WU + 27648);
    float* Ys = (float*)WU;                                   // [64][200] f32
    __nv_bfloat16* Hh = (__nv_bfloat16*)(smc + 106496);       // [64][72] 9216
    __nv_bfloat16* Hl = (__nv_bfloat16*)(smc + 115712);       // 9216 -> end 124928
    const int t = threadIdx.x, w = t >> 5, lane = t & 31;
    const int r0g = blockIdx.x * 64;
    const int lr = lane >> 2, lk = (lane & 3) * 2;
    const int r0 = (w & 3) * 16;
    const int c0h = (w >> 2) * 32;   // phase-1 cols within 64-chunk
    const int c0y = (w >> 2) * 96;   // phase-2 cols

    for (int i = t; i < 64 * DMODEL; i += 256) {
        int r = i / DMODEL, c = i % DMODEL;
        float x = g_X1[(r0g + r) * DMODEL + c];
        __nv_bfloat16 h = __float2bfloat16(x);
        Xh[r * SA + c] = h;
        Xl[r * SA + c] = __float2bfloat16(x - __bfloat162float(h));
    }

    float y[12][4];
#pragma unroll
    for (int n = 0; n < 12; n++)
#pragma unroll
        for (int q = 0; q < 4; q++) y[n][q] = 0.f;

#pragma unroll 1
    for (int fc = 0; fc < DFFN; fc += 64) {
        __syncthreads();   // guards W union reuse (and first-iter X staging)
        for (int i = t; i < 64 * 96; i += 256) {
            int f = i / 96, kp = i % 96;
            *(uint32_t*)&W1h[f * SA + kp * 2] = ((const uint32_t*)g_W1h)[(fc + f) * 96 + kp];
            *(uint32_t*)&W1l[f * SA + kp * 2] = ((const uint32_t*)g_W1l)[(fc + f) * 96 + kp];
        }
        __syncthreads();
        // ---- phase 1: H = relu(Xcat @ W1cat^T + b1) ----
        float hacc[4][4];
#pragma unroll
        for (int n = 0; n < 4; n++)
#pragma unroll
            for (int q = 0; q < 4; q++) hacc[n][q] = 0.f;
        {
            const __nv_bfloat16* As[3] = {Xh, Xh, Xl};
            const __nv_bfloat16* Bs[3] = {W1h, W1l, W1h};
#pragma unroll 1
            for (int s = 0; s < 3; s++) {
                const __nv_bfloat16* A = As[s];
                const __nv_bfloat16* B = Bs[s];
#pragma unroll 1
                for (int kk = 0; kk < 12; kk++) {
                    int kb = kk * 16;
                    uint32_t a0 = ld_u32(&A[(r0 + lr) * SA + kb + lk]);
                    uint32_t a1 = ld_u32(&A[(r0 + lr + 8) * SA + kb + lk]);
                    uint32_t a2 = ld_u32(&A[(r0 + lr) * SA + kb + lk + 8]);
                    uint32_t a3 = ld_u32(&A[(r0 + lr + 8) * SA + kb + lk + 8]);
#pragma unroll
                    for (int nt = 0; nt < 4; nt++) {
                        uint32_t b0 = ld_u32(&B[(c0h + nt * 8 + lr) * SA + kb + lk]);
                        uint32_t b1r = ld_u32(&B[(c0h + nt * 8 + lr) * SA + kb + lk + 8]);
                        mma16816(hacc[nt], a0, a1, a2, a3, b0, b1r);
                    }
                }
            }
        }
#pragma unroll
        for (int nt = 0; nt < 4; nt++) {
            int col = c0h + nt * 8 + lk;
            int fg = fc + col;
            float bv0 = b1[fg], bv1 = b1[fg + 1];
            float h00 = fmaxf(hacc[nt][0] + bv0, 0.f);
            float h01 = fmaxf(hacc[nt][1] + bv1, 0.f);
            float h10 = fmaxf(hacc[nt][2] + bv0, 0.f);
            float h11 = fmaxf(hacc[nt][3] + bv1, 0.f);
            __nv_bfloat16 a0 = __float2bfloat16(h00);
            __nv_bfloat16 a1 = __float2bfloat16(h01);
            __nv_bfloat16 a2 = __float2bfloat16(h10);
            __nv_bfloat16 a3 = __float2bfloat16(h11);
            *(uint32_t*)&Hh[(r0 + lr) * SH + col] = pack_bf2(a0, a1);
            *(uint32_t*)&Hh[(r0 + lr + 8) * SH + col] = pack_bf2(a2, a3);
            __nv_bfloat16 l0 = __float2bfloat16(h00 - __bfloat162float(a0));
            __nv_bfloat16 l1 = __float2bfloat16(h01 - __bfloat162float(a1));
            __nv_bfloat16 l2 = __float2bfloat16(h10 - __bfloat162float(a2));
            __nv_bfloat16 l3 = __float2bfloat16(h11 - __bfloat162float(a3));
            *(uint32_t*)&Hl[(r0 + lr) * SH + col] = pack_bf2(l0, l1);
            *(uint32_t*)&Hl[(r0 + lr + 8) * SH + col] = pack_bf2(l2, l3);
        }
        __syncthreads();
        // stage W2 chunk [d][f] -> [192][72]
        for (int i = t; i < DMODEL * 32; i += 256) {
            int d = i / 32, kp = i % 32;
            *(uint32_t*)&W2h[d * SH + kp * 2] = ((const uint32_t*)g_W2h)[d * (DFFN / 2) + (fc >> 1) + kp];
            *(uint32_t*)&W2l[d * SH + kp * 2] = ((const uint32_t*)g_W2l)[d * (DFFN / 2) + (fc >> 1) + kp];
        }
        __syncthreads();
        // ---- phase 2: Y += Hcat @ W2cat^T ----
        {
            const __nv_bfloat16* As[3] = {Hh, Hh, Hl};
            const __nv_bfloat16* Bs[3] = {W2h, W2l, W2h};
#pragma unroll 1
            for (int s = 0; s < 3; s++) {
                const __nv_bfloat16* A = As[s];
                const __nv_bfloat16* B = Bs[s];
#pragma unroll 1
                for (int kk = 0; kk < 4; kk++) {
                    int kb = kk * 16;
                    uint32_t a0 = ld_u32(&A[(r0 + lr) * SH + kb + lk]);
                    uint32_t a1 = ld_u32(&A[(r0 + lr + 8) * SH + kb + lk]);
                    uint32_t a2 = ld_u32(&A[(r0 + lr) * SH + kb + lk + 8]);
                    uint32_t a3 = ld_u32(&A[(r0 + lr + 8) * SH + kb + lk + 8]);
#pragma unroll
                    for (int nt = 0; nt < 12; nt++) {
                        uint32_t b0 = ld_u32(&B[(c0y + nt * 8 + lr) * SH + kb + lk]);
                        uint32_t b1r = ld_u32(&B[(c0y + nt * 8 + lr) * SH + kb + lk + 8]);
                        mma16816(y[nt], a0, a1, a2, a3, b0, b1r);
                    }
                }
            }
        }
    }
    __syncthreads();
#pragma unroll
    for (int nt = 0; nt < 12; nt++) {
        int col = c0y + nt * 8 + lk;
        int row = r0 + lr;
        Ys[row * SA + col]           = y[nt][0];
        Ys[row * SA + col + 1]       = y[nt][1];
        Ys[(row + 8) * SA + col]     = y[nt][2];
        Ys[(row + 8) * SA + col + 1] = y[nt][3];
    }
    __syncthreads();
    for (int rr = 0; rr < 8; rr++) {
        int r = w * 8 + rr;
        float v[6];
#pragma unroll
        for (int c = 0; c < 6; c++) {
            int d = lane * 6 + c;
            v[c] = Ys[r * SA + d] + b2[d] + g_X1[(r0g + r) * DMODEL + d];
        }
        float s = 0.f;
#pragma unroll
        for (int c = 0; c < 6; c++) s += v[c];
#pragma unroll
        for (int o = 16; o; o >>= 1) s += __shfl_xor_sync(0xffffffffu, s, o);
        float mean = s * (1.0f / 192.0f);
        float vs = 0.f;
#pragma unroll
        for (int c = 0; c < 6; c++) { float d0 = v[c] - mean; vs += d0 * d0; }
#pragma unroll
        for (int o = 16; o; o >>= 1) vs += __shfl_xor_sync(0xffffffffu, vs, o);
        float inv = rsqrtf(vs * (1.0f / 192.0f) + LN_EPS);
#pragma unroll
        for (int c = 0; c < 6; c++) {
            int d = lane * 6 + c;
            out[(r0g + r) * DMODEL + d] = (v[c] - mean) * inv * ln2g[d] + ln2b[d];
        }
    }
}

// ============================================================================
extern "C" void kernel_launch(void* const* d_in, const int* in_sizes, int n_in,
                              void* d_out, int out_size)
{
    const float* src  = (const float*)d_in[0];
    const int*   vcrd = (const int*)d_in[1];
    const float* boxf = (const float*)d_in[2];
    const int*   bcrd = (const int*)d_in[3];
    const float* pos  = (const float*)d_in[4];
    const float* boxp = (const float*)d_in[5];
    const int*   vind = (const int*)d_in[6];
    const float* Wq = (const float*)d_in[7];
    const float* bq = (const float*)d_in[8];
    const float* Wk = (const float*)d_in[9];
    const float* bk = (const float*)d_in[10];
    const float* Wv = (const float*)d_in[11];
    const float* bv = (const float*)d_in[12];
    const float* Wo = (const float*)d_in[13];
    const float* bo = (const float*)d_in[14];
    const float* W1 = (const float*)d_in[15];
    const float* b1 = (const float*)d_in[16];
    const float* W2 = (const float*)d_in[17];
    const float* b2 = (const float*)d_in[18];
    const float* g1 = (const float*)d_in[19];
    const float* lb1 = (const float*)d_in[20];
    const float* g2 = (const float*)d_in[21];
    const float* lb2 = (const float*)d_in[22];
    float* out = (float*)d_out;

    const int SMEM_PROJ = 205056;   // Ah/Al + Bh/Bl + gI
    const int SMEM_ATTN = (800 + 6400 + 6400 + 8224 + 3072) * 4 + 288 * 4;
    const int SMEM_FFN  = 124928;

    cudaFuncSetAttribute(qproj_mma_kernel, cudaFuncAttributeMaxDynamicSharedMemorySize, SMEM_PROJ);
    cudaFuncSetAttribute(oproj_mma_kernel, cudaFuncAttributeMaxDynamicSharedMemorySize, SMEM_PROJ);
    cudaFuncSetAttribute(attn_kernel, cudaFuncAttributeMaxDynamicSharedMemorySize, SMEM_ATTN);
    cudaFuncSetAttribute(ffn_mma_kernel, cudaFuncAttributeMaxDynamicSharedMemorySize, SMEM_FFN);

    split_weights_kernel<<<3360, 256>>>(Wq, Wo, W1, W2);
    kv_kernel<<<MTOK / 64, 256>>>(boxf, boxp, Wk, bk, Wv, bv);
    qproj_mma_kernel<<<NTOT / 64, 256, SMEM_PROJ>>>(src, pos, vind, bq);
    attn_kernel<<<dim3(NTOT / 32, NHEAD), 256, SMEM_ATTN>>>(vind, vcrd, bcrd);
    oproj_mma_kernel<<<NTOT / 64, 256, SMEM_PROJ>>>(src, vind, bo, g1, lb1);
    ffn_mma_kernel<<<NTOT / 64, 256, SMEM_FFN>>>(b1, b2, g2, lb2, out);
}

// round 8
// speedup vs baseline: 1.3188x; 1.0521x over previous
#include <cuda_runtime.h>
#include <cuda_bf16.h>
#include <math.h>
#include <stdint.h>

#define NTOT 46080
#define DMODEL 192
#define MTOK 256
#define BDIM 256
#define NHEAD 8
#define DHEAD 24
#define DFFN 2048
#define LN_EPS 1e-5f

__device__ float g_K[MTOK * DMODEL];
__device__ float g_V[MTOK * DMODEL];
__device__ float g_Q[NTOT * DMODEL];
__device__ float g_CTX[NTOT * DMODEL];
__device__ float g_X1[NTOT * DMODEL];

__device__ __nv_bfloat16 g_Wqh[DMODEL * DMODEL], g_Wql[DMODEL * DMODEL];
__device__ __nv_bfloat16 g_Woh[DMODEL * DMODEL], g_Wol[DMODEL * DMODEL];
__device__ __nv_bfloat16 g_W1h[DFFN * DMODEL],  g_W1l[DFFN * DMODEL];
__device__ __nv_bfloat16 g_W2h[DMODEL * DFFN],  g_W2l[DMODEL * DFFN];

__device__ __forceinline__ float nan_to_num_f(float x) {
    if (isnan(x)) return 0.0f;
    if (isinf(x)) return x > 0.0f ? 3.402823466e38f : -3.402823466e38f;
    return x;
}

__device__ __forceinline__ void mma16816(float* d,
    uint32_t a0, uint32_t a1, uint32_t a2, uint32_t a3,
    uint32_t b0, uint32_t b1)
{
    asm volatile(
        "mma.sync.aligned.m16n8k16.row.col.f32.bf16.bf16.f32 "
        "{%0,%1,%2,%3}, {%4,%5,%6,%7}, {%8,%9}, {%0,%1,%2,%3};\n"
        : "+f"(d[0]), "+f"(d[1]), "+f"(d[2]), "+f"(d[3])
        : "r"(a0), "r"(a1), "r"(a2), "r"(a3), "r"(b0), "r"(b1));
}

__device__ __forceinline__ uint32_t ld_u32(const __nv_bfloat16* p) {
    return *(const uint32_t*)p;
}
__device__ __forceinline__ uint32_t pack_bf2(__nv_bfloat16 lo, __nv_bfloat16 hi) {
    uint32_t a = (uint32_t)__bfloat16_as_ushort(lo);
    uint32_t b = (uint32_t)__bfloat16_as_ushort(hi);
    return a | (b << 16);
}

// ============================================================================
// Kernel 0: split fp32 weights into bf16 hi/lo pairs
// ============================================================================
__global__ __launch_bounds__(256) void split_weights_kernel(
    const float* __restrict__ Wq, const float* __restrict__ Wo,
    const float* __restrict__ W1, const float* __restrict__ W2)
{
    const int NQ = DMODEL * DMODEL;
    const int N1 = DFFN * DMODEL;
    int i = blockIdx.x * 256 + threadIdx.x;
    float v; __nv_bfloat16 *ph, *pl;
    if (i < NQ)                { v = Wq[i];              ph = g_Wqh + i;           pl = g_Wql + i; }
    else if (i < 2*NQ)         { int j = i - NQ;         v = Wo[j]; ph = g_Woh + j; pl = g_Wol + j; }
    else if (i < 2*NQ + N1)    { int j = i - 2*NQ;       v = W1[j]; ph = g_W1h + j; pl = g_W1l + j; }
    else if (i < 2*NQ + 2*N1)  { int j = i - 2*NQ - N1;  v = W2[j]; ph = g_W2h + j; pl = g_W2l + j; }
    else return;
    __nv_bfloat16 h = __float2bfloat16(v);
    *ph = h;
    *pl = __float2bfloat16(v - __bfloat162float(h));
}

// ============================================================================
// Kernel 1: K/V projections (small, fp32 SIMT)
// ============================================================================
__global__ __launch_bounds__(256) void kv_kernel(
    const float* __restrict__ boxf, const float* __restrict__ boxp,
    const float* __restrict__ Wk, const float* __restrict__ bk,
    const float* __restrict__ Wv, const float* __restrict__ bv)
{
    __shared__ float Asf[64 * 17];
    __shared__ float Asp[64 * 17];
    __shared__ float Bsk[16 * 193];
    __shared__ float Bsv[16 * 193];
    const int t = threadIdx.x;
    const int m0 = blockIdx.x * 64;
    const int tx = t & 15, ty = t >> 4;

    float ak[4][12], av[4][12];
#pragma unroll
    for (int i = 0; i < 4; i++)
#pragma unroll
        for (int j = 0; j < 12; j++) { ak[i][j] = 0.f; av[i][j] = 0.f; }

    for (int kt = 0; kt < BDIM; kt += 16) {
        __syncthreads();
        for (int i = t; i < 64 * 16; i += 256) {
            int r = i >> 4, k = i & 15;
            Asf[r * 17 + k] = boxf[(m0 + r) * BDIM + kt + k];
            Asp[r * 17 + k] = boxp[(m0 + r) * BDIM + kt + k];
        }
        for (int i = t; i < 16 * DMODEL; i += 256) {
            int d = i >> 4, k = i & 15;
            Bsk[k * 193 + d] = Wk[d * BDIM + kt + k];
            Bsv[k * 193 + d] = Wv[d * BDIM + kt + k];
        }
        __syncthreads();
#pragma unroll
        for (int k = 0; k < 16; k++) {
            float af[4], aa[4], wkr[12], wvr[12];
#pragma unroll
            for (int i = 0; i < 4; i++) {
                af[i] = Asf[(ty * 4 + i) * 17 + k];
                aa[i] = af[i] + Asp[(ty * 4 + i) * 17 + k];
            }
#pragma unroll
            for (int j = 0; j < 12; j++) {
                wkr[j] = Bsk[k * 193 + tx * 12 + j];
                wvr[j] = Bsv[k * 193 + tx * 12 + j];
            }
#pragma unroll
            for (int i = 0; i < 4; i++)
#pragma unroll
                for (int j = 0; j < 12; j++) {
                    ak[i][j] = fmaf(aa[i], wkr[j], ak[i][j]);
                    av[i][j] = fmaf(af[i], wvr[j], av[i][j]);
                }
        }
    }
#pragma unroll
    for (int i = 0; i < 4; i++) {
        int m = m0 + ty * 4 + i;
#pragma unroll
        for (int j = 0; j < 12; j++) {
            int d = tx * 12 + j;
            g_K[m * DMODEL + d] = ak[i][j] + bk[d];
            g_V[m * DMODEL + d] = av[i][j] + bv[d];
        }
    }
}

// ============================================================================
// Kernel 2: Q = gather(src+pos) @ Wq^T + bq   — bf16x3 mma.sync, 64 rows
// kk loops fully unrolled (R7 change vs R5-passing source)
// ============================================================================
#define SA 200
__global__ __launch_bounds__(256) void qproj_mma_kernel(
    const float* __restrict__ src, const float* __restrict__ pos,
    const int* __restrict__ vinds, const float* __restrict__ bq)
{
    extern __shared__ char smc[];
    __nv_bfloat16* Ah = (__nv_bfloat16*)smc;
    __nv_bfloat16* Al = (__nv_bfloat16*)(smc + 25600);
    __nv_bfloat16* Bh = (__nv_bfloat16*)(smc + 51200);
    __nv_bfloat16* Bl = (__nv_bfloat16*)(smc + 128000);
    int* gI = (int*)(smc + 204800);
    const int t = threadIdx.x;
    const int r0g = blockIdx.x * 64;
    if (t < 64) gI[t] = vinds[r0g + t];
    __syncthreads();
    for (int i = t; i < 64 * DMODEL; i += 256) {
        int r = i / DMODEL, c = i % DMODEL;
        int g = gI[r];
        float x = src[g * DMODEL + c] + pos[g * DMODEL + c];
        __nv_bfloat16 h = __float2bfloat16(x);
        Ah[r * SA + c] = h;
        Al[r * SA + c] = __float2bfloat16(x - __bfloat162float(h));
    }
    for (int i = t; i < DMODEL * 96; i += 256) {
        int d = i / 96, kp = i % 96;
        *(uint32_t*)&Bh[d * SA + kp * 2] = ((const uint32_t*)g_Wqh)[d * 96 + kp];
        *(uint32_t*)&Bl[d * SA + kp * 2] = ((const uint32_t*)g_Wql)[d * 96 + kp];
    }
    __syncthreads();

    const int w = t >> 5, lane = t & 31;
    const int r0 = (w & 3) * 16, c0 = (w >> 2) * 96;
    const int lr = lane >> 2, lk = (lane & 3) * 2;
    float acc[12][4];
#pragma unroll
    for (int n = 0; n < 12; n++)
#pragma unroll
        for (int q = 0; q < 4; q++) acc[n][q] = 0.f;

    const __nv_bfloat16* As[3] = {Ah, Ah, Al};
    const __nv_bfloat16* Bs[3] = {Bh, Bl, Bh};
#pragma unroll 1
    for (int s = 0; s < 3; s++) {
        const __nv_bfloat16* A = As[s];
        const __nv_bfloat16* B = Bs[s];
#pragma unroll
        for (int kk = 0; kk < 12; kk++) {
            int kb = kk * 16;
            uint32_t a0 = ld_u32(&A[(r0 + lr) * SA + kb + lk]);
            uint32_t a1 = ld_u32(&A[(r0 + lr + 8) * SA + kb + lk]);
            uint32_t a2 = ld_u32(&A[(r0 + lr) * SA + kb + lk + 8]);
            uint32_t a3 = ld_u32(&A[(r0 + lr + 8) * SA + kb + lk + 8]);
#pragma unroll
            for (int nt = 0; nt < 12; nt++) {
                uint32_t b0 = ld_u32(&B[(c0 + nt * 8 + lr) * SA + kb + lk]);
                uint32_t b1 = ld_u32(&B[(c0 + nt * 8 + lr) * SA + kb + lk + 8]);
                mma16816(acc[nt], a0, a1, a2, a3, b0, b1);
            }
        }
    }
#pragma unroll
    for (int nt = 0; nt < 12; nt++) {
        int col = c0 + nt * 8 + lk;
        int row = r0g + r0 + lr;
        float2 v0 = make_float2(acc[nt][0] + bq[col], acc[nt][1] + bq[col + 1]);
        float2 v1 = make_float2(acc[nt][2] + bq[col], acc[nt][3] + bq[col + 1]);
        *(float2*)&g_Q[row * DMODEL + col] = v0;
        *(float2*)&g_Q[(row + 8) * DMODEL + col] = v1;
    }
}

// ============================================================================
// Kernel 3: attention per (32-query tile, head) — fp32 SIMT (R5-identical)
// ============================================================================
__global__ __launch_bounds__(256) void attn_kernel(
    const int* __restrict__ vinds, const int* __restrict__ vcrd,
    const int* __restrict__ bcrd)
{
    extern __shared__ float sm[];
    float* Qs  = sm;
    float* Khs = sm + 800;
    float* Vhs = sm + 800 + 6400;
    float* Ss  = sm + 800 + 12800;
    float* part = sm + 800 + 12800 + 8224;
    int* qb = (int*)(sm + 800 + 12800 + 8224 + 3072);
    int* bb = qb + 32;

    const int t = threadIdx.x;
    const int q0 = blockIdx.x * 32;
    const int h = blockIdx.y;

    if (t < 32) { int g = vinds[q0 + t]; qb[t] = vcrd[g * 4]; }
    bb[t] = bcrd[t * 4];
    for (int i = t; i < 32 * DHEAD; i += 256) {
        int q = i / DHEAD, d = i % DHEAD;
        Qs[q * 25 + d] = g_Q[(q0 + q) * DMODEL + h * DHEAD + d];
    }
    for (int i = t; i < MTOK * DHEAD; i += 256) {
        int m = i / DHEAD, d = i % DHEAD;
        Khs[m * 25 + d] = g_K[m * DMODEL + h * DHEAD + d];
        Vhs[m * 25 + d] = g_V[m * DMODEL + h * DHEAD + d];
    }
    __syncthreads();

    const int mg = t & 31, qg = t >> 5;
    float sc[4][8];
#pragma unroll
    for (int i = 0; i < 4; i++)
#pragma unroll
        for (int j = 0; j < 8; j++) sc[i][j] = 0.f;
#pragma unroll
    for (int k = 0; k < DHEAD; k++) {
        float a[4], b[8];
#pragma unroll
        for (int i = 0; i < 4; i++) a[i] = Qs[(qg * 4 + i) * 25 + k];
#pragma unroll
        for (int j = 0; j < 8; j++) b[j] = Khs[(mg + j * 32) * 25 + k];
#pragma unroll
        for (int i = 0; i < 4; i++)
#pragma unroll
            for (int j = 0; j < 8; j++) sc[i][j] = fmaf(a[i], b[j], sc[i][j]);
    }
    const float scale = 0.20412414523193154f;
    const float NEG_INF = -__int_as_float(0x7f800000);
#pragma unroll
    for (int i = 0; i < 4; i++) {
        int q = qg * 4 + i;
#pragma unroll
        for (int j = 0; j < 8; j++) {
            int m = mg + j * 32;
            float s = sc[i][j] * scale;
            if (qb[q] != bb[m]) s = NEG_INF;
            Ss[q * 257 + m] = s;
        }
    }
    __syncthreads();

    {
        const int w = t >> 5, lane = t & 31;
        for (int rr = 0; rr < 4; rr++) {
            int q = w * 4 + rr;
            float v[8]; float mx = NEG_INF;
#pragma unroll
            for (int j = 0; j < 8; j++) {
                v[j] = Ss[q * 257 + lane + j * 32];
                mx = fmaxf(mx, v[j]);
            }
#pragma unroll
            for (int o = 16; o; o >>= 1) mx = fmaxf(mx, __shfl_xor_sync(0xffffffffu, mx, o));
            float ssum = 0.f;
#pragma unroll
            for (int j = 0; j < 8; j++) { v[j] = __expf(v[j] - mx); ssum += v[j]; }
#pragma unroll
            for (int o = 16; o; o >>= 1) ssum += __shfl_xor_sync(0xffffffffu, ssum, o);
            float inv = 1.0f / ssum;
#pragma unroll
            for (int j = 0; j < 8; j++) Ss[q * 257 + lane + j * 32] = v[j] * inv;
        }
    }
    __syncthreads();

    {
        const int grp = t >> 6, u = t & 63;
        const int qg2 = u >> 2, dg = u & 3;
        float c2[2][6];
#pragma unroll
        for (int i = 0; i < 2; i++)
#pragma unroll
            for (int j = 0; j < 6; j++) c2[i][j] = 0.f;
        for (int mm = 0; mm < 64; mm++) {
            int m = grp * 64 + mm;
            float p0 = Ss[(qg2 * 2 + 0) * 257 + m];
            float p1 = Ss[(qg2 * 2 + 1) * 257 + m];
            float vv[6];
#pragma unroll
            for (int j = 0; j < 6; j++) vv[j] = Vhs[m * 25 + dg * 6 + j];
#pragma unroll
            for (int j = 0; j < 6; j++) {
                c2[0][j] = fmaf(p0, vv[j], c2[0][j]);
                c2[1][j] = fmaf(p1, vv[j], c2[1][j]);
            }
        }
#pragma unroll
        for (int i = 0; i < 2; i++)
#pragma unroll
            for (int j = 0; j < 6; j++)
                part[(grp * 32 + qg2 * 2 + i) * 24 + dg * 6 + j] = c2[i][j];
    }
    __syncthreads();
    for (int o = t; o < 32 * 24; o += 256) {
        int q = o / 24, d = o % 24;
        float s = part[q * 24 + d] + part[(32 + q) * 24 + d]
                + part[(64 + q) * 24 + d] + part[(96 + q) * 24 + d];
        g_CTX[(q0 + q) * DMODEL + h * DHEAD + d] = s;
    }
}

// ============================================================================
// Kernel 4: O-proj + residual + LN1 — bf16x3 mma.sync, 64 rows
// ============================================================================
__global__ __launch_bounds__(256) void oproj_mma_kernel(
    const float* __restrict__ src, const int* __restrict__ vinds,
    const float* __restrict__ bo,
    const float* __restrict__ ln1g, const float* __restrict__ ln1b)
{
    extern __shared__ char smc[];
    __nv_bfloat16* Ah = (__nv_bfloat16*)smc;
    __nv_bfloat16* Al = (__nv_bfloat16*)(smc + 25600);
    __nv_bfloat16* Bh = (__nv_bfloat16*)(smc + 51200);
    __nv_bfloat16* Bl = (__nv_bfloat16*)(smc + 128000);
    int* gI = (int*)(smc + 204800);
    float* Ys = (float*)(smc + 51200);
    const int t = threadIdx.x;
    const int r0g = blockIdx.x * 64;
    if (t < 64) gI[t] = vinds[r0g + t];
    for (int i = t; i < 64 * DMODEL; i += 256) {
        int r = i / DMODEL, c = i % DMODEL;
        float x = g_CTX[(r0g + r) * DMODEL + c];
        __nv_bfloat16 h = __float2bfloat16(x);
        Ah[r * SA + c] = h;
        Al[r * SA + c] = __float2bfloat16(x - __bfloat162float(h));
    }
    for (int i = t; i < DMODEL * 96; i += 256) {
        int d = i / 96, kp = i % 96;
        *(uint32_t*)&Bh[d * SA + kp * 2] = ((const uint32_t*)g_Woh)[d * 96 + kp];
        *(uint32_t*)&Bl[d * SA + kp * 2] = ((const uint32_t*)g_Wol)[d * 96 + kp];
    }
    __syncthreads();

    const int w = t >> 5, lane = t & 31;
    const int r0 = (w & 3) * 16, c0 = (w >> 2) * 96;
    const int lr = lane >> 2, lk = (lane & 3) * 2;
    float acc[12][4];
#pragma unroll
    for (int n = 0; n < 12; n++)
#pragma unroll
        for (int q = 0; q < 4; q++) acc[n][q] = 0.f;

    const __nv_bfloat16* As[3] = {Ah, Ah, Al};
    const __nv_bfloat16* Bs[3] = {Bh, Bl, Bh};
#pragma unroll 1
    for (int s = 0; s < 3; s++) {
        const __nv_bfloat16* A = As[s];
        const __nv_bfloat16* B = Bs[s];
#pragma unroll
        for (int kk = 0; kk < 12; kk++) {
            int kb = kk * 16;
            uint32_t a0 = ld_u32(&A[(r0 + lr) * SA + kb + lk]);
            uint32_t a1 = ld_u32(&A[(r0 + lr + 8) * SA + kb + lk]);
            uint32_t a2 = ld_u32(&A[(r0 + lr) * SA + kb + lk + 8]);
            uint32_t a3 = ld_u32(&A[(r0 + lr + 8) * SA + kb + lk + 8]);
#pragma unroll
            for (int nt = 0; nt < 12; nt++) {
                uint32_t b0 = ld_u32(&B[(c0 + nt * 8 + lr) * SA + kb + lk]);
                uint32_t b1 = ld_u32(&B[(c0 + nt * 8 + lr) * SA + kb + lk + 8]);
                mma16816(acc[nt], a0, a1, a2, a3, b0, b1);
            }
        }
    }
    __syncthreads();
#pragma unroll
    for (int nt = 0; nt < 12; nt++) {
        int col = c0 + nt * 8 + lk;
        int row = r0 + lr;
        Ys[row * SA + col]           = nan_to_num_f(acc[nt][0] + bo[col]);
        Ys[row * SA + col + 1]       = nan_to_num_f(acc[nt][1] + bo[col + 1]);
        Ys[(row + 8) * SA + col]     = nan_to_num_f(acc[nt][2] + bo[col]);
        Ys[(row + 8) * SA + col + 1] = nan_to_num_f(acc[nt][3] + bo[col + 1]);
    }
    __syncthreads();
    for (int rr = 0; rr < 8; rr++) {
        int r = w * 8 + rr;
        int g = gI[r];
        float v[6];
#pragma unroll
        for (int c = 0; c < 6; c++)
            v[c] = Ys[r * SA + lane * 6 + c] + src[g * DMODEL + lane * 6 + c];
        float s = 0.f;
#pragma unroll
        for (int c = 0; c < 6; c++) s += v[c];
#pragma unroll
        for (int o = 16; o; o >>= 1) s += __shfl_xor_sync(0xffffffffu, s, o);
        float mean = s * (1.0f / 192.0f);
        float vs = 0.f;
#pragma unroll
        for (int c = 0; c < 6; c++) { float d0 = v[c] - mean; vs += d0 * d0; }
#pragma unroll
        for (int o = 16; o; o >>= 1) vs += __shfl_xor_sync(0xffffffffu, vs, o);
        float inv = rsqrtf(vs * (1.0f / 192.0f) + LN_EPS);
#pragma unroll
        for (int c = 0; c < 6; c++) {
            int d = lane * 6 + c;
            g_X1[g * DMODEL + d] = (v[c] - mean) * inv * ln1g[d] + ln1b[d];
        }
    }
}

// ============================================================================
// Kernel 5: FFN + residual + LN2 — bf16x3 mma.sync, 256 threads / 64 rows
// (R5-passing config; only kk-loop unrolls restored)
// ============================================================================
#define SH 72
__global__ __launch_bounds__(256) void ffn_mma_kernel(
    const float* __restrict__ b1, const float* __restrict__ b2,
    const float* __restrict__ ln2g, const float* __restrict__ ln2b,
    float* __restrict__ out)
{
    extern __shared__ char smc[];
    __nv_bfloat16* Xh = (__nv_bfloat16*)smc;                  // [64][200] 25600
    __nv_bfloat16* Xl = (__nv_bfloat16*)(smc + 25600);
    char* WU = smc + 51200;                                   // 55296 union
    __nv_bfloat16* W1h = (__nv_bfloat16*)WU;                  // [64][200]
    __nv_bfloat16* W1l = (__nv_bfloat16*)(WU + 25600);
    __nv_bfloat16* W2h = (__nv_bfloat16*)WU;                  // [192][72]
    __nv_bfloat16* W2l = (__nv_bfloat16*)(WU + 27648);
    float* Ys = (float*)WU;                                   // [64][200] f32
    __nv_bfloat16* Hh = (__nv_bfloat16*)(smc + 106496);       // [64][72] 9216
    __nv_bfloat16* Hl = (__nv_bfloat16*)(smc + 115712);       // 9216 -> end 124928
    const int t = threadIdx.x, w = t >> 5, lane = t & 31;
    const int r0g = blockIdx.x * 64;
    const int lr = lane >> 2, lk = (lane & 3) * 2;
    const int r0 = (w & 3) * 16;
    const int c0h = (w >> 2) * 32;
    const int c0y = (w >> 2) * 96;

    for (int i = t; i < 64 * DMODEL; i += 256) {
        int r = i / DMODEL, c = i % DMODEL;
        float x = g_X1[(r0g + r) * DMODEL + c];
        __nv_bfloat16 h = __float2bfloat16(x);
        Xh[r * SA + c] = h;
        Xl[r * SA + c] = __float2bfloat16(x - __bfloat162float(h));
    }

    float y[12][4];
#pragma unroll
    for (int n = 0; n < 12; n++)
#pragma unroll
        for (int q = 0; q < 4; q++) y[n][q] = 0.f;

#pragma unroll 1
    for (int fc = 0; fc < DFFN; fc += 64) {
        __syncthreads();
        for (int i = t; i < 64 * 96; i += 256) {
            int f = i / 96, kp = i % 96;
            *(uint32_t*)&W1h[f * SA + kp * 2] = ((const uint32_t*)g_W1h)[(fc + f) * 96 + kp];
            *(uint32_t*)&W1l[f * SA + kp * 2] = ((const uint32_t*)g_W1l)[(fc + f) * 96 + kp];
        }
        __syncthreads();
        // ---- phase 1: H = relu(Xcat @ W1cat^T + b1) ----
        float hacc[4][4];
#pragma unroll
        for (int n = 0; n < 4; n++)
#pragma unroll
            for (int q = 0; q < 4; q++) hacc[n][q] = 0.f;
        {
            const __nv_bfloat16* As[3] = {Xh, Xh, Xl};
            const __nv_bfloat16* Bs[3] = {W1h, W1l, W1h};
#pragma unroll 1
            for (int s = 0; s < 3; s++) {
                const __nv_bfloat16* A = As[s];
                const __nv_bfloat16* B = Bs[s];
#pragma unroll
                for (int kk = 0; kk < 12; kk++) {
                    int kb = kk * 16;
                    uint32_t a0 = ld_u32(&A[(r0 + lr) * SA + kb + lk]);
                    uint32_t a1 = ld_u32(&A[(r0 + lr + 8) * SA + kb + lk]);
                    uint32_t a2 = ld_u32(&A[(r0 + lr) * SA + kb + lk + 8]);
                    uint32_t a3 = ld_u32(&A[(r0 + lr + 8) * SA + kb + lk + 8]);
#pragma unroll
                    for (int nt = 0; nt < 4; nt++) {
                        uint32_t b0 = ld_u32(&B[(c0h + nt * 8 + lr) * SA + kb + lk]);
                        uint32_t b1r = ld_u32(&B[(c0h + nt * 8 + lr) * SA + kb + lk + 8]);
                        mma16816(hacc[nt], a0, a1, a2, a3, b0, b1r);
                    }
                }
            }
        }
#pragma unroll
        for (int nt = 0; nt < 4; nt++) {
            int col = c0h + nt * 8 + lk;
            int fg = fc + col;
            float bv0 = b1[fg], bv1 = b1[fg + 1];
            float h00 = fmaxf(hacc[nt][0] + bv0, 0.f);
            float h01 = fmaxf(hacc[nt][1] + bv1, 0.f);
            float h10 = fmaxf(hacc[nt][2] + bv0, 0.f);
            float h11 = fmaxf(hacc[nt][3] + bv1, 0.f);
            __nv_bfloat16 a0 = __float2bfloat16(h00);
            __nv_bfloat16 a1 = __float2bfloat16(h01);
            __nv_bfloat16 a2 = __float2bfloat16(h10);
            __nv_bfloat16 a3 = __float2bfloat16(h11);
            *(uint32_t*)&Hh[(r0 + lr) * SH + col] = pack_bf2(a0, a1);
            *(uint32_t*)&Hh[(r0 + lr + 8) * SH + col] = pack_bf2(a2, a3);
            __nv_bfloat16 l0 = __float2bfloat16(h00 - __bfloat162float(a0));
            __nv_bfloat16 l1 = __float2bfloat16(h01 - __bfloat162float(a1));
            __nv_bfloat16 l2 = __float2bfloat16(h10 - __bfloat162float(a2));
            __nv_bfloat16 l3 = __float2bfloat16(h11 - __bfloat162float(a3));
            *(uint32_t*)&Hl[(r0 + lr) * SH + col] = pack_bf2(l0, l1);
            *(uint32_t*)&Hl[(r0 + lr + 8) * SH + col] = pack_bf2(l2, l3);
        }
        __syncthreads();
        for (int i = t; i < DMODEL * 32; i += 256) {
            int d = i / 32, kp = i % 32;
            *(uint32_t*)&W2h[d * SH + kp * 2] = ((const uint32_t*)g_W2h)[d * (DFFN / 2) + (fc >> 1) + kp];
            *(uint32_t*)&W2l[d * SH + kp * 2] = ((const uint32_t*)g_W2l)[d * (DFFN / 2) + (fc >> 1) + kp];
        }
        __syncthreads();
        // ---- phase 2: Y += Hcat @ W2cat^T ----
        {
            const __nv_bfloat16* As[3] = {Hh, Hh, Hl};
            const __nv_bfloat16* Bs[3] = {W2h, W2l, W2h};
#pragma unroll 1
            for (int s = 0; s < 3; s++) {
                const __nv_bfloat16* A = As[s];
                const __nv_bfloat16* B = Bs[s];
#pragma unroll
                for (int kk = 0; kk < 4; kk++) {
                    int kb = kk * 16;
                    uint32_t a0 = ld_u32(&A[(r0 + lr) * SH + kb + lk]);
                    uint32_t a1 = ld_u32(&A[(r0 + lr + 8) * SH + kb + lk]);
                    uint32_t a2 = ld_u32(&A[(r0 + lr) * SH + kb + lk + 8]);
                    uint32_t a3 = ld_u32(&A[(r0 + lr + 8) * SH + kb + lk + 8]);
#pragma unroll
                    for (int nt = 0; nt < 12; nt++) {
                        uint32_t b0 = ld_u32(&B[(c0y + nt * 8 + lr) * SH + kb + lk]);
                        uint32_t b1r = ld_u32(&B[(c0y + nt * 8 + lr) * SH + kb + lk + 8]);
                        mma16816(y[nt], a0, a1, a2, a3, b0, b1r);
                    }
                }
            }
        }
    }
    __syncthreads();
#pragma unroll
    for (int nt = 0; nt < 12; nt++) {
        int col = c0y + nt * 8 + lk;
        int row = r0 + lr;
        Ys[row * SA + col]           = y[nt][0];
        Ys[row * SA + col + 1]       = y[nt][1];
        Ys[(row + 8) * SA + col]     = y[nt][2];
        Ys[(row + 8) * SA + col + 1] = y[nt][3];
    }
    __syncthreads();
    for (int rr = 0; rr < 8; rr++) {
        int r = w * 8 + rr;
        float v[6];
#pragma unroll
        for (int c = 0; c < 6; c++) {
            int d = lane * 6 + c;
            v[c] = Ys[r * SA + d] + b2[d] + g_X1[(r0g + r) * DMODEL + d];
        }
        float s = 0.f;
#pragma unroll
        for (int c = 0; c < 6; c++) s += v[c];
#pragma unroll
        for (int o = 16; o; o >>= 1) s += __shfl_xor_sync(0xffffffffu, s, o);
        float mean = s * (1.0f / 192.0f);
        float vs = 0.f;
#pragma unroll
        for (int c = 0; c < 6; c++) { float d0 = v[c] - mean; vs += d0 * d0; }
#pragma unroll
        for (int o = 16; o; o >>= 1) vs += __shfl_xor_sync(0xffffffffu, vs, o);
        float inv = rsqrtf(vs * (1.0f / 192.0f) + LN_EPS);
#pragma unroll
        for (int c = 0; c < 6; c++) {
            int d = lane * 6 + c;
            out[(r0g + r) * DMODEL + d] = (v[c] - mean) * inv * ln2g[d] + ln2b[d];
        }
    }
}

// ============================================================================
extern "C" void kernel_launch(void* const* d_in, const int* in_sizes, int n_in,
                              void* d_out, int out_size)
{
    const float* src  = (const float*)d_in[0];
    const int*   vcrd = (const int*)d_in[1];
    const float* boxf = (const float*)d_in[2];
    const int*   bcrd = (const int*)d_in[3];
    const float* pos  = (const float*)d_in[4];
    const float* boxp = (const float*)d_in[5];
    const int*   vind = (const int*)d_in[6];
    const float* Wq = (const float*)d_in[7];
    const float* bq = (const float*)d_in[8];
    const float* Wk = (const float*)d_in[9];
    const float* bk = (const float*)d_in[10];
    const float* Wv = (const float*)d_in[11];
    const float* bv = (const float*)d_in[12];
    const float* Wo = (const float*)d_in[13];
    const float* bo = (const float*)d_in[14];
    const float* W1 = (const float*)d_in[15];
    const float* b1 = (const float*)d_in[16];
    const float* W2 = (const float*)d_in[17];
    const float* b2 = (const float*)d_in[18];
    const float* g1 = (const float*)d_in[19];
    const float* lb1 = (const float*)d_in[20];
    const float* g2 = (const float*)d_in[21];
    const float* lb2 = (const float*)d_in[22];
    float* out = (float*)d_out;

    const int SMEM_PROJ = 205056;
    const int SMEM_ATTN = (800 + 6400 + 6400 + 8224 + 3072) * 4 + 288 * 4;
    const int SMEM_FFN  = 124928;

    cudaFuncSetAttribute(qproj_mma_kernel, cudaFuncAttributeMaxDynamicSharedMemorySize, SMEM_PROJ);
    cudaFuncSetAttribute(oproj_mma_kernel, cudaFuncAttributeMaxDynamicSharedMemorySize, SMEM_PROJ);
    cudaFuncSetAttribute(attn_kernel, cudaFuncAttributeMaxDynamicSharedMemorySize, SMEM_ATTN);
    cudaFuncSetAttribute(ffn_mma_kernel, cudaFuncAttributeMaxDynamicSharedMemorySize, SMEM_FFN);

    split_weights_kernel<<<3360, 256>>>(Wq, Wo, W1, W2);
    kv_kernel<<<MTOK / 64, 256>>>(boxf, boxp, Wk, bk, Wv, bv);
    qproj_mma_kernel<<<NTOT / 64, 256, SMEM_PROJ>>>(src, pos, vind, bq);
    attn_kernel<<<dim3(NTOT / 32, NHEAD), 256, SMEM_ATTN>>>(vind, vcrd, bcrd);
    oproj_mma_kernel<<<NTOT / 64, 256, SMEM_PROJ>>>(src, vind, bo, g1, lb1);
    ffn_mma_kernel<<<NTOT / 64, 256, SMEM_FFN>>>(b1, b2, g2, lb2, out);
}

// round 10
// speedup vs baseline: 1.6699x; 1.2662x over previous
#include <cuda_runtime.h>
#include <cuda_bf16.h>
#include <cuda_fp16.h>
#include <math.h>
#include <stdint.h>

#define NTOT 46080
#define DMODEL 192
#define MTOK 256
#define BDIM 256
#define NHEAD 8
#define DHEAD 24
#define DFFN 2048
#define LN_EPS 1e-5f

__device__ float g_K[MTOK * DMODEL];
__device__ float g_V[MTOK * DMODEL];
__device__ float g_Q[NTOT * DMODEL];
__device__ float g_CTX[NTOT * DMODEL];
__device__ float g_X1[NTOT * DMODEL];

// single fp16 weights (A-side hi/lo split happens in-kernel; exact A => only W quantization error)
__device__ __half g_Wq16[DMODEL * DMODEL];
__device__ __half g_Wo16[DMODEL * DMODEL];
__device__ __half g_W116[DFFN * DMODEL];
__device__ __half g_W216[DMODEL * DFFN];

__device__ __forceinline__ float nan_to_num_f(float x) {
    if (isnan(x)) return 0.0f;
    if (isinf(x)) return x > 0.0f ? 3.402823466e38f : -3.402823466e38f;
    return x;
}

__device__ __forceinline__ void mma16816h(float* d,
    uint32_t a0, uint32_t a1, uint32_t a2, uint32_t a3,
    uint32_t b0, uint32_t b1)
{
    asm volatile(
        "mma.sync.aligned.m16n8k16.row.col.f32.f16.f16.f32 "
        "{%0,%1,%2,%3}, {%4,%5,%6,%7}, {%8,%9}, {%0,%1,%2,%3};\n"
        : "+f"(d[0]), "+f"(d[1]), "+f"(d[2]), "+f"(d[3])
        : "r"(a0), "r"(a1), "r"(a2), "r"(a3), "r"(b0), "r"(b1));
}

__device__ __forceinline__ uint32_t ld_u32h(const __half* p) {
    return *(const uint32_t*)p;
}
__device__ __forceinline__ uint32_t pack_h2(__half lo, __half hi) {
    uint32_t a = (uint32_t)__half_as_ushort(lo);
    uint32_t b = (uint32_t)__half_as_ushort(hi);
    return a | (b << 16);
}

// ============================================================================
// Kernel 0: convert fp32 weights to fp16
// ============================================================================
__global__ __launch_bounds__(256) void split_weights_kernel(
    const float* __restrict__ Wq, const float* __restrict__ Wo,
    const float* __restrict__ W1, const float* __restrict__ W2)
{
    const int NQ = DMODEL * DMODEL;
    const int N1 = DFFN * DMODEL;
    int i = blockIdx.x * 256 + threadIdx.x;
    if (i < NQ)               g_Wq16[i] = __float2half(Wq[i]);
    else if (i < 2*NQ)        g_Wo16[i - NQ] = __float2half(Wo[i - NQ]);
    else if (i < 2*NQ + N1)   g_W116[i - 2*NQ] = __float2half(W1[i - 2*NQ]);
    else if (i < 2*NQ + 2*N1) g_W216[i - 2*NQ - N1] = __float2half(W2[i - 2*NQ - N1]);
}

// ============================================================================
// Kernel 1: K/V projections (small, fp32 SIMT) — unchanged
// ============================================================================
__global__ __launch_bounds__(256) void kv_kernel(
    const float* __restrict__ boxf, const float* __restrict__ boxp,
    const float* __restrict__ Wk, const float* __restrict__ bk,
    const float* __restrict__ Wv, const float* __restrict__ bv)
{
    __shared__ float Asf[64 * 17];
    __shared__ float Asp[64 * 17];
    __shared__ float Bsk[16 * 193];
    __shared__ float Bsv[16 * 193];
    const int t = threadIdx.x;
    const int m0 = blockIdx.x * 64;
    const int tx = t & 15, ty = t >> 4;

    float ak[4][12], av[4][12];
#pragma unroll
    for (int i = 0; i < 4; i++)
#pragma unroll
        for (int j = 0; j < 12; j++) { ak[i][j] = 0.f; av[i][j] = 0.f; }

    for (int kt = 0; kt < BDIM; kt += 16) {
        __syncthreads();
        for (int i = t; i < 64 * 16; i += 256) {
            int r = i >> 4, k = i & 15;
            Asf[r * 17 + k] = boxf[(m0 + r) * BDIM + kt + k];
            Asp[r * 17 + k] = boxp[(m0 + r) * BDIM + kt + k];
        }
        for (int i = t; i < 16 * DMODEL; i += 256) {
            int d = i >> 4, k = i & 15;
            Bsk[k * 193 + d] = Wk[d * BDIM + kt + k];
            Bsv[k * 193 + d] = Wv[d * BDIM + kt + k];
        }
        __syncthreads();
#pragma unroll
        for (int k = 0; k < 16; k++) {
            float af[4], aa[4], wkr[12], wvr[12];
#pragma unroll
            for (int i = 0; i < 4; i++) {
                af[i] = Asf[(ty * 4 + i) * 17 + k];
                aa[i] = af[i] + Asp[(ty * 4 + i) * 17 + k];
            }
#pragma unroll
            for (int j = 0; j < 12; j++) {
                wkr[j] = Bsk[k * 193 + tx * 12 + j];
                wvr[j] = Bsv[k * 193 + tx * 12 + j];
            }
#pragma unroll
            for (int i = 0; i < 4; i++)
#pragma unroll
                for (int j = 0; j < 12; j++) {
                    ak[i][j] = fmaf(aa[i], wkr[j], ak[i][j]);
                    av[i][j] = fmaf(af[i], wvr[j], av[i][j]);
                }
        }
    }
#pragma unroll
    for (int i = 0; i < 4; i++) {
        int m = m0 + ty * 4 + i;
#pragma unroll
        for (int j = 0; j < 12; j++) {
            int d = tx * 12 + j;
            g_K[m * DMODEL + d] = ak[i][j] + bk[d];
            g_V[m * DMODEL + d] = av[i][j] + bv[d];
        }
    }
}

// ============================================================================
// Kernel 2: Q = gather(src+pos) @ Wq^T + bq   — fp16x2 mma.sync, 64 rows
// smem: Ah/Al [64][200] fp16 (25600 each) | B [192][200] fp16 (76800) | gI
// ============================================================================
#define SA 200
__global__ __launch_bounds__(256) void qproj_mma_kernel(
    const float* __restrict__ src, const float* __restrict__ pos,
    const int* __restrict__ vinds, const float* __restrict__ bq)
{
    extern __shared__ char smc[];
    __half* Ah = (__half*)smc;
    __half* Al = (__half*)(smc + 25600);
    __half* Bs = (__half*)(smc + 51200);
    int* gI = (int*)(smc + 128000);
    const int t = threadIdx.x;
    const int r0g = blockIdx.x * 64;
    if (t < 64) gI[t] = vinds[r0g + t];
    __syncthreads();
    for (int i = t; i < 64 * DMODEL; i += 256) {
        int r = i / DMODEL, c = i % DMODEL;
        int g = gI[r];
        float x = src[g * DMODEL + c] + pos[g * DMODEL + c];
        __half h = __float2half(x);
        Ah[r * SA + c] = h;
        Al[r * SA + c] = __float2half(x - __half2float(h));
    }
    for (int i = t; i < DMODEL * 96; i += 256) {
        int d = i / 96, kp = i % 96;
        *(uint32_t*)&Bs[d * SA + kp * 2] = ((const uint32_t*)g_Wq16)[d * 96 + kp];
    }
    __syncthreads();

    const int w = t >> 5, lane = t & 31;
    const int r0 = (w & 3) * 16, c0 = (w >> 2) * 96;
    const int lr = lane >> 2, lk = (lane & 3) * 2;
    float acc[12][4];
#pragma unroll
    for (int n = 0; n < 12; n++)
#pragma unroll
        for (int q = 0; q < 4; q++) acc[n][q] = 0.f;

    const __half* As2[2] = {Ah, Al};
#pragma unroll 1
    for (int s = 0; s < 2; s++) {
        const __half* A = As2[s];
#pragma unroll
        for (int kk = 0; kk < 12; kk++) {
            int kb = kk * 16;
            uint32_t a0 = ld_u32h(&A[(r0 + lr) * SA + kb + lk]);
            uint32_t a1 = ld_u32h(&A[(r0 + lr + 8) * SA + kb + lk]);
            uint32_t a2 = ld_u32h(&A[(r0 + lr) * SA + kb + lk + 8]);
            uint32_t a3 = ld_u32h(&A[(r0 + lr + 8) * SA + kb + lk + 8]);
#pragma unroll
            for (int nt = 0; nt < 12; nt++) {
                uint32_t b0 = ld_u32h(&Bs[(c0 + nt * 8 + lr) * SA + kb + lk]);
                uint32_t b1 = ld_u32h(&Bs[(c0 + nt * 8 + lr) * SA + kb + lk + 8]);
                mma16816h(acc[nt], a0, a1, a2, a3, b0, b1);
            }
        }
    }
#pragma unroll
    for (int nt = 0; nt < 12; nt++) {
        int col = c0 + nt * 8 + lk;
        int row = r0g + r0 + lr;
        float2 v0 = make_float2(acc[nt][0] + bq[col], acc[nt][1] + bq[col + 1]);
        float2 v1 = make_float2(acc[nt][2] + bq[col], acc[nt][3] + bq[col + 1]);
        *(float2*)&g_Q[row * DMODEL + col] = v0;
        *(float2*)&g_Q[(row + 8) * DMODEL + col] = v1;
    }
}

// ============================================================================
// Kernel 3: attention per (32-query tile, head) — fp32 SIMT (unchanged)
// ============================================================================
__global__ __launch_bounds__(256) void attn_kernel(
    const int* __restrict__ vinds, const int* __restrict__ vcrd,
    const int* __restrict__ bcrd)
{
    extern __shared__ float sm[];
    float* Qs  = sm;
    float* Khs = sm + 800;
    float* Vhs = sm + 800 + 6400;
    float* Ss  = sm + 800 + 12800;
    float* part = sm + 800 + 12800 + 8224;
    int* qb = (int*)(sm + 800 + 12800 + 8224 + 3072);
    int* bb = qb + 32;

    const int t = threadIdx.x;
    const int q0 = blockIdx.x * 32;
    const int h = blockIdx.y;

    if (t < 32) { int g = vinds[q0 + t]; qb[t] = vcrd[g * 4]; }
    bb[t] = bcrd[t * 4];
    for (int i = t; i < 32 * DHEAD; i += 256) {
        int q = i / DHEAD, d = i % DHEAD;
        Qs[q * 25 + d] = g_Q[(q0 + q) * DMODEL + h * DHEAD + d];
    }
    for (int i = t; i < MTOK * DHEAD; i += 256) {
        int m = i / DHEAD, d = i % DHEAD;
        Khs[m * 25 + d] = g_K[m * DMODEL + h * DHEAD + d];
        Vhs[m * 25 + d] = g_V[m * DMODEL + h * DHEAD + d];
    }
    __syncthreads();

    const int mg = t & 31, qg = t >> 5;
    float sc[4][8];
#pragma unroll
    for (int i = 0; i < 4; i++)
#pragma unroll
        for (int j = 0; j < 8; j++) sc[i][j] = 0.f;
#pragma unroll
    for (int k = 0; k < DHEAD; k++) {
        float a[4], b[8];
#pragma unroll
        for (int i = 0; i < 4; i++) a[i] = Qs[(qg * 4 + i) * 25 + k];
#pragma unroll
        for (int j = 0; j < 8; j++) b[j] = Khs[(mg + j * 32) * 25 + k];
#pragma unroll
        for (int i = 0; i < 4; i++)
#pragma unroll
            for (int j = 0; j < 8; j++) sc[i][j] = fmaf(a[i], b[j], sc[i][j]);
    }
    const float scale = 0.20412414523193154f;
    const float NEG_INF = -__int_as_float(0x7f800000);
#pragma unroll
    for (int i = 0; i < 4; i++) {
        int q = qg * 4 + i;
#pragma unroll
        for (int j = 0; j < 8; j++) {
            int m = mg + j * 32;
            float s = sc[i][j] * scale;
            if (qb[q] != bb[m]) s = NEG_INF;
            Ss[q * 257 + m] = s;
        }
    }
    __syncthreads();

    {
        const int w = t >> 5, lane = t & 31;
        for (int rr = 0; rr < 4; rr++) {
            int q = w * 4 + rr;
            float v[8]; float mx = NEG_INF;
#pragma unroll
            for (int j = 0; j < 8; j++) {
                v[j] = Ss[q * 257 + lane + j * 32];
                mx = fmaxf(mx, v[j]);
            }
#pragma unroll
            for (int o = 16; o; o >>= 1) mx = fmaxf(mx, __shfl_xor_sync(0xffffffffu, mx, o));
            float ssum = 0.f;
#pragma unroll
            for (int j = 0; j < 8; j++) { v[j] = __expf(v[j] - mx); ssum += v[j]; }
#pragma unroll
            for (int o = 16; o; o >>= 1) ssum += __shfl_xor_sync(0xffffffffu, ssum, o);
            float inv = 1.0f / ssum;
#pragma unroll
            for (int j = 0; j < 8; j++) Ss[q * 257 + lane + j * 32] = v[j] * inv;
        }
    }
    __syncthreads();

    {
        const int grp = t >> 6, u = t & 63;
        const int qg2 = u >> 2, dg = u & 3;
        float c2[2][6];
#pragma unroll
        for (int i = 0; i < 2; i++)
#pragma unroll
            for (int j = 0; j < 6; j++) c2[i][j] = 0.f;
        for (int mm = 0; mm < 64; mm++) {
            int m = grp * 64 + mm;
            float p0 = Ss[(qg2 * 2 + 0) * 257 + m];
            float p1 = Ss[(qg2 * 2 + 1) * 257 + m];
            float vv[6];
#pragma unroll
            for (int j = 0; j < 6; j++) vv[j] = Vhs[m * 25 + dg * 6 + j];
#pragma unroll
            for (int j = 0; j < 6; j++) {
                c2[0][j] = fmaf(p0, vv[j], c2[0][j]);
                c2[1][j] = fmaf(p1, vv[j], c2[1][j]);
            }
        }
#pragma unroll
        for (int i = 0; i < 2; i++)
#pragma unroll
            for (int j = 0; j < 6; j++)
                part[(grp * 32 + qg2 * 2 + i) * 24 + dg * 6 + j] = c2[i][j];
    }
    __syncthreads();
    for (int o = t; o < 32 * 24; o += 256) {
        int q = o / 24, d = o % 24;
        float s = part[q * 24 + d] + part[(32 + q) * 24 + d]
                + part[(64 + q) * 24 + d] + part[(96 + q) * 24 + d];
        g_CTX[(q0 + q) * DMODEL + h * DHEAD + d] = s;
    }
}

// ============================================================================
// Kernel 4: O-proj + residual + LN1 — fp16x2 mma.sync, 64 rows
// ============================================================================
__global__ __launch_bounds__(256) void oproj_mma_kernel(
    const float* __restrict__ src, const int* __restrict__ vinds,
    const float* __restrict__ bo,
    const float* __restrict__ ln1g, const float* __restrict__ ln1b)
{
    extern __shared__ char smc[];
    __half* Ah = (__half*)smc;
    __half* Al = (__half*)(smc + 25600);
    __half* Bs = (__half*)(smc + 51200);
    int* gI = (int*)(smc + 128000);
    float* Ys = (float*)(smc + 51200);   // overlays B after GEMM (51200 <= 76800)
    const int t = threadIdx.x;
    const int r0g = blockIdx.x * 64;
    if (t < 64) gI[t] = vinds[r0g + t];
    for (int i = t; i < 64 * DMODEL; i += 256) {
        int r = i / DMODEL, c = i % DMODEL;
        float x = g_CTX[(r0g + r) * DMODEL + c];
        __half h = __float2half(x);
        Ah[r * SA + c] = h;
        Al[r * SA + c] = __float2half(x - __half2float(h));
    }
    for (int i = t; i < DMODEL * 96; i += 256) {
        int d = i / 96, kp = i % 96;
        *(uint32_t*)&Bs[d * SA + kp * 2] = ((const uint32_t*)g_Wo16)[d * 96 + kp];
    }
    __syncthreads();

    const int w = t >> 5, lane = t & 31;
    const int r0 = (w & 3) * 16, c0 = (w >> 2) * 96;
    const int lr = lane >> 2, lk = (lane & 3) * 2;
    float acc[12][4];
#pragma unroll
    for (int n = 0; n < 12; n++)
#pragma unroll
        for (int q = 0; q < 4; q++) acc[n][q] = 0.f;

    const __half* As2[2] = {Ah, Al};
#pragma unroll 1
    for (int s = 0; s < 2; s++) {
        const __half* A = As2[s];
#pragma unroll
        for (int kk = 0; kk < 12; kk++) {
            int kb = kk * 16;
            uint32_t a0 = ld_u32h(&A[(r0 + lr) * SA + kb + lk]);
            uint32_t a1 = ld_u32h(&A[(r0 + lr + 8) * SA + kb + lk]);
            uint32_t a2 = ld_u32h(&A[(r0 + lr) * SA + kb + lk + 8]);
            uint32_t a3 = ld_u32h(&A[(r0 + lr + 8) * SA + kb + lk + 8]);
#pragma unroll
            for (int nt = 0; nt < 12; nt++) {
                uint32_t b0 = ld_u32h(&Bs[(c0 + nt * 8 + lr) * SA + kb + lk]);
                uint32_t b1 = ld_u32h(&Bs[(c0 + nt * 8 + lr) * SA + kb + lk + 8]);
                mma16816h(acc[nt], a0, a1, a2, a3, b0, b1);
            }
        }
    }
    __syncthreads();
#pragma unroll
    for (int nt = 0; nt < 12; nt++) {
        int col = c0 + nt * 8 + lk;
        int row = r0 + lr;
        Ys[row * SA + col]           = nan_to_num_f(acc[nt][0] + bo[col]);
        Ys[row * SA + col + 1]       = nan_to_num_f(acc[nt][1] + bo[col + 1]);
        Ys[(row + 8) * SA + col]     = nan_to_num_f(acc[nt][2] + bo[col]);
        Ys[(row + 8) * SA + col + 1] = nan_to_num_f(acc[nt][3] + bo[col + 1]);
    }
    __syncthreads();
    for (int rr = 0; rr < 8; rr++) {
        int r = w * 8 + rr;
        int g = gI[r];
        float v[6];
#pragma unroll
        for (int c = 0; c < 6; c++)
            v[c] = Ys[r * SA + lane * 6 + c] + src[g * DMODEL + lane * 6 + c];
        float s = 0.f;
#pragma unroll
        for (int c = 0; c < 6; c++) s += v[c];
#pragma unroll
        for (int o = 16; o; o >>= 1) s += __shfl_xor_sync(0xffffffffu, s, o);
        float mean = s * (1.0f / 192.0f);
        float vs = 0.f;
#pragma unroll
        for (int c = 0; c < 6; c++) { float d0 = v[c] - mean; vs += d0 * d0; }
#pragma unroll
        for (int o = 16; o; o >>= 1) vs += __shfl_xor_sync(0xffffffffu, vs, o);
        float inv = rsqrtf(vs * (1.0f / 192.0f) + LN_EPS);
#pragma unroll
        for (int c = 0; c < 6; c++) {
            int d = lane * 6 + c;
            g_X1[g * DMODEL + d] = (v[c] - mean) * inv * ln1g[d] + ln1b[d];
        }
    }
}

// ============================================================================
// Kernel 5: FFN + residual + LN2 — fp16x2 mma.sync, 256 threads / 64 rows
// smem: Xh@0 Xl@25600 (fp16 [64][200]) | WU@51200 (51200: W1 [64][200] fp16 OR
//       W2 [192][72] fp16 OR Ys f32 [64][200]) | Hh@102400 Hl@111616 ([64][72] fp16)
//       total 120832
// ============================================================================
#define SH 72
__global__ __launch_bounds__(256) void ffn_mma_kernel(
    const float* __restrict__ b1, const float* __restrict__ b2,
    const float* __restrict__ ln2g, const float* __restrict__ ln2b,
    float* __restrict__ out)
{
    extern __shared__ char smc[];
    __half* Xh = (__half*)smc;
    __half* Xl = (__half*)(smc + 25600);
    char* WU = smc + 51200;
    __half* W1s = (__half*)WU;           // [64][200]
    __half* W2s = (__half*)WU;           // [192][72]
    float* Ys = (float*)WU;              // [64][200] f32
    __half* Hh = (__half*)(smc + 102400);
    __half* Hl = (__half*)(smc + 111616);
    const int t = threadIdx.x, w = t >> 5, lane = t & 31;
    const int r0g = blockIdx.x * 64;
    const int lr = lane >> 2, lk = (lane & 3) * 2;
    const int r0 = (w & 3) * 16;
    const int c0h = (w >> 2) * 32;
    const int c0y = (w >> 2) * 96;

    for (int i = t; i < 64 * DMODEL; i += 256) {
        int r = i / DMODEL, c = i % DMODEL;
        float x = g_X1[(r0g + r) * DMODEL + c];
        __half h = __float2half(x);
        Xh[r * SA + c] = h;
        Xl[r * SA + c] = __float2half(x - __half2float(h));
    }

    float y[12][4];
#pragma unroll
    for (int n = 0; n < 12; n++)
#pragma unroll
        for (int q = 0; q < 4; q++) y[n][q] = 0.f;

#pragma unroll 1
    for (int fc = 0; fc < DFFN; fc += 64) {
        __syncthreads();
        for (int i = t; i < 64 * 96; i += 256) {
            int f = i / 96, kp = i % 96;
            *(uint32_t*)&W1s[f * SA + kp * 2] = ((const uint32_t*)g_W116)[(fc + f) * 96 + kp];
        }
        __syncthreads();
        // ---- phase 1: H = relu(X @ W1c^T + b1)  (fp16x2: Xh + Xl vs single W1) ----
        float hacc[4][4];
#pragma unroll
        for (int n = 0; n < 4; n++)
#pragma unroll
            for (int q = 0; q < 4; q++) hacc[n][q] = 0.f;
        {
            const __half* As2[2] = {Xh, Xl};
#pragma unroll 1
            for (int s = 0; s < 2; s++) {
                const __half* A = As2[s];
#pragma unroll
                for (int kk = 0; kk < 12; kk++) {
                    int kb = kk * 16;
                    uint32_t a0 = ld_u32h(&A[(r0 + lr) * SA + kb + lk]);
                    uint32_t a1 = ld_u32h(&A[(r0 + lr + 8) * SA + kb + lk]);
                    uint32_t a2 = ld_u32h(&A[(r0 + lr) * SA + kb + lk + 8]);
                    uint32_t a3 = ld_u32h(&A[(r0 + lr + 8) * SA + kb + lk + 8]);
#pragma unroll
                    for (int nt = 0; nt < 4; nt++) {
                        uint32_t b0 = ld_u32h(&W1s[(c0h + nt * 8 + lr) * SA + kb + lk]);
                        uint32_t b1r = ld_u32h(&W1s[(c0h + nt * 8 + lr) * SA + kb + lk + 8]);
                        mma16816h(hacc[nt], a0, a1, a2, a3, b0, b1r);
                    }
                }
            }
        }
#pragma unroll
        for (int nt = 0; nt < 4; nt++) {
            int col = c0h + nt * 8 + lk;
            int fg = fc + col;
            float bv0 = b1[fg], bv1 = b1[fg + 1];
            float h00 = fmaxf(hacc[nt][0] + bv0, 0.f);
            float h01 = fmaxf(hacc[nt][1] + bv1, 0.f);
            float h10 = fmaxf(hacc[nt][2] + bv0, 0.f);
            float h11 = fmaxf(hacc[nt][3] + bv1, 0.f);
            __half a0 = __float2half(h00);
            __half a1 = __float2half(h01);
            __half a2 = __float2half(h10);
            __half a3 = __float2half(h11);
            *(uint32_t*)&Hh[(r0 + lr) * SH + col] = pack_h2(a0, a1);
            *(uint32_t*)&Hh[(r0 + lr + 8) * SH + col] = pack_h2(a2, a3);
            __half l0 = __float2half(h00 - __half2float(a0));
            __half l1 = __float2half(h01 - __half2float(a1));
            __half l2 = __float2half(h10 - __half2float(a2));
            __half l3 = __float2half(h11 - __half2float(a3));
            *(uint32_t*)&Hl[(r0 + lr) * SH + col] = pack_h2(l0, l1);
            *(uint32_t*)&Hl[(r0 + lr + 8) * SH + col] = pack_h2(l2, l3);
        }
        __syncthreads();
        // stage W2 chunk [d][f] -> [192][72]
        for (int i = t; i < DMODEL * 32; i += 256) {
            int d = i / 32, kp = i % 32;
            *(uint32_t*)&W2s[d * SH + kp * 2] = ((const uint32_t*)g_W216)[d * (DFFN / 2) + (fc >> 1) + kp];
        }
        __syncthreads();
        // ---- phase 2: Y += H @ W2c^T  (fp16x2: Hh + Hl vs single W2) ----
        {
            const __half* As2[2] = {Hh, Hl};
#pragma unroll 1
            for (int s = 0; s < 2; s++) {
                const __half* A = As2[s];
#pragma unroll
                for (int kk = 0; kk < 4; kk++) {
                    int kb = kk * 16;
                    uint32_t a0 = ld_u32h(&A[(r0 + lr) * SH + kb + lk]);
                    uint32_t a1 = ld_u32h(&A[(r0 + lr + 8) * SH + kb + lk]);
                    uint32_t a2 = ld_u32h(&A[(r0 + lr) * SH + kb + lk + 8]);
                    uint32_t a3 = ld_u32h(&A[(r0 + lr + 8) * SH + kb + lk + 8]);
#pragma unroll
                    for (int nt = 0; nt < 12; nt++) {
                        uint32_t b0 = ld_u32h(&W2s[(c0y + nt * 8 + lr) * SH + kb + lk]);
                        uint32_t b1r = ld_u32h(&W2s[(c0y + nt * 8 + lr) * SH + kb + lk + 8]);
                        mma16816h(y[nt], a0, a1, a2, a3, b0, b1r);
                    }
                }
            }
        }
    }
    __syncthreads();
#pragma unroll
    for (int nt = 0; nt < 12; nt++) {
        int col = c0y + nt * 8 + lk;
        int row = r0 + lr;
        Ys[row * SA + col]           = y[nt][0];
        Ys[row * SA + col + 1]       = y[nt][1];
        Ys[(row + 8) * SA + col]     = y[nt][2];
        Ys[(row + 8) * SA + col + 1] = y[nt][3];
    }
    __syncthreads();
    for (int rr = 0; rr < 8; rr++) {
        int r = w * 8 + rr;
        float v[6];
#pragma unroll
        for (int c = 0; c < 6; c++) {
            int d = lane * 6 + c;
            v[c] = Ys[r * SA + d] + b2[d] + g_X1[(r0g + r) * DMODEL + d];
        }
        float s = 0.f;
#pragma unroll
        for (int c = 0; c < 6; c++) s += v[c];
#pragma unroll
        for (int o = 16; o; o >>= 1) s += __shfl_xor_sync(0xffffffffu, s, o);
        float mean = s * (1.0f / 192.0f);
        float vs = 0.f;
#pragma unroll
        for (int c = 0; c < 6; c++) { float d0 = v[c] - mean; vs += d0 * d0; }
#pragma unroll
        for (int o = 16; o; o >>= 1) vs += __shfl_xor_sync(0xffffffffu, vs, o);
        float inv = rsqrtf(vs * (1.0f / 192.0f) + LN_EPS);
#pragma unroll
        for (int c = 0; c < 6; c++) {
            int d = lane * 6 + c;
            out[(r0g + r) * DMODEL + d] = (v[c] - mean) * inv * ln2g[d] + ln2b[d];
        }
    }
}

// ============================================================================
extern "C" void kernel_launch(void* const* d_in, const int* in_sizes, int n_in,
                              void* d_out, int out_size)
{
    const float* src  = (const float*)d_in[0];
    const int*   vcrd = (const int*)d_in[1];
    const float* boxf = (const float*)d_in[2];
    const int*   bcrd = (const int*)d_in[3];
    const float* pos  = (const float*)d_in[4];
    const float* boxp = (const float*)d_in[5];
    const int*   vind = (const int*)d_in[6];
    const float* Wq = (const float*)d_in[7];
    const float* bq = (const float*)d_in[8];
    const float* Wk = (const float*)d_in[9];
    const float* bk = (const float*)d_in[10];
    const float* Wv = (const float*)d_in[11];
    const float* bv = (const float*)d_in[12];
    const float* Wo = (const float*)d_in[13];
    const float* bo = (const float*)d_in[14];
    const float* W1 = (const float*)d_in[15];
    const float* b1 = (const float*)d_in[16];
    const float* W2 = (const float*)d_in[17];
    const float* b2 = (const float*)d_in[18];
    const float* g1 = (const float*)d_in[19];
    const float* lb1 = (const float*)d_in[20];
    const float* g2 = (const float*)d_in[21];
    const float* lb2 = (const float*)d_in[22];
    float* out = (float*)d_out;

    const int SMEM_PROJ = 128256;
    const int SMEM_ATTN = (800 + 6400 + 6400 + 8224 + 3072) * 4 + 288 * 4;
    const int SMEM_FFN  = 120832;

    cudaFuncSetAttribute(qproj_mma_kernel, cudaFuncAttributeMaxDynamicSharedMemorySize, SMEM_PROJ);
    cudaFuncSetAttribute(oproj_mma_kernel, cudaFuncAttributeMaxDynamicSharedMemorySize, SMEM_PROJ);
    cudaFuncSetAttribute(attn_kernel, cudaFuncAttributeMaxDynamicSharedMemorySize, SMEM_ATTN);
    cudaFuncSetAttribute(ffn_mma_kernel, cudaFuncAttributeMaxDynamicSharedMemorySize, SMEM_FFN);

    split_weights_kernel<<<3360, 256>>>(Wq, Wo, W1, W2);
    kv_kernel<<<MTOK / 64, 256>>>(boxf, boxp, Wk, bk, Wv, bv);
    qproj_mma_kernel<<<NTOT / 64, 256, SMEM_PROJ>>>(src, pos, vind, bq);
    attn_kernel<<<dim3(NTOT / 32, NHEAD), 256, SMEM_ATTN>>>(vind, vcrd, bcrd);
    oproj_mma_kernel<<<NTOT / 64, 256, SMEM_PROJ>>>(src, vind, bo, g1, lb1);
    ffn_mma_kernel<<<NTOT / 64, 256, SMEM_FFN>>>(b1, b2, g2, lb2, out);
}

// round 11
// speedup vs baseline: 2.2014x; 1.3183x over previous
#include <cuda_runtime.h>
#include <cuda_fp16.h>
#include <math.h>
#include <stdint.h>

#define NTOT 46080
#define DMODEL 192
#define MTOK 256
#define BDIM 256
#define NHEAD 8
#define DHEAD 24
#define DFFN 2048
#define LN_EPS 1e-5f

__device__ float g_K[MTOK * DMODEL];
__device__ float g_V[MTOK * DMODEL];
__device__ float g_Q[NTOT * DMODEL];
__device__ float g_CTX[NTOT * DMODEL];
__device__ float g_X1[NTOT * DMODEL];

__device__ __half g_Wq16[DMODEL * DMODEL];
__device__ __half g_Wo16[DMODEL * DMODEL];
__device__ __half g_W116[DFFN * DMODEL];
__device__ __half g_W216[DMODEL * DFFN];

__device__ __forceinline__ float nan_to_num_f(float x) {
    if (isnan(x)) return 0.0f;
    if (isinf(x)) return x > 0.0f ? 3.402823466e38f : -3.402823466e38f;
    return x;
}

__device__ __forceinline__ void mma16816h(float* d,
    uint32_t a0, uint32_t a1, uint32_t a2, uint32_t a3,
    uint32_t b0, uint32_t b1)
{
    asm volatile(
        "mma.sync.aligned.m16n8k16.row.col.f32.f16.f16.f32 "
        "{%0,%1,%2,%3}, {%4,%5,%6,%7}, {%8,%9}, {%0,%1,%2,%3};\n"
        : "+f"(d[0]), "+f"(d[1]), "+f"(d[2]), "+f"(d[3])
        : "r"(a0), "r"(a1), "r"(a2), "r"(a3), "r"(b0), "r"(b1));
}

__device__ __forceinline__ uint32_t ld_u32h(const __half* p) {
    return *(const uint32_t*)p;
}

// ============================================================================
// Kernel 0: convert fp32 weights to fp16
// ============================================================================
__global__ __launch_bounds__(256) void split_weights_kernel(
    const float* __restrict__ Wq, const float* __restrict__ Wo,
    const float* __restrict__ W1, const float* __restrict__ W2)
{
    const int NQ = DMODEL * DMODEL;
    const int N1 = DFFN * DMODEL;
    int i = blockIdx.x * 256 + threadIdx.x;
    if (i < NQ)               g_Wq16[i] = __float2half(Wq[i]);
    else if (i < 2*NQ)        g_Wo16[i - NQ] = __float2half(Wo[i - NQ]);
    else if (i < 2*NQ + N1)   g_W116[i - 2*NQ] = __float2half(W1[i - 2*NQ]);
    else if (i < 2*NQ + 2*N1) g_W216[i - 2*NQ - N1] = __float2half(W2[i - 2*NQ - N1]);
}

// ============================================================================
// Kernel 1: K/V projections (fp32 SIMT, unchanged)
// ============================================================================
__global__ __launch_bounds__(256) void kv_kernel(
    const float* __restrict__ boxf, const float* __restrict__ boxp,
    const float* __restrict__ Wk, const float* __restrict__ bk,
    const float* __restrict__ Wv, const float* __restrict__ bv)
{
    __shared__ float Asf[64 * 17];
    __shared__ float Asp[64 * 17];
    __shared__ float Bsk[16 * 193];
    __shared__ float Bsv[16 * 193];
    const int t = threadIdx.x;
    const int m0 = blockIdx.x * 64;
    const int tx = t & 15, ty = t >> 4;

    float ak[4][12], av[4][12];
#pragma unroll
    for (int i = 0; i < 4; i++)
#pragma unroll
        for (int j = 0; j < 12; j++) { ak[i][j] = 0.f; av[i][j] = 0.f; }

    for (int kt = 0; kt < BDIM; kt += 16) {
        __syncthreads();
        for (int i = t; i < 64 * 16; i += 256) {
            int r = i >> 4, k = i & 15;
            Asf[r * 17 + k] = boxf[(m0 + r) * BDIM + kt + k];
            Asp[r * 17 + k] = boxp[(m0 + r) * BDIM + kt + k];
        }
        for (int i = t; i < 16 * DMODEL; i += 256) {
            int d = i >> 4, k = i & 15;
            Bsk[k * 193 + d] = Wk[d * BDIM + kt + k];
            Bsv[k * 193 + d] = Wv[d * BDIM + kt + k];
        }
        __syncthreads();
#pragma unroll
        for (int k = 0; k < 16; k++) {
            float af[4], aa[4], wkr[12], wvr[12];
#pragma unroll
            for (int i = 0; i < 4; i++) {
                af[i] = Asf[(ty * 4 + i) * 17 + k];
                aa[i] = af[i] + Asp[(ty * 4 + i) * 17 + k];
            }
#pragma unroll
            for (int j = 0; j < 12; j++) {
                wkr[j] = Bsk[k * 193 + tx * 12 + j];
                wvr[j] = Bsv[k * 193 + tx * 12 + j];
            }
#pragma unroll
            for (int i = 0; i < 4; i++)
#pragma unroll
                for (int j = 0; j < 12; j++) {
                    ak[i][j] = fmaf(aa[i], wkr[j], ak[i][j]);
                    av[i][j] = fmaf(af[i], wvr[j], av[i][j]);
                }
        }
    }
#pragma unroll
    for (int i = 0; i < 4; i++) {
        int m = m0 + ty * 4 + i;
#pragma unroll
        for (int j = 0; j < 12; j++) {
            int d = tx * 12 + j;
            g_K[m * DMODEL + d] = ak[i][j] + bk[d];
            g_V[m * DMODEL + d] = av[i][j] + bv[d];
        }
    }
}

// ============================================================================
// Kernel 2: Q-proj — fp16x1 mma.sync, 64 rows
// smem: A [64][200] fp16 @0 | B [192][200] fp16 @25600 | gI @102400; tot 102656
// ============================================================================
#define SA 200
__global__ __launch_bounds__(256) void qproj_mma_kernel(
    const float* __restrict__ src, const float* __restrict__ pos,
    const int* __restrict__ vinds, const float* __restrict__ bq)
{
    extern __shared__ char smc[];
    __half* Ah = (__half*)smc;
    __half* Bs = (__half*)(smc + 25600);
    int* gI = (int*)(smc + 102400);
    const int t = threadIdx.x;
    const int r0g = blockIdx.x * 64;
    if (t < 64) gI[t] = vinds[r0g + t];
    __syncthreads();
    for (int i = t; i < 64 * DMODEL; i += 256) {
        int r = i / DMODEL, c = i % DMODEL;
        int g = gI[r];
        Ah[r * SA + c] = __float2half(src[g * DMODEL + c] + pos[g * DMODEL + c]);
    }
    for (int i = t; i < DMODEL * 96; i += 256) {
        int d = i / 96, kp = i % 96;
        *(uint32_t*)&Bs[d * SA + kp * 2] = ((const uint32_t*)g_Wq16)[d * 96 + kp];
    }
    __syncthreads();

    const int w = t >> 5, lane = t & 31;
    const int r0 = (w & 3) * 16, c0 = (w >> 2) * 96;
    const int lr = lane >> 2, lk = (lane & 3) * 2;
    float acc[12][4];
#pragma unroll
    for (int n = 0; n < 12; n++)
#pragma unroll
        for (int q = 0; q < 4; q++) acc[n][q] = 0.f;

#pragma unroll
    for (int kk = 0; kk < 12; kk++) {
        int kb = kk * 16;
        uint32_t a0 = ld_u32h(&Ah[(r0 + lr) * SA + kb + lk]);
        uint32_t a1 = ld_u32h(&Ah[(r0 + lr + 8) * SA + kb + lk]);
        uint32_t a2 = ld_u32h(&Ah[(r0 + lr) * SA + kb + lk + 8]);
        uint32_t a3 = ld_u32h(&Ah[(r0 + lr + 8) * SA + kb + lk + 8]);
#pragma unroll
        for (int nt = 0; nt < 12; nt++) {
            uint32_t b0 = ld_u32h(&Bs[(c0 + nt * 8 + lr) * SA + kb + lk]);
            uint32_t b1 = ld_u32h(&Bs[(c0 + nt * 8 + lr) * SA + kb + lk + 8]);
            mma16816h(acc[nt], a0, a1, a2, a3, b0, b1);
        }
    }
#pragma unroll
    for (int nt = 0; nt < 12; nt++) {
        int col = c0 + nt * 8 + lk;
        int row = r0g + r0 + lr;
        float2 v0 = make_float2(acc[nt][0] + bq[col], acc[nt][1] + bq[col + 1]);
        float2 v1 = make_float2(acc[nt][2] + bq[col], acc[nt][3] + bq[col + 1]);
        *(float2*)&g_Q[row * DMODEL + col] = v0;
        *(float2*)&g_Q[(row + 8) * DMODEL + col] = v1;
    }
}

// ============================================================================
// Kernel 3: attention — fp16 mma (QK^T and P@V), fp32 softmax
// grid (1440, 8) x 256. smem layout (bytes):
//   Qs fp16 [32][40]  @0      (2560)
//   Ks fp16 [256][40] @2560   (20480)
//   Vt fp16 [24][264] @23040  (12672)
//   Ss f32  [32][257] @35712  (32896)
//   Pt fp16 [32][264] @68608  (16896)
//   qb int[32] @85504, bb int[256] @85632  -> total 86656
// ============================================================================
__global__ __launch_bounds__(256) void attn_mma_kernel(
    const int* __restrict__ vinds, const int* __restrict__ vcrd,
    const int* __restrict__ bcrd)
{
    extern __shared__ char smc[];
    __half* Qs = (__half*)smc;
    __half* Ks = (__half*)(smc + 2560);
    __half* Vt = (__half*)(smc + 23040);
    float*  Ss = (float*)(smc + 35712);
    __half* Pt = (__half*)(smc + 68608);
    int* qb = (int*)(smc + 85504);
    int* bb = (int*)(smc + 85632);

    const int t = threadIdx.x;
    const int q0 = blockIdx.x * 32;
    const int h = blockIdx.y;

    if (t < 32) { int g = vinds[q0 + t]; qb[t] = vcrd[g * 4]; }
    bb[t] = bcrd[t * 4];
    // Q tile [32][32] (K padded 24->32 with zeros)
    for (int i = t; i < 32 * 32; i += 256) {
        int r = i >> 5, d = i & 31;
        Qs[r * 40 + d] = (d < DHEAD) ? __float2half(g_Q[(q0 + r) * DMODEL + h * DHEAD + d])
                                     : __ushort_as_half(0);
    }
    // K tile [256][32]
    for (int i = t; i < MTOK * 32; i += 256) {
        int m = i >> 5, d = i & 31;
        Ks[m * 40 + d] = (d < DHEAD) ? __float2half(g_K[m * DMODEL + h * DHEAD + d])
                                     : __ushort_as_half(0);
    }
    // V transposed [24][256]
    for (int i = t; i < DHEAD * MTOK; i += 256) {
        int d = i >> 8, m = i & 255;
        Vt[d * 264 + m] = __float2half(g_V[m * DMODEL + h * DHEAD + d]);
    }
    __syncthreads();

    const int w = t >> 5, lane = t & 31;
    const int lr = lane >> 2, lk = (lane & 3) * 2;

    // ---- phase B: S = Q @ K^T (warp: m-tile w&1, n-cols (w>>1)*64) ----
    {
        const int mt = (w & 1) * 16, c0 = (w >> 1) * 64;
        float acc[8][4];
#pragma unroll
        for (int n = 0; n < 8; n++)
#pragma unroll
            for (int q = 0; q < 4; q++) acc[n][q] = 0.f;
#pragma unroll
        for (int ks = 0; ks < 2; ks++) {
            int kb = ks * 16;
            uint32_t a0 = ld_u32h(&Qs[(mt + lr) * 40 + kb + lk]);
            uint32_t a1 = ld_u32h(&Qs[(mt + lr + 8) * 40 + kb + lk]);
            uint32_t a2 = ld_u32h(&Qs[(mt + lr) * 40 + kb + lk + 8]);
            uint32_t a3 = ld_u32h(&Qs[(mt + lr + 8) * 40 + kb + lk + 8]);
#pragma unroll
            for (int nt = 0; nt < 8; nt++) {
                uint32_t b0 = ld_u32h(&Ks[(c0 + nt * 8 + lr) * 40 + kb + lk]);
                uint32_t b1 = ld_u32h(&Ks[(c0 + nt * 8 + lr) * 40 + kb + lk + 8]);
                mma16816h(acc[nt], a0, a1, a2, a3, b0, b1);
            }
        }
        const float scale = 0.20412414523193154f;
        const float NEG_INF = -__int_as_float(0x7f800000);
#pragma unroll
        for (int nt = 0; nt < 8; nt++) {
            int col = c0 + nt * 8 + lk;
#pragma unroll
            for (int half_ = 0; half_ < 2; half_++) {
                int q = mt + lr + half_ * 8;
                float s0 = acc[nt][half_ * 2] * scale;
                float s1 = acc[nt][half_ * 2 + 1] * scale;
                int qv = qb[q];
                if (qv != bb[col]) s0 = NEG_INF;
                if (qv != bb[col + 1]) s1 = NEG_INF;
                Ss[q * 257 + col] = s0;
                Ss[q * 257 + col + 1] = s1;
            }
        }
    }
    __syncthreads();

    // ---- softmax (fp32) -> Pt (fp16) ----
    {
        const float NEG_INF = -__int_as_float(0x7f800000);
        for (int rr = 0; rr < 4; rr++) {
            int q = w * 4 + rr;
            float v[8]; float mx = NEG_INF;
#pragma unroll
            for (int j = 0; j < 8; j++) {
                v[j] = Ss[q * 257 + lane + j * 32];
                mx = fmaxf(mx, v[j]);
            }
#pragma unroll
            for (int o = 16; o; o >>= 1) mx = fmaxf(mx, __shfl_xor_sync(0xffffffffu, mx, o));
            float ssum = 0.f;
#pragma unroll
            for (int j = 0; j < 8; j++) { v[j] = __expf(v[j] - mx); ssum += v[j]; }
#pragma unroll
            for (int o = 16; o; o >>= 1) ssum += __shfl_xor_sync(0xffffffffu, ssum, o);
            float inv = 1.0f / ssum;   // all-masked -> NaN propagates (matches jax)
#pragma unroll
            for (int j = 0; j < 8; j++)
                Pt[q * 264 + lane + j * 32] = __float2half(v[j] * inv);
        }
    }
    __syncthreads();

    // ---- phase D: ctx = P @ V (warps 0-5: m-tile w&1, n-tile w>>1) ----
    if (w < 6) {
        const int mt = (w & 1) * 16, n0 = (w >> 1) * 8;
        float c[4] = {0.f, 0.f, 0.f, 0.f};
#pragma unroll
        for (int ks = 0; ks < 16; ks++) {
            int kb = ks * 16;
            uint32_t a0 = ld_u32h(&Pt[(mt + lr) * 264 + kb + lk]);
            uint32_t a1 = ld_u32h(&Pt[(mt + lr + 8) * 264 + kb + lk]);
            uint32_t a2 = ld_u32h(&Pt[(mt + lr) * 264 + kb + lk + 8]);
            uint32_t a3 = ld_u32h(&Pt[(mt + lr + 8) * 264 + kb + lk + 8]);
            uint32_t b0 = ld_u32h(&Vt[(n0 + lr) * 264 + kb + lk]);
            uint32_t b1 = ld_u32h(&Vt[(n0 + lr) * 264 + kb + lk + 8]);
            mma16816h(c, a0, a1, a2, a3, b0, b1);
        }
        int row = q0 + mt + lr;
        int col = h * DHEAD + n0 + lk;
        g_CTX[row * DMODEL + col] = c[0];
        g_CTX[row * DMODEL + col + 1] = c[1];
        g_CTX[(row + 8) * DMODEL + col] = c[2];
        g_CTX[(row + 8) * DMODEL + col + 1] = c[3];
    }
}

// ============================================================================
// Kernel 4: O-proj + residual + LN1 — fp16x1 mma.sync, 64 rows
// ============================================================================
__global__ __launch_bounds__(256) void oproj_mma_kernel(
    const float* __restrict__ src, const int* __restrict__ vinds,
    const float* __restrict__ bo,
    const float* __restrict__ ln1g, const float* __restrict__ ln1b)
{
    extern __shared__ char smc[];
    __half* Ah = (__half*)smc;
    __half* Bs = (__half*)(smc + 25600);
    int* gI = (int*)(smc + 102400);
    float* Ys = (float*)(smc + 25600);   // overlays B after GEMM (51200 <= 76800)
    const int t = threadIdx.x;
    const int r0g = blockIdx.x * 64;
    if (t < 64) gI[t] = vinds[r0g + t];
    for (int i = t; i < 64 * DMODEL; i += 256) {
        int r = i / DMODEL, c = i % DMODEL;
        Ah[r * SA + c] = __float2half(g_CTX[(r0g + r) * DMODEL + c]);
    }
    for (int i = t; i < DMODEL * 96; i += 256) {
        int d = i / 96, kp = i % 96;
        *(uint32_t*)&Bs[d * SA + kp * 2] = ((const uint32_t*)g_Wo16)[d * 96 + kp];
    }
    __syncthreads();

    const int w = t >> 5, lane = t & 31;
    const int r0 = (w & 3) * 16, c0 = (w >> 2) * 96;
    const int lr = lane >> 2, lk = (lane & 3) * 2;
    float acc[12][4];
#pragma unroll
    for (int n = 0; n < 12; n++)
#pragma unroll
        for (int q = 0; q < 4; q++) acc[n][q] = 0.f;

#pragma unroll
    for (int kk = 0; kk < 12; kk++) {
        int kb = kk * 16;
        uint32_t a0 = ld_u32h(&Ah[(r0 + lr) * SA + kb + lk]);
        uint32_t a1 = ld_u32h(&Ah[(r0 + lr + 8) * SA + kb + lk]);
        uint32_t a2 = ld_u32h(&Ah[(r0 + lr) * SA + kb + lk + 8]);
        uint32_t a3 = ld_u32h(&Ah[(r0 + lr + 8) * SA + kb + lk + 8]);
#pragma unroll
        for (int nt = 0; nt < 12; nt++) {
            uint32_t b0 = ld_u32h(&Bs[(c0 + nt * 8 + lr) * SA + kb + lk]);
            uint32_t b1 = ld_u32h(&Bs[(c0 + nt * 8 + lr) * SA + kb + lk + 8]);
            mma16816h(acc[nt], a0, a1, a2, a3, b0, b1);
        }
    }
    __syncthreads();
#pragma unroll
    for (int nt = 0; nt < 12; nt++) {
        int col = c0 + nt * 8 + lk;
        int row = r0 + lr;
        Ys[row * SA + col]           = nan_to_num_f(acc[nt][0] + bo[col]);
        Ys[row * SA + col + 1]       = nan_to_num_f(acc[nt][1] + bo[col + 1]);
        Ys[(row + 8) * SA + col]     = nan_to_num_f(acc[nt][2] + bo[col]);
        Ys[(row + 8) * SA + col + 1] = nan_to_num_f(acc[nt][3] + bo[col + 1]);
    }
    __syncthreads();
    for (int rr = 0; rr < 8; rr++) {
        int r = w * 8 + rr;
        int g = gI[r];
        float v[6];
#pragma unroll
        for (int c = 0; c < 6; c++)
            v[c] = Ys[r * SA + lane * 6 + c] + src[g * DMODEL + lane * 6 + c];
        float s = 0.f;
#pragma unroll
        for (int c = 0; c < 6; c++) s += v[c];
#pragma unroll
        for (int o = 16; o; o >>= 1) s += __shfl_xor_sync(0xffffffffu, s, o);
        float mean = s * (1.0f / 192.0f);
        float vs = 0.f;
#pragma unroll
        for (int c = 0; c < 6; c++) { float d0 = v[c] - mean; vs += d0 * d0; }
#pragma unroll
        for (int o = 16; o; o >>= 1) vs += __shfl_xor_sync(0xffffffffu, vs, o);
        float inv = rsqrtf(vs * (1.0f / 192.0f) + LN_EPS);
#pragma unroll
        for (int c = 0; c < 6; c++) {
            int d = lane * 6 + c;
            g_X1[g * DMODEL + d] = (v[c] - mean) * inv * ln1g[d] + ln1b[d];
        }
    }
}

// ============================================================================
// Kernel 5: FFN + residual + LN2 — fp16x1 mma.sync, 256 threads / 64 rows
// smem: Xh@0 [64][200] fp16 | WU@25600 51200 (W1 [64][200] / W2 [192][72] / Ys f32)
//       Hh@76800 [64][72] fp16 -> total 86016
// ============================================================================
#define SH 72
__global__ __launch_bounds__(256) void ffn_mma_kernel(
    const float* __restrict__ b1, const float* __restrict__ b2,
    const float* __restrict__ ln2g, const float* __restrict__ ln2b,
    float* __restrict__ out)
{
    extern __shared__ char smc[];
    __half* Xh = (__half*)smc;
    char* WU = smc + 25600;
    __half* W1s = (__half*)WU;           // [64][200]
    __half* W2s = (__half*)WU;           // [192][72]
    float* Ys = (float*)WU;              // [64][200] f32
    __half* Hh = (__half*)(smc + 76800);
    const int t = threadIdx.x, w = t >> 5, lane = t & 31;
    const int r0g = blockIdx.x * 64;
    const int lr = lane >> 2, lk = (lane & 3) * 2;
    const int r0 = (w & 3) * 16;
    const int c0h = (w >> 2) * 32;
    const int c0y = (w >> 2) * 96;

    for (int i = t; i < 64 * DMODEL; i += 256) {
        int r = i / DMODEL, c = i % DMODEL;
        Xh[r * SA + c] = __float2half(g_X1[(r0g + r) * DMODEL + c]);
    }

    float y[12][4];
#pragma unroll
    for (int n = 0; n < 12; n++)
#pragma unroll
        for (int q = 0; q < 4; q++) y[n][q] = 0.f;

#pragma unroll 1
    for (int fc = 0; fc < DFFN; fc += 64) {
        __syncthreads();
        for (int i = t; i < 64 * 96; i += 256) {
            int f = i / 96, kp = i % 96;
            *(uint32_t*)&W1s[f * SA + kp * 2] = ((const uint32_t*)g_W116)[(fc + f) * 96 + kp];
        }
        __syncthreads();
        // ---- phase 1: H = relu(X @ W1c^T + b1) ----
        float hacc[4][4];
#pragma unroll
        for (int n = 0; n < 4; n++)
#pragma unroll
            for (int q = 0; q < 4; q++) hacc[n][q] = 0.f;
#pragma unroll
        for (int kk = 0; kk < 12; kk++) {
            int kb = kk * 16;
            uint32_t a0 = ld_u32h(&Xh[(r0 + lr) * SA + kb + lk]);
            uint32_t a1 = ld_u32h(&Xh[(r0 + lr + 8) * SA + kb + lk]);
            uint32_t a2 = ld_u32h(&Xh[(r0 + lr) * SA + kb + lk + 8]);
            uint32_t a3 = ld_u32h(&Xh[(r0 + lr + 8) * SA + kb + lk + 8]);
#pragma unroll
            for (int nt = 0; nt < 4; nt++) {
                uint32_t b0 = ld_u32h(&W1s[(c0h + nt * 8 + lr) * SA + kb + lk]);
                uint32_t b1r = ld_u32h(&W1s[(c0h + nt * 8 + lr) * SA + kb + lk + 8]);
                mma16816h(hacc[nt], a0, a1, a2, a3, b0, b1r);
            }
        }
#pragma unroll
        for (int nt = 0; nt < 4; nt++) {
            int col = c0h + nt * 8 + lk;
            int fg = fc + col;
            float bv0 = b1[fg], bv1 = b1[fg + 1];
            __half h00 = __float2half(fmaxf(hacc[nt][0] + bv0, 0.f));
            __half h01 = __float2half(fmaxf(hacc[nt][1] + bv1, 0.f));
            __half h10 = __float2half(fmaxf(hacc[nt][2] + bv0, 0.f));
            __half h11 = __float2half(fmaxf(hacc[nt][3] + bv1, 0.f));
            Hh[(r0 + lr) * SH + col] = h00;
            Hh[(r0 + lr) * SH + col + 1] = h01;
            Hh[(r0 + lr + 8) * SH + col] = h10;
            Hh[(r0 + lr + 8) * SH + col + 1] = h11;
        }
        __syncthreads();
        // stage W2 chunk [d][f] -> [192][72]
        for (int i = t; i < DMODEL * 32; i += 256) {
            int d = i / 32, kp = i % 32;
            *(uint32_t*)&W2s[d * SH + kp * 2] = ((const uint32_t*)g_W216)[d * (DFFN / 2) + (fc >> 1) + kp];
        }
        __syncthreads();
        // ---- phase 2: Y += H @ W2c^T ----
#pragma unroll
        for (int kk = 0; kk < 4; kk++) {
            int kb = kk * 16;
            uint32_t a0 = ld_u32h(&Hh[(r0 + lr) * SH + kb + lk]);
            uint32_t a1 = ld_u32h(&Hh[(r0 + lr + 8) * SH + kb + lk]);
            uint32_t a2 = ld_u32h(&Hh[(r0 + lr) * SH + kb + lk + 8]);
            uint32_t a3 = ld_u32h(&Hh[(r0 + lr + 8) * SH + kb + lk + 8]);
#pragma unroll
            for (int nt = 0; nt < 12; nt++) {
                uint32_t b0 = ld_u32h(&W2s[(c0y + nt * 8 + lr) * SH + kb + lk]);
                uint32_t b1r = ld_u32h(&W2s[(c0y + nt * 8 + lr) * SH + kb + lk + 8]);
                mma16816h(y[nt], a0, a1, a2, a3, b0, b1r);
            }
        }
    }
    __syncthreads();
#pragma unroll
    for (int nt = 0; nt < 12; nt++) {
        int col = c0y + nt * 8 + lk;
        int row = r0 + lr;
        Ys[row * SA + col]           = y[nt][0];
        Ys[row * SA + col + 1]       = y[nt][1];
        Ys[(row + 8) * SA + col]     = y[nt][2];
        Ys[(row + 8) * SA + col + 1] = y[nt][3];
    }
    __syncthreads();
    for (int rr = 0; rr < 8; rr++) {
        int r = w * 8 + rr;
        float v[6];
#pragma unroll
        for (int c = 0; c < 6; c++) {
            int d = lane * 6 + c;
            v[c] = Ys[r * SA + d] + b2[d] + g_X1[(r0g + r) * DMODEL + d];
        }
        float s = 0.f;
#pragma unroll
        for (int c = 0; c < 6; c++) s += v[c];
#pragma unroll
        for (int o = 16; o; o >>= 1) s += __shfl_xor_sync(0xffffffffu, s, o);
        float mean = s * (1.0f / 192.0f);
        float vs = 0.f;
#pragma unroll
        for (int c = 0; c < 6; c++) { float d0 = v[c] - mean; vs += d0 * d0; }
#pragma unroll
        for (int o = 16; o; o >>= 1) vs += __shfl_xor_sync(0xffffffffu, vs, o);
        float inv = rsqrtf(vs * (1.0f / 192.0f) + LN_EPS);
#pragma unroll
        for (int c = 0; c < 6; c++) {
            int d = lane * 6 + c;
            out[(r0g + r) * DMODEL + d] = (v[c] - mean) * inv * ln2g[d] + ln2b[d];
        }
    }
}

// ============================================================================
extern "C" void kernel_launch(void* const* d_in, const int* in_sizes, int n_in,
                              void* d_out, int out_size)
{
    const float* src  = (const float*)d_in[0];
    const int*   vcrd = (const int*)d_in[1];
    const float* boxf = (const float*)d_in[2];
    const int*   bcrd = (const int*)d_in[3];
    const float* pos  = (const float*)d_in[4];
    const float* boxp = (const float*)d_in[5];
    const int*   vind = (const int*)d_in[6];
    const float* Wq = (const float*)d_in[7];
    const float* bq = (const float*)d_in[8];
    const float* Wk = (const float*)d_in[9];
    const float* bk = (const float*)d_in[10];
    const float* Wv = (const float*)d_in[11];
    const float* bv = (const float*)d_in[12];
    const float* Wo = (const float*)d_in[13];
    const float* bo = (const float*)d_in[14];
    const float* W1 = (const float*)d_in[15];
    const float* b1 = (const float*)d_in[16];
    const float* W2 = (const float*)d_in[17];
    const float* b2 = (const float*)d_in[18];
    const float* g1 = (const float*)d_in[19];
    const float* lb1 = (const float*)d_in[20];
    const float* g2 = (const float*)d_in[21];
    const float* lb2 = (const float*)d_in[22];
    float* out = (float*)d_out;

    const int SMEM_PROJ = 102656;
    const int SMEM_ATTN = 86656;
    const int SMEM_FFN  = 86016;

    cudaFuncSetAttribute(qproj_mma_kernel, cudaFuncAttributeMaxDynamicSharedMemorySize, SMEM_PROJ);
    cudaFuncSetAttribute(oproj_mma_kernel, cudaFuncAttributeMaxDynamicSharedMemorySize, SMEM_PROJ);
    cudaFuncSetAttribute(attn_mma_kernel, cudaFuncAttributeMaxDynamicSharedMemorySize, SMEM_ATTN);
    cudaFuncSetAttribute(ffn_mma_kernel, cudaFuncAttributeMaxDynamicSharedMemorySize, SMEM_FFN);

    split_weights_kernel<<<3360, 256>>>(Wq, Wo, W1, W2);
    kv_kernel<<<MTOK / 64, 256>>>(boxf, boxp, Wk, bk, Wv, bv);
    qproj_mma_kernel<<<NTOT / 64, 256, SMEM_PROJ>>>(src, pos, vind, bq);
    attn_mma_kernel<<<dim3(NTOT / 32, NHEAD), 256, SMEM_ATTN>>>(vind, vcrd, bcrd);
    oproj_mma_kernel<<<NTOT / 64, 256, SMEM_PROJ>>>(src, vind, bo, g1, lb1);
    ffn_mma_kernel<<<NTOT / 64, 256, SMEM_FFN>>>(b1, b2, g2, lb2, out);
}

// round 12
// speedup vs baseline: 2.5061x; 1.1384x over previous
#include <cuda_runtime.h>
#include <cuda_fp16.h>
#include <math.h>
#include <stdint.h>

#define NTOT 46080
#define DMODEL 192
#define MTOK 256
#define BDIM 256
#define NHEAD 8
#define DHEAD 24
#define DFFN 2048
#define LN_EPS 1e-5f

__device__ float g_K[MTOK * DMODEL];
__device__ float g_V[MTOK * DMODEL];
__device__ float g_Q[NTOT * DMODEL];
__device__ float g_CTX[NTOT * DMODEL];
__device__ float g_X1[NTOT * DMODEL];

__device__ __half g_Wq16[DMODEL * DMODEL];
__device__ __half g_Wo16[DMODEL * DMODEL];
__device__ __half g_W116[DFFN * DMODEL];
__device__ __half g_W216[DMODEL * DFFN];

__device__ __forceinline__ float nan_to_num_f(float x) {
    if (isnan(x)) return 0.0f;
    if (isinf(x)) return x > 0.0f ? 3.402823466e38f : -3.402823466e38f;
    return x;
}

__device__ __forceinline__ void mma16816h(float* d,
    uint32_t a0, uint32_t a1, uint32_t a2, uint32_t a3,
    uint32_t b0, uint32_t b1)
{
    asm volatile(
        "mma.sync.aligned.m16n8k16.row.col.f32.f16.f16.f32 "
        "{%0,%1,%2,%3}, {%4,%5,%6,%7}, {%8,%9}, {%0,%1,%2,%3};\n"
        : "+f"(d[0]), "+f"(d[1]), "+f"(d[2]), "+f"(d[3])
        : "r"(a0), "r"(a1), "r"(a2), "r"(a3), "r"(b0), "r"(b1));
}

__device__ __forceinline__ uint32_t ld_u32h(const __half* p) {
    return *(const uint32_t*)p;
}
__device__ __forceinline__ uint32_t pack_h2f(float lo, float hi) {
    uint32_t a = (uint32_t)__half_as_ushort(__float2half(lo));
    uint32_t b = (uint32_t)__half_as_ushort(__float2half(hi));
    return a | (b << 16);
}

// ============================================================================
// Kernel 0: convert fp32 weights to fp16
// ============================================================================
__global__ __launch_bounds__(256) void split_weights_kernel(
    const float* __restrict__ Wq, const float* __restrict__ Wo,
    const float* __restrict__ W1, const float* __restrict__ W2)
{
    const int NQ = DMODEL * DMODEL;
    const int N1 = DFFN * DMODEL;
    int i = blockIdx.x * 256 + threadIdx.x;
    if (i < NQ)               g_Wq16[i] = __float2half(Wq[i]);
    else if (i < 2*NQ)        g_Wo16[i - NQ] = __float2half(Wo[i - NQ]);
    else if (i < 2*NQ + N1)   g_W116[i - 2*NQ] = __float2half(W1[i - 2*NQ]);
    else if (i < 2*NQ + 2*N1) g_W216[i - 2*NQ - N1] = __float2half(W2[i - 2*NQ - N1]);
}

// ============================================================================
// Kernel 1: K/V projections (fp32 SIMT, unchanged)
// ============================================================================
__global__ __launch_bounds__(256) void kv_kernel(
    const float* __restrict__ boxf, const float* __restrict__ boxp,
    const float* __restrict__ Wk, const float* __restrict__ bk,
    const float* __restrict__ Wv, const float* __restrict__ bv)
{
    __shared__ float Asf[64 * 17];
    __shared__ float Asp[64 * 17];
    __shared__ float Bsk[16 * 193];
    __shared__ float Bsv[16 * 193];
    const int t = threadIdx.x;
    const int m0 = blockIdx.x * 64;
    const int tx = t & 15, ty = t >> 4;

    float ak[4][12], av[4][12];
#pragma unroll
    for (int i = 0; i < 4; i++)
#pragma unroll
        for (int j = 0; j < 12; j++) { ak[i][j] = 0.f; av[i][j] = 0.f; }

    for (int kt = 0; kt < BDIM; kt += 16) {
        __syncthreads();
        for (int i = t; i < 64 * 16; i += 256) {
            int r = i >> 4, k = i & 15;
            Asf[r * 17 + k] = boxf[(m0 + r) * BDIM + kt + k];
            Asp[r * 17 + k] = boxp[(m0 + r) * BDIM + kt + k];
        }
        for (int i = t; i < 16 * DMODEL; i += 256) {
            int d = i >> 4, k = i & 15;
            Bsk[k * 193 + d] = Wk[d * BDIM + kt + k];
            Bsv[k * 193 + d] = Wv[d * BDIM + kt + k];
        }
        __syncthreads();
#pragma unroll
        for (int k = 0; k < 16; k++) {
            float af[4], aa[4], wkr[12], wvr[12];
#pragma unroll
            for (int i = 0; i < 4; i++) {
                af[i] = Asf[(ty * 4 + i) * 17 + k];
                aa[i] = af[i] + Asp[(ty * 4 + i) * 17 + k];
            }
#pragma unroll
            for (int j = 0; j < 12; j++) {
                wkr[j] = Bsk[k * 193 + tx * 12 + j];
                wvr[j] = Bsv[k * 193 + tx * 12 + j];
            }
#pragma unroll
            for (int i = 0; i < 4; i++)
#pragma unroll
                for (int j = 0; j < 12; j++) {
                    ak[i][j] = fmaf(aa[i], wkr[j], ak[i][j]);
                    av[i][j] = fmaf(af[i], wvr[j], av[i][j]);
                }
        }
    }
#pragma unroll
    for (int i = 0; i < 4; i++) {
        int m = m0 + ty * 4 + i;
#pragma unroll
        for (int j = 0; j < 12; j++) {
            int d = tx * 12 + j;
            g_K[m * DMODEL + d] = ak[i][j] + bk[d];
            g_V[m * DMODEL + d] = av[i][j] + bv[d];
        }
    }
}

// ============================================================================
// Kernel 2: Q-proj — fp16x1 mma.sync, 64 rows (unchanged from R11 pass)
// ============================================================================
#define SA 200
__global__ __launch_bounds__(256) void qproj_mma_kernel(
    const float* __restrict__ src, const float* __restrict__ pos,
    const int* __restrict__ vinds, const float* __restrict__ bq)
{
    extern __shared__ char smc[];
    __half* Ah = (__half*)smc;
    __half* Bs = (__half*)(smc + 25600);
    int* gI = (int*)(smc + 102400);
    const int t = threadIdx.x;
    const int r0g = blockIdx.x * 64;
    if (t < 64) gI[t] = vinds[r0g + t];
    __syncthreads();
    for (int i = t; i < 64 * DMODEL; i += 256) {
        int r = i / DMODEL, c = i % DMODEL;
        int g = gI[r];
        Ah[r * SA + c] = __float2half(src[g * DMODEL + c] + pos[g * DMODEL + c]);
    }
    for (int i = t; i < DMODEL * 96; i += 256) {
        int d = i / 96, kp = i % 96;
        *(uint32_t*)&Bs[d * SA + kp * 2] = ((const uint32_t*)g_Wq16)[d * 96 + kp];
    }
    __syncthreads();

    const int w = t >> 5, lane = t & 31;
    const int r0 = (w & 3) * 16, c0 = (w >> 2) * 96;
    const int lr = lane >> 2, lk = (lane & 3) * 2;
    float acc[12][4];
#pragma unroll
    for (int n = 0; n < 12; n++)
#pragma unroll
        for (int q = 0; q < 4; q++) acc[n][q] = 0.f;

#pragma unroll
    for (int kk = 0; kk < 12; kk++) {
        int kb = kk * 16;
        uint32_t a0 = ld_u32h(&Ah[(r0 + lr) * SA + kb + lk]);
        uint32_t a1 = ld_u32h(&Ah[(r0 + lr + 8) * SA + kb + lk]);
        uint32_t a2 = ld_u32h(&Ah[(r0 + lr) * SA + kb + lk + 8]);
        uint32_t a3 = ld_u32h(&Ah[(r0 + lr + 8) * SA + kb + lk + 8]);
#pragma unroll
        for (int nt = 0; nt < 12; nt++) {
            uint32_t b0 = ld_u32h(&Bs[(c0 + nt * 8 + lr) * SA + kb + lk]);
            uint32_t b1 = ld_u32h(&Bs[(c0 + nt * 8 + lr) * SA + kb + lk + 8]);
            mma16816h(acc[nt], a0, a1, a2, a3, b0, b1);
        }
    }
#pragma unroll
    for (int nt = 0; nt < 12; nt++) {
        int col = c0 + nt * 8 + lk;
        int row = r0g + r0 + lr;
        float2 v0 = make_float2(acc[nt][0] + bq[col], acc[nt][1] + bq[col + 1]);
        float2 v1 = make_float2(acc[nt][2] + bq[col], acc[nt][3] + bq[col + 1]);
        *(float2*)&g_Q[row * DMODEL + col] = v0;
        *(float2*)&g_Q[(row + 8) * DMODEL + col] = v1;
    }
}

// ============================================================================
// Kernel 3: attention — fp16 mma, REGISTER-RESIDENT softmax (no Ss buffer)
// grid (1440, 8) x 256. smem (bytes):
//   Qs fp16 [32][40]  @0      (2560)
//   Ks fp16 [256][40] @2560   (20480)
//   Vt fp16 [24][264] @23040  (12672)
//   Pt fp16 [32][264] @35712  (16896)
//   redmax f32 [32][4] @52608 (512)
//   redsum f32 [32][4] @53120 (512)
//   qb int[32] @53632, bb int[256] @53760 -> total 54784 (4 blocks/SM)
// ============================================================================
__global__ __launch_bounds__(256) void attn_mma_kernel(
    const int* __restrict__ vinds, const int* __restrict__ vcrd,
    const int* __restrict__ bcrd)
{
    extern __shared__ char smc[];
    __half* Qs = (__half*)smc;
    __half* Ks = (__half*)(smc + 2560);
    __half* Vt = (__half*)(smc + 23040);
    __half* Pt = (__half*)(smc + 35712);
    float* redmax = (float*)(smc + 52608);
    float* redsum = (float*)(smc + 53120);
    int* qb = (int*)(smc + 53632);
    int* bb = (int*)(smc + 53760);

    const int t = threadIdx.x;
    const int q0 = blockIdx.x * 32;
    const int h = blockIdx.y;

    if (t < 32) { int g = vinds[q0 + t]; qb[t] = vcrd[g * 4]; }
    bb[t] = bcrd[t * 4];
    for (int i = t; i < 32 * 32; i += 256) {
        int r = i >> 5, d = i & 31;
        Qs[r * 40 + d] = (d < DHEAD) ? __float2half(g_Q[(q0 + r) * DMODEL + h * DHEAD + d])
                                     : __ushort_as_half(0);
    }
    for (int i = t; i < MTOK * 32; i += 256) {
        int m = i >> 5, d = i & 31;
        Ks[m * 40 + d] = (d < DHEAD) ? __float2half(g_K[m * DMODEL + h * DHEAD + d])
                                     : __ushort_as_half(0);
    }
    for (int i = t; i < DHEAD * MTOK; i += 256) {
        int d = i >> 8, m = i & 255;
        Vt[d * 264 + m] = __float2half(g_V[m * DMODEL + h * DHEAD + d]);
    }
    __syncthreads();

    const int w = t >> 5, lane = t & 31;
    const int lr = lane >> 2, lk = (lane & 3) * 2;
    const float NEG_INF = -__int_as_float(0x7f800000);

    // ---- phase B: S = Q @ K^T ; warp: rows mt..mt+15(+8), cols c0..c0+63 ----
    const int mt = (w & 1) * 16, c0 = (w >> 1) * 64, cg = w >> 1;
    float acc[8][4];
#pragma unroll
    for (int n = 0; n < 8; n++)
#pragma unroll
        for (int q = 0; q < 4; q++) acc[n][q] = 0.f;
#pragma unroll
    for (int ks = 0; ks < 2; ks++) {
        int kb = ks * 16;
        uint32_t a0 = ld_u32h(&Qs[(mt + lr) * 40 + kb + lk]);
        uint32_t a1 = ld_u32h(&Qs[(mt + lr + 8) * 40 + kb + lk]);
        uint32_t a2 = ld_u32h(&Qs[(mt + lr) * 40 + kb + lk + 8]);
        uint32_t a3 = ld_u32h(&Qs[(mt + lr + 8) * 40 + kb + lk + 8]);
#pragma unroll
        for (int nt = 0; nt < 8; nt++) {
            uint32_t b0 = ld_u32h(&Ks[(c0 + nt * 8 + lr) * 40 + kb + lk]);
            uint32_t b1 = ld_u32h(&Ks[(c0 + nt * 8 + lr) * 40 + kb + lk + 8]);
            mma16816h(acc[nt], a0, a1, a2, a3, b0, b1);
        }
    }
    // scale + mask in registers
    {
        const float scale = 0.20412414523193154f;
        int qv0 = qb[mt + lr], qv1 = qb[mt + lr + 8];
#pragma unroll
        for (int nt = 0; nt < 8; nt++) {
            int col = c0 + nt * 8 + lk;
            int b0v = bb[col], b1v = bb[col + 1];
            acc[nt][0] = (qv0 == b0v) ? acc[nt][0] * scale : NEG_INF;
            acc[nt][1] = (qv0 == b1v) ? acc[nt][1] * scale : NEG_INF;
            acc[nt][2] = (qv1 == b0v) ? acc[nt][2] * scale : NEG_INF;
            acc[nt][3] = (qv1 == b1v) ? acc[nt][3] * scale : NEG_INF;
        }
    }
    // row max: local over nt, then shfl over lane&3 group, then cross-warp smem
    float mx0 = NEG_INF, mx1 = NEG_INF;
#pragma unroll
    for (int nt = 0; nt < 8; nt++) {
        mx0 = fmaxf(mx0, fmaxf(acc[nt][0], acc[nt][1]));
        mx1 = fmaxf(mx1, fmaxf(acc[nt][2], acc[nt][3]));
    }
    mx0 = fmaxf(mx0, __shfl_xor_sync(0xffffffffu, mx0, 1));
    mx0 = fmaxf(mx0, __shfl_xor_sync(0xffffffffu, mx0, 2));
    mx1 = fmaxf(mx1, __shfl_xor_sync(0xffffffffu, mx1, 1));
    mx1 = fmaxf(mx1, __shfl_xor_sync(0xffffffffu, mx1, 2));
    if ((lane & 3) == 0) {
        redmax[(mt + lr) * 4 + cg] = mx0;
        redmax[(mt + lr + 8) * 4 + cg] = mx1;
    }
    __syncthreads();
    float gmx0 = fmaxf(fmaxf(redmax[(mt + lr) * 4 + 0], redmax[(mt + lr) * 4 + 1]),
                       fmaxf(redmax[(mt + lr) * 4 + 2], redmax[(mt + lr) * 4 + 3]));
    float gmx1 = fmaxf(fmaxf(redmax[(mt + lr + 8) * 4 + 0], redmax[(mt + lr + 8) * 4 + 1]),
                       fmaxf(redmax[(mt + lr + 8) * 4 + 2], redmax[(mt + lr + 8) * 4 + 3]));
    // exp + row sum
    float s0 = 0.f, s1 = 0.f;
#pragma unroll
    for (int nt = 0; nt < 8; nt++) {
        acc[nt][0] = __expf(acc[nt][0] - gmx0);
        acc[nt][1] = __expf(acc[nt][1] - gmx0);
        acc[nt][2] = __expf(acc[nt][2] - gmx1);
        acc[nt][3] = __expf(acc[nt][3] - gmx1);
        s0 += acc[nt][0] + acc[nt][1];
        s1 += acc[nt][2] + acc[nt][3];
    }
    s0 += __shfl_xor_sync(0xffffffffu, s0, 1);
    s0 += __shfl_xor_sync(0xffffffffu, s0, 2);
    s1 += __shfl_xor_sync(0xffffffffu, s1, 1);
    s1 += __shfl_xor_sync(0xffffffffu, s1, 2);
    if ((lane & 3) == 0) {
        redsum[(mt + lr) * 4 + cg] = s0;
        redsum[(mt + lr + 8) * 4 + cg] = s1;
    }
    __syncthreads();
    float gs0 = redsum[(mt + lr) * 4 + 0] + redsum[(mt + lr) * 4 + 1]
              + redsum[(mt + lr) * 4 + 2] + redsum[(mt + lr) * 4 + 3];
    float gs1 = redsum[(mt + lr + 8) * 4 + 0] + redsum[(mt + lr + 8) * 4 + 1]
              + redsum[(mt + lr + 8) * 4 + 2] + redsum[(mt + lr + 8) * 4 + 3];
    float inv0 = 1.0f / gs0;   // all-masked -> NaN propagates (matches jax)
    float inv1 = 1.0f / gs1;
#pragma unroll
    for (int nt = 0; nt < 8; nt++) {
        int col = c0 + nt * 8 + lk;
        *(uint32_t*)&Pt[(mt + lr) * 264 + col] = pack_h2f(acc[nt][0] * inv0, acc[nt][1] * inv0);
        *(uint32_t*)&Pt[(mt + lr + 8) * 264 + col] = pack_h2f(acc[nt][2] * inv1, acc[nt][3] * inv1);
    }
    __syncthreads();

    // ---- phase D: ctx = P @ V (warps 0-5, 4-way split accumulator chains) ----
    if (w < 6) {
        const int mt2 = (w & 1) * 16, n0 = (w >> 1) * 8;
        float c[4][4];
#pragma unroll
        for (int j = 0; j < 4; j++)
#pragma unroll
            for (int q = 0; q < 4; q++) c[j][q] = 0.f;
#pragma unroll
        for (int ks = 0; ks < 16; ks++) {
            int kb = ks * 16;
            uint32_t a0 = ld_u32h(&Pt[(mt2 + lr) * 264 + kb + lk]);
            uint32_t a1 = ld_u32h(&Pt[(mt2 + lr + 8) * 264 + kb + lk]);
            uint32_t a2 = ld_u32h(&Pt[(mt2 + lr) * 264 + kb + lk + 8]);
            uint32_t a3 = ld_u32h(&Pt[(mt2 + lr + 8) * 264 + kb + lk + 8]);
            uint32_t b0 = ld_u32h(&Vt[(n0 + lr) * 264 + kb + lk]);
            uint32_t b1 = ld_u32h(&Vt[(n0 + lr) * 264 + kb + lk + 8]);
            mma16816h(c[ks & 3], a0, a1, a2, a3, b0, b1);
        }
        float r0v = c[0][0] + c[1][0] + c[2][0] + c[3][0];
        float r1v = c[0][1] + c[1][1] + c[2][1] + c[3][1];
        float r2v = c[0][2] + c[1][2] + c[2][2] + c[3][2];
        float r3v = c[0][3] + c[1][3] + c[2][3] + c[3][3];
        int row = q0 + mt2 + lr;
        int col = h * DHEAD + n0 + lk;
        g_CTX[row * DMODEL + col] = r0v;
        g_CTX[row * DMODEL + col + 1] = r1v;
        g_CTX[(row + 8) * DMODEL + col] = r2v;
        g_CTX[(row + 8) * DMODEL + col + 1] = r3v;
    }
}

// ============================================================================
// Kernel 4: O-proj + residual + LN1 — fp16x1 mma.sync (unchanged from R11)
// ============================================================================
__global__ __launch_bounds__(256) void oproj_mma_kernel(
    const float* __restrict__ src, const int* __restrict__ vinds,
    const float* __restrict__ bo,
    const float* __restrict__ ln1g, const float* __restrict__ ln1b)
{
    extern __shared__ char smc[];
    __half* Ah = (__half*)smc;
    __half* Bs = (__half*)(smc + 25600);
    int* gI = (int*)(smc + 102400);
    float* Ys = (float*)(smc + 25600);
    const int t = threadIdx.x;
    const int r0g = blockIdx.x * 64;
    if (t < 64) gI[t] = vinds[r0g + t];
    for (int i = t; i < 64 * DMODEL; i += 256) {
        int r = i / DMODEL, c = i % DMODEL;
        Ah[r * SA + c] = __float2half(g_CTX[(r0g + r) * DMODEL + c]);
    }
    for (int i = t; i < DMODEL * 96; i += 256) {
        int d = i / 96, kp = i % 96;
        *(uint32_t*)&Bs[d * SA + kp * 2] = ((const uint32_t*)g_Wo16)[d * 96 + kp];
    }
    __syncthreads();

    const int w = t >> 5, lane = t & 31;
    const int r0 = (w & 3) * 16, c0 = (w >> 2) * 96;
    const int lr = lane >> 2, lk = (lane & 3) * 2;
    float acc[12][4];
#pragma unroll
    for (int n = 0; n < 12; n++)
#pragma unroll
        for (int q = 0; q < 4; q++) acc[n][q] = 0.f;

#pragma unroll
    for (int kk = 0; kk < 12; kk++) {
        int kb = kk * 16;
        uint32_t a0 = ld_u32h(&Ah[(r0 + lr) * SA + kb + lk]);
        uint32_t a1 = ld_u32h(&Ah[(r0 + lr + 8) * SA + kb + lk]);
        uint32_t a2 = ld_u32h(&Ah[(r0 + lr) * SA + kb + lk + 8]);
        uint32_t a3 = ld_u32h(&Ah[(r0 + lr + 8) * SA + kb + lk + 8]);
#pragma unroll
        for (int nt = 0; nt < 12; nt++) {
            uint32_t b0 = ld_u32h(&Bs[(c0 + nt * 8 + lr) * SA + kb + lk]);
            uint32_t b1 = ld_u32h(&Bs[(c0 + nt * 8 + lr) * SA + kb + lk + 8]);
            mma16816h(acc[nt], a0, a1, a2, a3, b0, b1);
        }
    }
    __syncthreads();
#pragma unroll
    for (int nt = 0; nt < 12; nt++) {
        int col = c0 + nt * 8 + lk;
        int row = r0 + lr;
        Ys[row * SA + col]           = nan_to_num_f(acc[nt][0] + bo[col]);
        Ys[row * SA + col + 1]       = nan_to_num_f(acc[nt][1] + bo[col + 1]);
        Ys[(row + 8) * SA + col]     = nan_to_num_f(acc[nt][2] + bo[col]);
        Ys[(row + 8) * SA + col + 1] = nan_to_num_f(acc[nt][3] + bo[col + 1]);
    }
    __syncthreads();
    for (int rr = 0; rr < 8; rr++) {
        int r = w * 8 + rr;
        int g = gI[r];
        float v[6];
#pragma unroll
        for (int c = 0; c < 6; c++)
            v[c] = Ys[r * SA + lane * 6 + c] + src[g * DMODEL + lane * 6 + c];
        float s = 0.f;
#pragma unroll
        for (int c = 0; c < 6; c++) s += v[c];
#pragma unroll
        for (int o = 16; o; o >>= 1) s += __shfl_xor_sync(0xffffffffu, s, o);
        float mean = s * (1.0f / 192.0f);
        float vs = 0.f;
#pragma unroll
        for (int c = 0; c < 6; c++) { float d0 = v[c] - mean; vs += d0 * d0; }
#pragma unroll
        for (int o = 16; o; o >>= 1) vs += __shfl_xor_sync(0xffffffffu, vs, o);
        float inv = rsqrtf(vs * (1.0f / 192.0f) + LN_EPS);
#pragma unroll
        for (int c = 0; c < 6; c++) {
            int d = lane * 6 + c;
            g_X1[g * DMODEL + d] = (v[c] - mean) * inv * ln1g[d] + ln1b[d];
        }
    }
}

// ============================================================================
// Kernel 5: FFN + residual + LN2 — fp16x1 mma.sync (unchanged from R11)
// ============================================================================
#define SH 72
__global__ __launch_bounds__(256) void ffn_mma_kernel(
    const float* __restrict__ b1, const float* __restrict__ b2,
    const float* __restrict__ ln2g, const float* __restrict__ ln2b,
    float* __restrict__ out)
{
    extern __shared__ char smc[];
    __half* Xh = (__half*)smc;
    char* WU = smc + 25600;
    __half* W1s = (__half*)WU;
    __half* W2s = (__half*)WU;
    float* Ys = (float*)WU;
    __half* Hh = (__half*)(smc + 76800);
    const int t = threadIdx.x, w = t >> 5, lane = t & 31;
    const int r0g = blockIdx.x * 64;
    const int lr = lane >> 2, lk = (lane & 3) * 2;
    const int r0 = (w & 3) * 16;
    const int c0h = (w >> 2) * 32;
    const int c0y = (w >> 2) * 96;

    for (int i = t; i < 64 * DMODEL; i += 256) {
        int r = i / DMODEL, c = i % DMODEL;
        Xh[r * SA + c] = __float2half(g_X1[(r0g + r) * DMODEL + c]);
    }

    float y[12][4];
#pragma unroll
    for (int n = 0; n < 12; n++)
#pragma unroll
        for (int q = 0; q < 4; q++) y[n][q] = 0.f;

#pragma unroll 1
    for (int fc = 0; fc < DFFN; fc += 64) {
        __syncthreads();
        for (int i = t; i < 64 * 96; i += 256) {
            int f = i / 96, kp = i % 96;
            *(uint32_t*)&W1s[f * SA + kp * 2] = ((const uint32_t*)g_W116)[(fc + f) * 96 + kp];
        }
        __syncthreads();
        float hacc[4][4];
#pragma unroll
        for (int n = 0; n < 4; n++)
#pragma unroll
            for (int q = 0; q < 4; q++) hacc[n][q] = 0.f;
#pragma unroll
        for (int kk = 0; kk < 12; kk++) {
            int kb = kk * 16;
            uint32_t a0 = ld_u32h(&Xh[(r0 + lr) * SA + kb + lk]);
            uint32_t a1 = ld_u32h(&Xh[(r0 + lr + 8) * SA + kb + lk]);
            uint32_t a2 = ld_u32h(&Xh[(r0 + lr) * SA + kb + lk + 8]);
            uint32_t a3 = ld_u32h(&Xh[(r0 + lr + 8) * SA + kb + lk + 8]);
#pragma unroll
            for (int nt = 0; nt < 4; nt++) {
                uint32_t b0 = ld_u32h(&W1s[(c0h + nt * 8 + lr) * SA + kb + lk]);
                uint32_t b1r = ld_u32h(&W1s[(c0h + nt * 8 + lr) * SA + kb + lk + 8]);
                mma16816h(hacc[nt], a0, a1, a2, a3, b0, b1r);
            }
        }
#pragma unroll
        for (int nt = 0; nt < 4; nt++) {
            int col = c0h + nt * 8 + lk;
            int fg = fc + col;
            float bv0 = b1[fg], bv1 = b1[fg + 1];
            Hh[(r0 + lr) * SH + col] = __float2half(fmaxf(hacc[nt][0] + bv0, 0.f));
            Hh[(r0 + lr) * SH + col + 1] = __float2half(fmaxf(hacc[nt][1] + bv1, 0.f));
            Hh[(r0 + lr + 8) * SH + col] = __float2half(fmaxf(hacc[nt][2] + bv0, 0.f));
            Hh[(r0 + lr + 8) * SH + col + 1] = __float2half(fmaxf(hacc[nt][3] + bv1, 0.f));
        }
        __syncthreads();
        for (int i = t; i < DMODEL * 32; i += 256) {
            int d = i / 32, kp = i % 32;
            *(uint32_t*)&W2s[d * SH + kp * 2] = ((const uint32_t*)g_W216)[d * (DFFN / 2) + (fc >> 1) + kp];
        }
        __syncthreads();
#pragma unroll
        for (int kk = 0; kk < 4; kk++) {
            int kb = kk * 16;
            uint32_t a0 = ld_u32h(&Hh[(r0 + lr) * SH + kb + lk]);
            uint32_t a1 = ld_u32h(&Hh[(r0 + lr + 8) * SH + kb + lk]);
            uint32_t a2 = ld_u32h(&Hh[(r0 + lr) * SH + kb + lk + 8]);
            uint32_t a3 = ld_u32h(&Hh[(r0 + lr + 8) * SH + kb + lk + 8]);
#pragma unroll
            for (int nt = 0; nt < 12; nt++) {
                uint32_t b0 = ld_u32h(&W2s[(c0y + nt * 8 + lr) * SH + kb + lk]);
                uint32_t b1r = ld_u32h(&W2s[(c0y + nt * 8 + lr) * SH + kb + lk + 8]);
                mma16816h(y[nt], a0, a1, a2, a3, b0, b1r);
            }
        }
    }
    __syncthreads();
#pragma unroll
    for (int nt = 0; nt < 12; nt++) {
        int col = c0y + nt * 8 + lk;
        int row = r0 + lr;
        Ys[row * SA + col]           = y[nt][0];
        Ys[row * SA + col + 1]       = y[nt][1];
        Ys[(row + 8) * SA + col]     = y[nt][2];
        Ys[(row + 8) * SA + col + 1] = y[nt][3];
    }
    __syncthreads();
    for (int rr = 0; rr < 8; rr++) {
        int r = w * 8 + rr;
        float v[6];
#pragma unroll
        for (int c = 0; c < 6; c++) {
            int d = lane * 6 + c;
            v[c] = Ys[r * SA + d] + b2[d] + g_X1[(r0g + r) * DMODEL + d];
        }
        float s = 0.f;
#pragma unroll
        for (int c = 0; c < 6; c++) s += v[c];
#pragma unroll
        for (int o = 16; o; o >>= 1) s += __shfl_xor_sync(0xffffffffu, s, o);
        float mean = s * (1.0f / 192.0f);
        float vs = 0.f;
#pragma unroll
        for (int c = 0; c < 6; c++) { float d0 = v[c] - mean; vs += d0 * d0; }
#pragma unroll
        for (int o = 16; o; o >>= 1) vs += __shfl_xor_sync(0xffffffffu, vs, o);
        float inv = rsqrtf(vs * (1.0f / 192.0f) + LN_EPS);
#pragma unroll
        for (int c = 0; c < 6; c++) {
            int d = lane * 6 + c;
            out[(r0g + r) * DMODEL + d] = (v[c] - mean) * inv * ln2g[d] + ln2b[d];
        }
    }
}

// ============================================================================
extern "C" void kernel_launch(void* const* d_in, const int* in_sizes, int n_in,
                              void* d_out, int out_size)
{
    const float* src  = (const float*)d_in[0];
    const int*   vcrd = (const int*)d_in[1];
    const float* boxf = (const float*)d_in[2];
    const int*   bcrd = (const int*)d_in[3];
    const float* pos  = (const float*)d_in[4];
    const float* boxp = (const float*)d_in[5];
    const int*   vind = (const int*)d_in[6];
    const float* Wq = (const float*)d_in[7];
    const float* bq = (const float*)d_in[8];
    const float* Wk = (const float*)d_in[9];
    const float* bk = (const float*)d_in[10];
    const float* Wv = (const float*)d_in[11];
    const float* bv = (const float*)d_in[12];
    const float* Wo = (const float*)d_in[13];
    const float* bo = (const float*)d_in[14];
    const float* W1 = (const float*)d_in[15];
    const float* b1 = (const float*)d_in[16];
    const float* W2 = (const float*)d_in[17];
    const float* b2 = (const float*)d_in[18];
    const float* g1 = (const float*)d_in[19];
    const float* lb1 = (const float*)d_in[20];
    const float* g2 = (const float*)d_in[21];
    const float* lb2 = (const float*)d_in[22];
    float* out = (float*)d_out;

    const int SMEM_PROJ = 102656;
    const int SMEM_ATTN = 54784;
    const int SMEM_FFN  = 86016;

    cudaFuncSetAttribute(qproj_mma_kernel, cudaFuncAttributeMaxDynamicSharedMemorySize, SMEM_PROJ);
    cudaFuncSetAttribute(oproj_mma_kernel, cudaFuncAttributeMaxDynamicSharedMemorySize, SMEM_PROJ);
    cudaFuncSetAttribute(attn_mma_kernel, cudaFuncAttributeMaxDynamicSharedMemorySize, SMEM_ATTN);
    cudaFuncSetAttribute(ffn_mma_kernel, cudaFuncAttributeMaxDynamicSharedMemorySize, SMEM_FFN);

    split_weights_kernel<<<3360, 256>>>(Wq, Wo, W1, W2);
    kv_kernel<<<MTOK / 64, 256>>>(boxf, boxp, Wk, bk, Wv, bv);
    qproj_mma_kernel<<<NTOT / 64, 256, SMEM_PROJ>>>(src, pos, vind, bq);
    attn_mma_kernel<<<dim3(NTOT / 32, NHEAD), 256, SMEM_ATTN>>>(vind, vcrd, bcrd);
    oproj_mma_kernel<<<NTOT / 64, 256, SMEM_PROJ>>>(src, vind, bo, g1, lb1);
    ffn_mma_kernel<<<NTOT / 64, 256, SMEM_FFN>>>(b1, b2, g2, lb2, out);
}

// round 13
// speedup vs baseline: 2.6666x; 1.0641x over previous
#include <cuda_runtime.h>
#include <cuda_fp16.h>
#include <math.h>
#include <stdint.h>

#define NTOT 46080
#define DMODEL 192
#define MTOK 256
#define BDIM 256
#define NHEAD 8
#define DHEAD 24
#define DFFN 2048
#define LN_EPS 1e-5f

__device__ float g_K[MTOK * DMODEL];
__device__ float g_V[MTOK * DMODEL];
__device__ float g_Q[NTOT * DMODEL];
__device__ float g_CTX[NTOT * DMODEL];
__device__ float g_X1[NTOT * DMODEL];

__device__ __half g_Wq16[DMODEL * DMODEL];
__device__ __half g_Wo16[DMODEL * DMODEL];
__device__ __half g_W116[DFFN * DMODEL];
__device__ __half g_W216[DMODEL * DFFN];

__device__ __forceinline__ float nan_to_num_f(float x) {
    if (isnan(x)) return 0.0f;
    if (isinf(x)) return x > 0.0f ? 3.402823466e38f : -3.402823466e38f;
    return x;
}

__device__ __forceinline__ void mma16816h(float* d,
    uint32_t a0, uint32_t a1, uint32_t a2, uint32_t a3,
    uint32_t b0, uint32_t b1)
{
    asm volatile(
        "mma.sync.aligned.m16n8k16.row.col.f32.f16.f16.f32 "
        "{%0,%1,%2,%3}, {%4,%5,%6,%7}, {%8,%9}, {%0,%1,%2,%3};\n"
        : "+f"(d[0]), "+f"(d[1]), "+f"(d[2]), "+f"(d[3])
        : "r"(a0), "r"(a1), "r"(a2), "r"(a3), "r"(b0), "r"(b1));
}

__device__ __forceinline__ uint32_t ld_u32h(const __half* p) {
    return *(const uint32_t*)p;
}
__device__ __forceinline__ uint32_t pack_h2f(float lo, float hi) {
    uint32_t a = (uint32_t)__half_as_ushort(__float2half(lo));
    uint32_t b = (uint32_t)__half_as_ushort(__float2half(hi));
    return a | (b << 16);
}

// ============================================================================
// Kernel 0: convert fp32 weights to fp16
// ============================================================================
__global__ __launch_bounds__(256) void split_weights_kernel(
    const float* __restrict__ Wq, const float* __restrict__ Wo,
    const float* __restrict__ W1, const float* __restrict__ W2)
{
    const int NQ = DMODEL * DMODEL;
    const int N1 = DFFN * DMODEL;
    int i = blockIdx.x * 256 + threadIdx.x;
    if (i < NQ)               g_Wq16[i] = __float2half(Wq[i]);
    else if (i < 2*NQ)        g_Wo16[i - NQ] = __float2half(Wo[i - NQ]);
    else if (i < 2*NQ + N1)   g_W116[i - 2*NQ] = __float2half(W1[i - 2*NQ]);
    else if (i < 2*NQ + 2*N1) g_W216[i - 2*NQ - N1] = __float2half(W2[i - 2*NQ - N1]);
}

// ============================================================================
// Kernel 1: K/V projections (fp32 SIMT, unchanged)
// ============================================================================
__global__ __launch_bounds__(256) void kv_kernel(
    const float* __restrict__ boxf, const float* __restrict__ boxp,
    const float* __restrict__ Wk, const float* __restrict__ bk,
    const float* __restrict__ Wv, const float* __restrict__ bv)
{
    __shared__ float Asf[64 * 17];
    __shared__ float Asp[64 * 17];
    __shared__ float Bsk[16 * 193];
    __shared__ float Bsv[16 * 193];
    const int t = threadIdx.x;
    const int m0 = blockIdx.x * 64;
    const int tx = t & 15, ty = t >> 4;

    float ak[4][12], av[4][12];
#pragma unroll
    for (int i = 0; i < 4; i++)
#pragma unroll
        for (int j = 0; j < 12; j++) { ak[i][j] = 0.f; av[i][j] = 0.f; }

    for (int kt = 0; kt < BDIM; kt += 16) {
        __syncthreads();
        for (int i = t; i < 64 * 16; i += 256) {
            int r = i >> 4, k = i & 15;
            Asf[r * 17 + k] = boxf[(m0 + r) * BDIM + kt + k];
            Asp[r * 17 + k] = boxp[(m0 + r) * BDIM + kt + k];
        }
        for (int i = t; i < 16 * DMODEL; i += 256) {
            int d = i >> 4, k = i & 15;
            Bsk[k * 193 + d] = Wk[d * BDIM + kt + k];
            Bsv[k * 193 + d] = Wv[d * BDIM + kt + k];
        }
        __syncthreads();
#pragma unroll
        for (int k = 0; k < 16; k++) {
            float af[4], aa[4], wkr[12], wvr[12];
#pragma unroll
            for (int i = 0; i < 4; i++) {
                af[i] = Asf[(ty * 4 + i) * 17 + k];
                aa[i] = af[i] + Asp[(ty * 4 + i) * 17 + k];
            }
#pragma unroll
            for (int j = 0; j < 12; j++) {
                wkr[j] = Bsk[k * 193 + tx * 12 + j];
                wvr[j] = Bsv[k * 193 + tx * 12 + j];
            }
#pragma unroll
            for (int i = 0; i < 4; i++)
#pragma unroll
                for (int j = 0; j < 12; j++) {
                    ak[i][j] = fmaf(aa[i], wkr[j], ak[i][j]);
                    av[i][j] = fmaf(af[i], wvr[j], av[i][j]);
                }
        }
    }
#pragma unroll
    for (int i = 0; i < 4; i++) {
        int m = m0 + ty * 4 + i;
#pragma unroll
        for (int j = 0; j < 12; j++) {
            int d = tx * 12 + j;
            g_K[m * DMODEL + d] = ak[i][j] + bk[d];
            g_V[m * DMODEL + d] = av[i][j] + bv[d];
        }
    }
}

// ============================================================================
// Kernel 2: Q-proj — fp16x1 mma.sync, 64 rows (unchanged from R12 pass)
// ============================================================================
#define SA 200
__global__ __launch_bounds__(256) void qproj_mma_kernel(
    const float* __restrict__ src, const float* __restrict__ pos,
    const int* __restrict__ vinds, const float* __restrict__ bq)
{
    extern __shared__ char smc[];
    __half* Ah = (__half*)smc;
    __half* Bs = (__half*)(smc + 25600);
    int* gI = (int*)(smc + 102400);
    const int t = threadIdx.x;
    const int r0g = blockIdx.x * 64;
    if (t < 64) gI[t] = vinds[r0g + t];
    __syncthreads();
    for (int i = t; i < 64 * DMODEL; i += 256) {
        int r = i / DMODEL, c = i % DMODEL;
        int g = gI[r];
        Ah[r * SA + c] = __float2half(src[g * DMODEL + c] + pos[g * DMODEL + c]);
    }
    for (int i = t; i < DMODEL * 96; i += 256) {
        int d = i / 96, kp = i % 96;
        *(uint32_t*)&Bs[d * SA + kp * 2] = ((const uint32_t*)g_Wq16)[d * 96 + kp];
    }
    __syncthreads();

    const int w = t >> 5, lane = t & 31;
    const int r0 = (w & 3) * 16, c0 = (w >> 2) * 96;
    const int lr = lane >> 2, lk = (lane & 3) * 2;
    float acc[12][4];
#pragma unroll
    for (int n = 0; n < 12; n++)
#pragma unroll
        for (int q = 0; q < 4; q++) acc[n][q] = 0.f;

#pragma unroll
    for (int kk = 0; kk < 12; kk++) {
        int kb = kk * 16;
        uint32_t a0 = ld_u32h(&Ah[(r0 + lr) * SA + kb + lk]);
        uint32_t a1 = ld_u32h(&Ah[(r0 + lr + 8) * SA + kb + lk]);
        uint32_t a2 = ld_u32h(&Ah[(r0 + lr) * SA + kb + lk + 8]);
        uint32_t a3 = ld_u32h(&Ah[(r0 + lr + 8) * SA + kb + lk + 8]);
#pragma unroll
        for (int nt = 0; nt < 12; nt++) {
            uint32_t b0 = ld_u32h(&Bs[(c0 + nt * 8 + lr) * SA + kb + lk]);
            uint32_t b1 = ld_u32h(&Bs[(c0 + nt * 8 + lr) * SA + kb + lk + 8]);
            mma16816h(acc[nt], a0, a1, a2, a3, b0, b1);
        }
    }
#pragma unroll
    for (int nt = 0; nt < 12; nt++) {
        int col = c0 + nt * 8 + lk;
        int row = r0g + r0 + lr;
        float2 v0 = make_float2(acc[nt][0] + bq[col], acc[nt][1] + bq[col + 1]);
        float2 v1 = make_float2(acc[nt][2] + bq[col], acc[nt][3] + bq[col + 1]);
        *(float2*)&g_Q[row * DMODEL + col] = v0;
        *(float2*)&g_Q[(row + 8) * DMODEL + col] = v1;
    }
}

// ============================================================================
// Kernel 3: attention v3 — 64-query blocks, packed staging, reg softmax
// grid (720, 8) x 256. smem (bytes):
//   Qs fp16 [64][40]  @0      (5120)
//   Ks fp16 [256][40] @5120   (20480)
//   Vt fp16 [24][264] @25600  (12672)
//   Pt fp16 [64][264] @38272  (33792)
//   redmax f32 [64][4] @72064 (1024)
//   redsum f32 [64][4] @73088 (1024)
//   qb int[64] @74112, bb int[256] @74368 -> total 75392 (3 blocks/SM)
// ============================================================================
__global__ __launch_bounds__(256) void attn_mma_kernel(
    const int* __restrict__ vinds, const int* __restrict__ vcrd,
    const int* __restrict__ bcrd)
{
    extern __shared__ char smc[];
    __half* Qs = (__half*)smc;
    __half* Ks = (__half*)(smc + 5120);
    __half* Vt = (__half*)(smc + 25600);
    __half* Pt = (__half*)(smc + 38272);
    float* redmax = (float*)(smc + 72064);
    float* redsum = (float*)(smc + 73088);
    int* qb = (int*)(smc + 74112);
    int* bb = (int*)(smc + 74368);

    const int t = threadIdx.x;
    const int q0 = blockIdx.x * 64;
    const int h = blockIdx.y;

    if (t < 64) { int g = vinds[q0 + t]; qb[t] = vcrd[g * 4]; }
    bb[t] = bcrd[t * 4];
    // Q [64][32] packed (pairs 0..11 real, 12..15 zero)
    for (int i = t; i < 64 * 16; i += 256) {
        int r = i >> 4, p = i & 15;
        uint32_t v = 0;
        if (p < 12) {
            float2 x = *(const float2*)&g_Q[(q0 + r) * DMODEL + h * DHEAD + p * 2];
            v = pack_h2f(x.x, x.y);
        }
        *(uint32_t*)&Qs[r * 40 + p * 2] = v;
    }
    // K [256][32] packed
    for (int i = t; i < MTOK * 16; i += 256) {
        int m = i >> 4, p = i & 15;
        uint32_t v = 0;
        if (p < 12) {
            float2 x = *(const float2*)&g_K[m * DMODEL + h * DHEAD + p * 2];
            v = pack_h2f(x.x, x.y);
        }
        *(uint32_t*)&Ks[m * 40 + p * 2] = v;
    }
    // V transposed [24][256], packed over m-pairs
    for (int i = t; i < DHEAD * 128; i += 256) {
        int d = i >> 7, mp = i & 127;
        float v0 = g_V[(2 * mp) * DMODEL + h * DHEAD + d];
        float v1 = g_V[(2 * mp + 1) * DMODEL + h * DHEAD + d];
        *(uint32_t*)&Vt[d * 264 + 2 * mp] = pack_h2f(v0, v1);
    }
    __syncthreads();

    const int w = t >> 5, lane = t & 31;
    const int lr = lane >> 2, lk = (lane & 3) * 2;
    const float NEG_INF = -__int_as_float(0x7f800000);
    const int mg = w & 1, cg = w >> 1, c0 = cg * 64;

#pragma unroll 1
    for (int sub = 0; sub < 2; sub++) {
        const int mt = mg * 16 + sub * 32;
        float acc[8][4];
#pragma unroll
        for (int n = 0; n < 8; n++)
#pragma unroll
            for (int q = 0; q < 4; q++) acc[n][q] = 0.f;
#pragma unroll
        for (int ks = 0; ks < 2; ks++) {
            int kb = ks * 16;
            uint32_t a0 = ld_u32h(&Qs[(mt + lr) * 40 + kb + lk]);
            uint32_t a1 = ld_u32h(&Qs[(mt + lr + 8) * 40 + kb + lk]);
            uint32_t a2 = ld_u32h(&Qs[(mt + lr) * 40 + kb + lk + 8]);
            uint32_t a3 = ld_u32h(&Qs[(mt + lr + 8) * 40 + kb + lk + 8]);
#pragma unroll
            for (int nt = 0; nt < 8; nt++) {
                uint32_t b0 = ld_u32h(&Ks[(c0 + nt * 8 + lr) * 40 + kb + lk]);
                uint32_t b1 = ld_u32h(&Ks[(c0 + nt * 8 + lr) * 40 + kb + lk + 8]);
                mma16816h(acc[nt], a0, a1, a2, a3, b0, b1);
            }
        }
        {
            const float scale = 0.20412414523193154f;
            int qv0 = qb[mt + lr], qv1 = qb[mt + lr + 8];
#pragma unroll
            for (int nt = 0; nt < 8; nt++) {
                int col = c0 + nt * 8 + lk;
                int b0v = bb[col], b1v = bb[col + 1];
                acc[nt][0] = (qv0 == b0v) ? acc[nt][0] * scale : NEG_INF;
                acc[nt][1] = (qv0 == b1v) ? acc[nt][1] * scale : NEG_INF;
                acc[nt][2] = (qv1 == b0v) ? acc[nt][2] * scale : NEG_INF;
                acc[nt][3] = (qv1 == b1v) ? acc[nt][3] * scale : NEG_INF;
            }
        }
        float mx0 = NEG_INF, mx1 = NEG_INF;
#pragma unroll
        for (int nt = 0; nt < 8; nt++) {
            mx0 = fmaxf(mx0, fmaxf(acc[nt][0], acc[nt][1]));
            mx1 = fmaxf(mx1, fmaxf(acc[nt][2], acc[nt][3]));
        }
        mx0 = fmaxf(mx0, __shfl_xor_sync(0xffffffffu, mx0, 1));
        mx0 = fmaxf(mx0, __shfl_xor_sync(0xffffffffu, mx0, 2));
        mx1 = fmaxf(mx1, __shfl_xor_sync(0xffffffffu, mx1, 1));
        mx1 = fmaxf(mx1, __shfl_xor_sync(0xffffffffu, mx1, 2));
        if ((lane & 3) == 0) {
            redmax[(mt + lr) * 4 + cg] = mx0;
            redmax[(mt + lr + 8) * 4 + cg] = mx1;
        }
        __syncthreads();
        float gmx0 = fmaxf(fmaxf(redmax[(mt + lr) * 4 + 0], redmax[(mt + lr) * 4 + 1]),
                           fmaxf(redmax[(mt + lr) * 4 + 2], redmax[(mt + lr) * 4 + 3]));
        float gmx1 = fmaxf(fmaxf(redmax[(mt + lr + 8) * 4 + 0], redmax[(mt + lr + 8) * 4 + 1]),
                           fmaxf(redmax[(mt + lr + 8) * 4 + 2], redmax[(mt + lr + 8) * 4 + 3]));
        float s0 = 0.f, s1 = 0.f;
#pragma unroll
        for (int nt = 0; nt < 8; nt++) {
            acc[nt][0] = __expf(acc[nt][0] - gmx0);
            acc[nt][1] = __expf(acc[nt][1] - gmx0);
            acc[nt][2] = __expf(acc[nt][2] - gmx1);
            acc[nt][3] = __expf(acc[nt][3] - gmx1);
            s0 += acc[nt][0] + acc[nt][1];
            s1 += acc[nt][2] + acc[nt][3];
        }
        s0 += __shfl_xor_sync(0xffffffffu, s0, 1);
        s0 += __shfl_xor_sync(0xffffffffu, s0, 2);
        s1 += __shfl_xor_sync(0xffffffffu, s1, 1);
        s1 += __shfl_xor_sync(0xffffffffu, s1, 2);
        if ((lane & 3) == 0) {
            redsum[(mt + lr) * 4 + cg] = s0;
            redsum[(mt + lr + 8) * 4 + cg] = s1;
        }
        __syncthreads();
        float gs0 = redsum[(mt + lr) * 4 + 0] + redsum[(mt + lr) * 4 + 1]
                  + redsum[(mt + lr) * 4 + 2] + redsum[(mt + lr) * 4 + 3];
        float gs1 = redsum[(mt + lr + 8) * 4 + 0] + redsum[(mt + lr + 8) * 4 + 1]
                  + redsum[(mt + lr + 8) * 4 + 2] + redsum[(mt + lr + 8) * 4 + 3];
        float inv0 = 1.0f / gs0;   // all-masked -> NaN propagates (matches jax)
        float inv1 = 1.0f / gs1;
#pragma unroll
        for (int nt = 0; nt < 8; nt++) {
            int col = c0 + nt * 8 + lk;
            *(uint32_t*)&Pt[(mt + lr) * 264 + col] = pack_h2f(acc[nt][0] * inv0, acc[nt][1] * inv0);
            *(uint32_t*)&Pt[(mt + lr + 8) * 264 + col] = pack_h2f(acc[nt][2] * inv1, acc[nt][3] * inv1);
        }
    }
    __syncthreads();

    // ---- phase D: ctx = P @ V ; 12 tiles (4m x 3n) over 8 warps ----
#pragma unroll 1
    for (int pass = 0; pass < 2; pass++) {
        int tau = (pass == 0) ? w : (w + 8);
        if (tau >= 12) break;
        const int mt2 = (tau & 3) * 16, n0 = (tau >> 2) * 8;
        float c[4][4];
#pragma unroll
        for (int j = 0; j < 4; j++)
#pragma unroll
            for (int q = 0; q < 4; q++) c[j][q] = 0.f;
#pragma unroll
        for (int ks = 0; ks < 16; ks++) {
            int kb = ks * 16;
            uint32_t a0 = ld_u32h(&Pt[(mt2 + lr) * 264 + kb + lk]);
            uint32_t a1 = ld_u32h(&Pt[(mt2 + lr + 8) * 264 + kb + lk]);
            uint32_t a2 = ld_u32h(&Pt[(mt2 + lr) * 264 + kb + lk + 8]);
            uint32_t a3 = ld_u32h(&Pt[(mt2 + lr + 8) * 264 + kb + lk + 8]);
            uint32_t b0 = ld_u32h(&Vt[(n0 + lr) * 264 + kb + lk]);
            uint32_t b1 = ld_u32h(&Vt[(n0 + lr) * 264 + kb + lk + 8]);
            mma16816h(c[ks & 3], a0, a1, a2, a3, b0, b1);
        }
        float r0v = c[0][0] + c[1][0] + c[2][0] + c[3][0];
        float r1v = c[0][1] + c[1][1] + c[2][1] + c[3][1];
        float r2v = c[0][2] + c[1][2] + c[2][2] + c[3][2];
        float r3v = c[0][3] + c[1][3] + c[2][3] + c[3][3];
        int row = q0 + mt2 + lr;
        int col = h * DHEAD + n0 + lk;
        g_CTX[row * DMODEL + col] = r0v;
        g_CTX[row * DMODEL + col + 1] = r1v;
        g_CTX[(row + 8) * DMODEL + col] = r2v;
        g_CTX[(row + 8) * DMODEL + col + 1] = r3v;
    }
}

// ============================================================================
// Kernel 4: O-proj + residual + LN1 — fp16x1 mma.sync (unchanged)
// ============================================================================
__global__ __launch_bounds__(256) void oproj_mma_kernel(
    const float* __restrict__ src, const int* __restrict__ vinds,
    const float* __restrict__ bo,
    const float* __restrict__ ln1g, const float* __restrict__ ln1b)
{
    extern __shared__ char smc[];
    __half* Ah = (__half*)smc;
    __half* Bs = (__half*)(smc + 25600);
    int* gI = (int*)(smc + 102400);
    float* Ys = (float*)(smc + 25600);
    const int t = threadIdx.x;
    const int r0g = blockIdx.x * 64;
    if (t < 64) gI[t] = vinds[r0g + t];
    for (int i = t; i < 64 * DMODEL; i += 256) {
        int r = i / DMODEL, c = i % DMODEL;
        Ah[r * SA + c] = __float2half(g_CTX[(r0g + r) * DMODEL + c]);
    }
    for (int i = t; i < DMODEL * 96; i += 256) {
        int d = i / 96, kp = i % 96;
        *(uint32_t*)&Bs[d * SA + kp * 2] = ((const uint32_t*)g_Wo16)[d * 96 + kp];
    }
    __syncthreads();

    const int w = t >> 5, lane = t & 31;
    const int r0 = (w & 3) * 16, c0 = (w >> 2) * 96;
    const int lr = lane >> 2, lk = (lane & 3) * 2;
    float acc[12][4];
#pragma unroll
    for (int n = 0; n < 12; n++)
#pragma unroll
        for (int q = 0; q < 4; q++) acc[n][q] = 0.f;

#pragma unroll
    for (int kk = 0; kk < 12; kk++) {
        int kb = kk * 16;
        uint32_t a0 = ld_u32h(&Ah[(r0 + lr) * SA + kb + lk]);
        uint32_t a1 = ld_u32h(&Ah[(r0 + lr + 8) * SA + kb + lk]);
        uint32_t a2 = ld_u32h(&Ah[(r0 + lr) * SA + kb + lk + 8]);
        uint32_t a3 = ld_u32h(&Ah[(r0 + lr + 8) * SA + kb + lk + 8]);
#pragma unroll
        for (int nt = 0; nt < 12; nt++) {
            uint32_t b0 = ld_u32h(&Bs[(c0 + nt * 8 + lr) * SA + kb + lk]);
            uint32_t b1 = ld_u32h(&Bs[(c0 + nt * 8 + lr) * SA + kb + lk + 8]);
            mma16816h(acc[nt], a0, a1, a2, a3, b0, b1);
        }
    }
    __syncthreads();
#pragma unroll
    for (int nt = 0; nt < 12; nt++) {
        int col = c0 + nt * 8 + lk;
        int row = r0 + lr;
        Ys[row * SA + col]           = nan_to_num_f(acc[nt][0] + bo[col]);
        Ys[row * SA + col + 1]       = nan_to_num_f(acc[nt][1] + bo[col + 1]);
        Ys[(row + 8) * SA + col]     = nan_to_num_f(acc[nt][2] + bo[col]);
        Ys[(row + 8) * SA + col + 1] = nan_to_num_f(acc[nt][3] + bo[col + 1]);
    }
    __syncthreads();
    for (int rr = 0; rr < 8; rr++) {
        int r = w * 8 + rr;
        int g = gI[r];
        float v[6];
#pragma unroll
        for (int c = 0; c < 6; c++)
            v[c] = Ys[r * SA + lane * 6 + c] + src[g * DMODEL + lane * 6 + c];
        float s = 0.f;
#pragma unroll
        for (int c = 0; c < 6; c++) s += v[c];
#pragma unroll
        for (int o = 16; o; o >>= 1) s += __shfl_xor_sync(0xffffffffu, s, o);
        float mean = s * (1.0f / 192.0f);
        float vs = 0.f;
#pragma unroll
        for (int c = 0; c < 6; c++) { float d0 = v[c] - mean; vs += d0 * d0; }
#pragma unroll
        for (int o = 16; o; o >>= 1) vs += __shfl_xor_sync(0xffffffffu, vs, o);
        float inv = rsqrtf(vs * (1.0f / 192.0f) + LN_EPS);
#pragma unroll
        for (int c = 0; c < 6; c++) {
            int d = lane * 6 + c;
            g_X1[g * DMODEL + d] = (v[c] - mean) * inv * ln1g[d] + ln1b[d];
        }
    }
}

// ============================================================================
// Kernel 5: FFN + residual + LN2 — fp16x1 mma.sync (unchanged)
// ============================================================================
#define SH 72
__global__ __launch_bounds__(256) void ffn_mma_kernel(
    const float* __restrict__ b1, const float* __restrict__ b2,
    const float* __restrict__ ln2g, const float* __restrict__ ln2b,
    float* __restrict__ out)
{
    extern __shared__ char smc[];
    __half* Xh = (__half*)smc;
    char* WU = smc + 25600;
    __half* W1s = (__half*)WU;
    __half* W2s = (__half*)WU;
    float* Ys = (float*)WU;
    __half* Hh = (__half*)(smc + 76800);
    const int t = threadIdx.x, w = t >> 5, lane = t & 31;
    const int r0g = blockIdx.x * 64;
    const int lr = lane >> 2, lk = (lane & 3) * 2;
    const int r0 = (w & 3) * 16;
    const int c0h = (w >> 2) * 32;
    const int c0y = (w >> 2) * 96;

    for (int i = t; i < 64 * DMODEL; i += 256) {
        int r = i / DMODEL, c = i % DMODEL;
        Xh[r * SA + c] = __float2half(g_X1[(r0g + r) * DMODEL + c]);
    }

    float y[12][4];
#pragma unroll
    for (int n = 0; n < 12; n++)
#pragma unroll
        for (int q = 0; q < 4; q++) y[n][q] = 0.f;

#pragma unroll 1
    for (int fc = 0; fc < DFFN; fc += 64) {
        __syncthreads();
        for (int i = t; i < 64 * 96; i += 256) {
            int f = i / 96, kp = i % 96;
            *(uint32_t*)&W1s[f * SA + kp * 2] = ((const uint32_t*)g_W116)[(fc + f) * 96 + kp];
        }
        __syncthreads();
        float hacc[4][4];
#pragma unroll
        for (int n = 0; n < 4; n++)
#pragma unroll
            for (int q = 0; q < 4; q++) hacc[n][q] = 0.f;
#pragma unroll
        for (int kk = 0; kk < 12; kk++) {
            int kb = kk * 16;
            uint32_t a0 = ld_u32h(&Xh[(r0 + lr) * SA + kb + lk]);
            uint32_t a1 = ld_u32h(&Xh[(r0 + lr + 8) * SA + kb + lk]);
            uint32_t a2 = ld_u32h(&Xh[(r0 + lr) * SA + kb + lk + 8]);
            uint32_t a3 = ld_u32h(&Xh[(r0 + lr + 8) * SA + kb + lk + 8]);
#pragma unroll
            for (int nt = 0; nt < 4; nt++) {
                uint32_t b0 = ld_u32h(&W1s[(c0h + nt * 8 + lr) * SA + kb + lk]);
                uint32_t b1r = ld_u32h(&W1s[(c0h + nt * 8 + lr) * SA + kb + lk + 8]);
                mma16816h(hacc[nt], a0, a1, a2, a3, b0, b1r);
            }
        }
#pragma unroll
        for (int nt = 0; nt < 4; nt++) {
            int col = c0h + nt * 8 + lk;
            int fg = fc + col;
            float bv0 = b1[fg], bv1 = b1[fg + 1];
            Hh[(r0 + lr) * SH + col] = __float2half(fmaxf(hacc[nt][0] + bv0, 0.f));
            Hh[(r0 + lr) * SH + col + 1] = __float2half(fmaxf(hacc[nt][1] + bv1, 0.f));
            Hh[(r0 + lr + 8) * SH + col] = __float2half(fmaxf(hacc[nt][2] + bv0, 0.f));
            Hh[(r0 + lr + 8) * SH + col + 1] = __float2half(fmaxf(hacc[nt][3] + bv1, 0.f));
        }
        __syncthreads();
        for (int i = t; i < DMODEL * 32; i += 256) {
            int d = i / 32, kp = i % 32;
            *(uint32_t*)&W2s[d * SH + kp * 2] = ((const uint32_t*)g_W216)[d * (DFFN / 2) + (fc >> 1) + kp];
        }
        __syncthreads();
#pragma unroll
        for (int kk = 0; kk < 4; kk++) {
            int kb = kk * 16;
            uint32_t a0 = ld_u32h(&Hh[(r0 + lr) * SH + kb + lk]);
            uint32_t a1 = ld_u32h(&Hh[(r0 + lr + 8) * SH + kb + lk]);
            uint32_t a2 = ld_u32h(&Hh[(r0 + lr) * SH + kb + lk + 8]);
            uint32_t a3 = ld_u32h(&Hh[(r0 + lr + 8) * SH + kb + lk + 8]);
#pragma unroll
            for (int nt = 0; nt < 12; nt++) {
                uint32_t b0 = ld_u32h(&W2s[(c0y + nt * 8 + lr) * SH + kb + lk]);
                uint32_t b1r = ld_u32h(&W2s[(c0y + nt * 8 + lr) * SH + kb + lk + 8]);
                mma16816h(y[nt], a0, a1, a2, a3, b0, b1r);
            }
        }
    }
    __syncthreads();
#pragma unroll
    for (int nt = 0; nt < 12; nt++) {
        int col = c0y + nt * 8 + lk;
        int row = r0 + lr;
        Ys[row * SA + col]           = y[nt][0];
        Ys[row * SA + col + 1]       = y[nt][1];
        Ys[(row + 8) * SA + col]     = y[nt][2];
        Ys[(row + 8) * SA + col + 1] = y[nt][3];
    }
    __syncthreads();
    for (int rr = 0; rr < 8; rr++) {
        int r = w * 8 + rr;
        float v[6];
#pragma unroll
        for (int c = 0; c < 6; c++) {
            int d = lane * 6 + c;
            v[c] = Ys[r * SA + d] + b2[d] + g_X1[(r0g + r) * DMODEL + d];
        }
        float s = 0.f;
#pragma unroll
        for (int c = 0; c < 6; c++) s += v[c];
#pragma unroll
        for (int o = 16; o; o >>= 1) s += __shfl_xor_sync(0xffffffffu, s, o);
        float mean = s * (1.0f / 192.0f);
        float vs = 0.f;
#pragma unroll
        for (int c = 0; c < 6; c++) { float d0 = v[c] - mean; vs += d0 * d0; }
#pragma unroll
        for (int o = 16; o; o >>= 1) vs += __shfl_xor_sync(0xffffffffu, vs, o);
        float inv = rsqrtf(vs * (1.0f / 192.0f) + LN_EPS);
#pragma unroll
        for (int c = 0; c < 6; c++) {
            int d = lane * 6 + c;
            out[(r0g + r) * DMODEL + d] = (v[c] - mean) * inv * ln2g[d] + ln2b[d];
        }
    }
}

// ============================================================================
extern "C" void kernel_launch(void* const* d_in, const int* in_sizes, int n_in,
                              void* d_out, int out_size)
{
    const float* src  = (const float*)d_in[0];
    const int*   vcrd = (const int*)d_in[1];
    const float* boxf = (const float*)d_in[2];
    const int*   bcrd = (const int*)d_in[3];
    const float* pos  = (const float*)d_in[4];
    const float* boxp = (const float*)d_in[5];
    const int*   vind = (const int*)d_in[6];
    const float* Wq = (const float*)d_in[7];
    const float* bq = (const float*)d_in[8];
    const float* Wk = (const float*)d_in[9];
    const float* bk = (const float*)d_in[10];
    const float* Wv = (const float*)d_in[11];
    const float* bv = (const float*)d_in[12];
    const float* Wo = (const float*)d_in[13];
    const float* bo = (const float*)d_in[14];
    const float* W1 = (const float*)d_in[15];
    const float* b1 = (const float*)d_in[16];
    const float* W2 = (const float*)d_in[17];
    const float* b2 = (const float*)d_in[18];
    const float* g1 = (const float*)d_in[19];
    const float* lb1 = (const float*)d_in[20];
    const float* g2 = (const float*)d_in[21];
    const float* lb2 = (const float*)d_in[22];
    float* out = (float*)d_out;

    const int SMEM_PROJ = 102656;
    const int SMEM_ATTN = 75392;
    const int SMEM_FFN  = 86016;

    cudaFuncSetAttribute(qproj_mma_kernel, cudaFuncAttributeMaxDynamicSharedMemorySize, SMEM_PROJ);
    cudaFuncSetAttribute(oproj_mma_kernel, cudaFuncAttributeMaxDynamicSharedMemorySize, SMEM_PROJ);
    cudaFuncSetAttribute(attn_mma_kernel, cudaFuncAttributeMaxDynamicSharedMemorySize, SMEM_ATTN);
    cudaFuncSetAttribute(ffn_mma_kernel, cudaFuncAttributeMaxDynamicSharedMemorySize, SMEM_FFN);

    split_weights_kernel<<<3360, 256>>>(Wq, Wo, W1, W2);
    kv_kernel<<<MTOK / 64, 256>>>(boxf, boxp, Wk, bk, Wv, bv);
    qproj_mma_kernel<<<NTOT / 64, 256, SMEM_PROJ>>>(src, pos, vind, bq);
    attn_mma_kernel<<<dim3(NTOT / 64, NHEAD), 256, SMEM_ATTN>>>(vind, vcrd, bcrd);
    oproj_mma_kernel<<<NTOT / 64, 256, SMEM_PROJ>>>(src, vind, bo, g1, lb1);
    ffn_mma_kernel<<<NTOT / 64, 256, SMEM_FFN>>>(b1, b2, g2, lb2, out);
}

// round 14
// speedup vs baseline: 2.9234x; 1.0963x over previous
#include <cuda_runtime.h>
#include <cuda_fp16.h>
#include <math.h>
#include <stdint.h>

#define NTOT 46080
#define DMODEL 192
#define MTOK 256
#define BDIM 256
#define NHEAD 8
#define DHEAD 24
#define DFFN 2048
#define LN_EPS 1e-5f

__device__ float g_K[MTOK * DMODEL];
__device__ float g_V[MTOK * DMODEL];
__device__ float g_Q[NTOT * DMODEL];
__device__ float g_CTX[NTOT * DMODEL];
__device__ float g_X1[NTOT * DMODEL];

__device__ __half g_Wq16[DMODEL * DMODEL];
__device__ __half g_Wo16[DMODEL * DMODEL];
__device__ __half g_W116[DFFN * DMODEL];
__device__ __half g_W216[DMODEL * DFFN];

__device__ __forceinline__ float nan_to_num_f(float x) {
    if (isnan(x)) return 0.0f;
    if (isinf(x)) return x > 0.0f ? 3.402823466e38f : -3.402823466e38f;
    return x;
}

__device__ __forceinline__ void mma16816h(float* d,
    uint32_t a0, uint32_t a1, uint32_t a2, uint32_t a3,
    uint32_t b0, uint32_t b1)
{
    asm volatile(
        "mma.sync.aligned.m16n8k16.row.col.f32.f16.f16.f32 "
        "{%0,%1,%2,%3}, {%4,%5,%6,%7}, {%8,%9}, {%0,%1,%2,%3};\n"
        : "+f"(d[0]), "+f"(d[1]), "+f"(d[2]), "+f"(d[3])
        : "r"(a0), "r"(a1), "r"(a2), "r"(a3), "r"(b0), "r"(b1));
}

__device__ __forceinline__ uint32_t ld_u32h(const __half* p) {
    return *(const uint32_t*)p;
}
__device__ __forceinline__ uint32_t pack_h2f(float lo, float hi) {
    uint32_t a = (uint32_t)__half_as_ushort(__float2half(lo));
    uint32_t b = (uint32_t)__half_as_ushort(__float2half(hi));
    return a | (b << 16);
}

// ============================================================================
// Kernel 0: convert fp32 weights to fp16
// ============================================================================
__global__ __launch_bounds__(256) void split_weights_kernel(
    const float* __restrict__ Wq, const float* __restrict__ Wo,
    const float* __restrict__ W1, const float* __restrict__ W2)
{
    const int NQ = DMODEL * DMODEL;
    const int N1 = DFFN * DMODEL;
    int i = blockIdx.x * 256 + threadIdx.x;
    if (i < NQ)               g_Wq16[i] = __float2half(Wq[i]);
    else if (i < 2*NQ)        g_Wo16[i - NQ] = __float2half(Wo[i - NQ]);
    else if (i < 2*NQ + N1)   g_W116[i - 2*NQ] = __float2half(W1[i - 2*NQ]);
    else if (i < 2*NQ + 2*N1) g_W216[i - 2*NQ - N1] = __float2half(W2[i - 2*NQ - N1]);
}

// ============================================================================
// Kernel 1: K/V projections (fp32 SIMT, unchanged)
// ============================================================================
__global__ __launch_bounds__(256) void kv_kernel(
    const float* __restrict__ boxf, const float* __restrict__ boxp,
    const float* __restrict__ Wk, const float* __restrict__ bk,
    const float* __restrict__ Wv, const float* __restrict__ bv)
{
    __shared__ float Asf[64 * 17];
    __shared__ float Asp[64 * 17];
    __shared__ float Bsk[16 * 193];
    __shared__ float Bsv[16 * 193];
    const int t = threadIdx.x;
    const int m0 = blockIdx.x * 64;
    const int tx = t & 15, ty = t >> 4;

    float ak[4][12], av[4][12];
#pragma unroll
    for (int i = 0; i < 4; i++)
#pragma unroll
        for (int j = 0; j < 12; j++) { ak[i][j] = 0.f; av[i][j] = 0.f; }

    for (int kt = 0; kt < BDIM; kt += 16) {
        __syncthreads();
        for (int i = t; i < 64 * 16; i += 256) {
            int r = i >> 4, k = i & 15;
            Asf[r * 17 + k] = boxf[(m0 + r) * BDIM + kt + k];
            Asp[r * 17 + k] = boxp[(m0 + r) * BDIM + kt + k];
        }
        for (int i = t; i < 16 * DMODEL; i += 256) {
            int d = i >> 4, k = i & 15;
            Bsk[k * 193 + d] = Wk[d * BDIM + kt + k];
            Bsv[k * 193 + d] = Wv[d * BDIM + kt + k];
        }
        __syncthreads();
#pragma unroll
        for (int k = 0; k < 16; k++) {
            float af[4], aa[4], wkr[12], wvr[12];
#pragma unroll
            for (int i = 0; i < 4; i++) {
                af[i] = Asf[(ty * 4 + i) * 17 + k];
                aa[i] = af[i] + Asp[(ty * 4 + i) * 17 + k];
            }
#pragma unroll
            for (int j = 0; j < 12; j++) {
                wkr[j] = Bsk[k * 193 + tx * 12 + j];
                wvr[j] = Bsv[k * 193 + tx * 12 + j];
            }
#pragma unroll
            for (int i = 0; i < 4; i++)
#pragma unroll
                for (int j = 0; j < 12; j++) {
                    ak[i][j] = fmaf(aa[i], wkr[j], ak[i][j]);
                    av[i][j] = fmaf(af[i], wvr[j], av[i][j]);
                }
        }
    }
#pragma unroll
    for (int i = 0; i < 4; i++) {
        int m = m0 + ty * 4 + i;
#pragma unroll
        for (int j = 0; j < 12; j++) {
            int d = tx * 12 + j;
            g_K[m * DMODEL + d] = ak[i][j] + bk[d];
            g_V[m * DMODEL + d] = av[i][j] + bv[d];
        }
    }
}

// ============================================================================
// Kernel 2: Q-proj — fp16x1 mma.sync, 64 rows (unchanged)
// ============================================================================
#define SA 200
__global__ __launch_bounds__(256) void qproj_mma_kernel(
    const float* __restrict__ src, const float* __restrict__ pos,
    const int* __restrict__ vinds, const float* __restrict__ bq)
{
    extern __shared__ char smc[];
    __half* Ah = (__half*)smc;
    __half* Bs = (__half*)(smc + 25600);
    int* gI = (int*)(smc + 102400);
    const int t = threadIdx.x;
    const int r0g = blockIdx.x * 64;
    if (t < 64) gI[t] = vinds[r0g + t];
    __syncthreads();
    for (int i = t; i < 64 * DMODEL; i += 256) {
        int r = i / DMODEL, c = i % DMODEL;
        int g = gI[r];
        Ah[r * SA + c] = __float2half(src[g * DMODEL + c] + pos[g * DMODEL + c]);
    }
    for (int i = t; i < DMODEL * 96; i += 256) {
        int d = i / 96, kp = i % 96;
        *(uint32_t*)&Bs[d * SA + kp * 2] = ((const uint32_t*)g_Wq16)[d * 96 + kp];
    }
    __syncthreads();

    const int w = t >> 5, lane = t & 31;
    const int r0 = (w & 3) * 16, c0 = (w >> 2) * 96;
    const int lr = lane >> 2, lk = (lane & 3) * 2;
    float acc[12][4];
#pragma unroll
    for (int n = 0; n < 12; n++)
#pragma unroll
        for (int q = 0; q < 4; q++) acc[n][q] = 0.f;

#pragma unroll
    for (int kk = 0; kk < 12; kk++) {
        int kb = kk * 16;
        uint32_t a0 = ld_u32h(&Ah[(r0 + lr) * SA + kb + lk]);
        uint32_t a1 = ld_u32h(&Ah[(r0 + lr + 8) * SA + kb + lk]);
        uint32_t a2 = ld_u32h(&Ah[(r0 + lr) * SA + kb + lk + 8]);
        uint32_t a3 = ld_u32h(&Ah[(r0 + lr + 8) * SA + kb + lk + 8]);
#pragma unroll
        for (int nt = 0; nt < 12; nt++) {
            uint32_t b0 = ld_u32h(&Bs[(c0 + nt * 8 + lr) * SA + kb + lk]);
            uint32_t b1 = ld_u32h(&Bs[(c0 + nt * 8 + lr) * SA + kb + lk + 8]);
            mma16816h(acc[nt], a0, a1, a2, a3, b0, b1);
        }
    }
#pragma unroll
    for (int nt = 0; nt < 12; nt++) {
        int col = c0 + nt * 8 + lk;
        int row = r0g + r0 + lr;
        float2 v0 = make_float2(acc[nt][0] + bq[col], acc[nt][1] + bq[col + 1]);
        float2 v1 = make_float2(acc[nt][2] + bq[col], acc[nt][3] + bq[col + 1]);
        *(float2*)&g_Q[row * DMODEL + col] = v0;
        *(float2*)&g_Q[(row + 8) * DMODEL + col] = v1;
    }
}

// ============================================================================
// Kernel 3: attention v3 — unchanged from R13 pass
// ============================================================================
__global__ __launch_bounds__(256) void attn_mma_kernel(
    const int* __restrict__ vinds, const int* __restrict__ vcrd,
    const int* __restrict__ bcrd)
{
    extern __shared__ char smc[];
    __half* Qs = (__half*)smc;
    __half* Ks = (__half*)(smc + 5120);
    __half* Vt = (__half*)(smc + 25600);
    __half* Pt = (__half*)(smc + 38272);
    float* redmax = (float*)(smc + 72064);
    float* redsum = (float*)(smc + 73088);
    int* qb = (int*)(smc + 74112);
    int* bb = (int*)(smc + 74368);

    const int t = threadIdx.x;
    const int q0 = blockIdx.x * 64;
    const int h = blockIdx.y;

    if (t < 64) { int g = vinds[q0 + t]; qb[t] = vcrd[g * 4]; }
    bb[t] = bcrd[t * 4];
    for (int i = t; i < 64 * 16; i += 256) {
        int r = i >> 4, p = i & 15;
        uint32_t v = 0;
        if (p < 12) {
            float2 x = *(const float2*)&g_Q[(q0 + r) * DMODEL + h * DHEAD + p * 2];
            v = pack_h2f(x.x, x.y);
        }
        *(uint32_t*)&Qs[r * 40 + p * 2] = v;
    }
    for (int i = t; i < MTOK * 16; i += 256) {
        int m = i >> 4, p = i & 15;
        uint32_t v = 0;
        if (p < 12) {
            float2 x = *(const float2*)&g_K[m * DMODEL + h * DHEAD + p * 2];
            v = pack_h2f(x.x, x.y);
        }
        *(uint32_t*)&Ks[m * 40 + p * 2] = v;
    }
    for (int i = t; i < DHEAD * 128; i += 256) {
        int d = i >> 7, mp = i & 127;
        float v0 = g_V[(2 * mp) * DMODEL + h * DHEAD + d];
        float v1 = g_V[(2 * mp + 1) * DMODEL + h * DHEAD + d];
        *(uint32_t*)&Vt[d * 264 + 2 * mp] = pack_h2f(v0, v1);
    }
    __syncthreads();

    const int w = t >> 5, lane = t & 31;
    const int lr = lane >> 2, lk = (lane & 3) * 2;
    const float NEG_INF = -__int_as_float(0x7f800000);
    const int mg = w & 1, cg = w >> 1, c0 = cg * 64;

#pragma unroll 1
    for (int sub = 0; sub < 2; sub++) {
        const int mt = mg * 16 + sub * 32;
        float acc[8][4];
#pragma unroll
        for (int n = 0; n < 8; n++)
#pragma unroll
            for (int q = 0; q < 4; q++) acc[n][q] = 0.f;
#pragma unroll
        for (int ks = 0; ks < 2; ks++) {
            int kb = ks * 16;
            uint32_t a0 = ld_u32h(&Qs[(mt + lr) * 40 + kb + lk]);
            uint32_t a1 = ld_u32h(&Qs[(mt + lr + 8) * 40 + kb + lk]);
            uint32_t a2 = ld_u32h(&Qs[(mt + lr) * 40 + kb + lk + 8]);
            uint32_t a3 = ld_u32h(&Qs[(mt + lr + 8) * 40 + kb + lk + 8]);
#pragma unroll
            for (int nt = 0; nt < 8; nt++) {
                uint32_t b0 = ld_u32h(&Ks[(c0 + nt * 8 + lr) * 40 + kb + lk]);
                uint32_t b1 = ld_u32h(&Ks[(c0 + nt * 8 + lr) * 40 + kb + lk + 8]);
                mma16816h(acc[nt], a0, a1, a2, a3, b0, b1);
            }
        }
        {
            const float scale = 0.20412414523193154f;
            int qv0 = qb[mt + lr], qv1 = qb[mt + lr + 8];
#pragma unroll
            for (int nt = 0; nt < 8; nt++) {
                int col = c0 + nt * 8 + lk;
                int b0v = bb[col], b1v = bb[col + 1];
                acc[nt][0] = (qv0 == b0v) ? acc[nt][0] * scale : NEG_INF;
                acc[nt][1] = (qv0 == b1v) ? acc[nt][1] * scale : NEG_INF;
                acc[nt][2] = (qv1 == b0v) ? acc[nt][2] * scale : NEG_INF;
                acc[nt][3] = (qv1 == b1v) ? acc[nt][3] * scale : NEG_INF;
            }
        }
        float mx0 = NEG_INF, mx1 = NEG_INF;
#pragma unroll
        for (int nt = 0; nt < 8; nt++) {
            mx0 = fmaxf(mx0, fmaxf(acc[nt][0], acc[nt][1]));
            mx1 = fmaxf(mx1, fmaxf(acc[nt][2], acc[nt][3]));
        }
        mx0 = fmaxf(mx0, __shfl_xor_sync(0xffffffffu, mx0, 1));
        mx0 = fmaxf(mx0, __shfl_xor_sync(0xffffffffu, mx0, 2));
        mx1 = fmaxf(mx1, __shfl_xor_sync(0xffffffffu, mx1, 1));
        mx1 = fmaxf(mx1, __shfl_xor_sync(0xffffffffu, mx1, 2));
        if ((lane & 3) == 0) {
            redmax[(mt + lr) * 4 + cg] = mx0;
            redmax[(mt + lr + 8) * 4 + cg] = mx1;
        }
        __syncthreads();
        float gmx0 = fmaxf(fmaxf(redmax[(mt + lr) * 4 + 0], redmax[(mt + lr) * 4 + 1]),
                           fmaxf(redmax[(mt + lr) * 4 + 2], redmax[(mt + lr) * 4 + 3]));
        float gmx1 = fmaxf(fmaxf(redmax[(mt + lr + 8) * 4 + 0], redmax[(mt + lr + 8) * 4 + 1]),
                           fmaxf(redmax[(mt + lr + 8) * 4 + 2], redmax[(mt + lr + 8) * 4 + 3]));
        float s0 = 0.f, s1 = 0.f;
#pragma unroll
        for (int nt = 0; nt < 8; nt++) {
            acc[nt][0] = __expf(acc[nt][0] - gmx0);
            acc[nt][1] = __expf(acc[nt][1] - gmx0);
            acc[nt][2] = __expf(acc[nt][2] - gmx1);
            acc[nt][3] = __expf(acc[nt][3] - gmx1);
            s0 += acc[nt][0] + acc[nt][1];
            s1 += acc[nt][2] + acc[nt][3];
        }
        s0 += __shfl_xor_sync(0xffffffffu, s0, 1);
        s0 += __shfl_xor_sync(0xffffffffu, s0, 2);
        s1 += __shfl_xor_sync(0xffffffffu, s1, 1);
        s1 += __shfl_xor_sync(0xffffffffu, s1, 2);
        if ((lane & 3) == 0) {
            redsum[(mt + lr) * 4 + cg] = s0;
            redsum[(mt + lr + 8) * 4 + cg] = s1;
        }
        __syncthreads();
        float gs0 = redsum[(mt + lr) * 4 + 0] + redsum[(mt + lr) * 4 + 1]
                  + redsum[(mt + lr) * 4 + 2] + redsum[(mt + lr) * 4 + 3];
        float gs1 = redsum[(mt + lr + 8) * 4 + 0] + redsum[(mt + lr + 8) * 4 + 1]
                  + redsum[(mt + lr + 8) * 4 + 2] + redsum[(mt + lr + 8) * 4 + 3];
        float inv0 = 1.0f / gs0;   // all-masked -> NaN propagates (matches jax)
        float inv1 = 1.0f / gs1;
#pragma unroll
        for (int nt = 0; nt < 8; nt++) {
            int col = c0 + nt * 8 + lk;
            *(uint32_t*)&Pt[(mt + lr) * 264 + col] = pack_h2f(acc[nt][0] * inv0, acc[nt][1] * inv0);
            *(uint32_t*)&Pt[(mt + lr + 8) * 264 + col] = pack_h2f(acc[nt][2] * inv1, acc[nt][3] * inv1);
        }
    }
    __syncthreads();

#pragma unroll 1
    for (int pass = 0; pass < 2; pass++) {
        int tau = (pass == 0) ? w : (w + 8);
        if (tau >= 12) break;
        const int mt2 = (tau & 3) * 16, n0 = (tau >> 2) * 8;
        float c[4][4];
#pragma unroll
        for (int j = 0; j < 4; j++)
#pragma unroll
            for (int q = 0; q < 4; q++) c[j][q] = 0.f;
#pragma unroll
        for (int ks = 0; ks < 16; ks++) {
            int kb = ks * 16;
            uint32_t a0 = ld_u32h(&Pt[(mt2 + lr) * 264 + kb + lk]);
            uint32_t a1 = ld_u32h(&Pt[(mt2 + lr + 8) * 264 + kb + lk]);
            uint32_t a2 = ld_u32h(&Pt[(mt2 + lr) * 264 + kb + lk + 8]);
            uint32_t a3 = ld_u32h(&Pt[(mt2 + lr + 8) * 264 + kb + lk + 8]);
            uint32_t b0 = ld_u32h(&Vt[(n0 + lr) * 264 + kb + lk]);
            uint32_t b1 = ld_u32h(&Vt[(n0 + lr) * 264 + kb + lk + 8]);
            mma16816h(c[ks & 3], a0, a1, a2, a3, b0, b1);
        }
        float r0v = c[0][0] + c[1][0] + c[2][0] + c[3][0];
        float r1v = c[0][1] + c[1][1] + c[2][1] + c[3][1];
        float r2v = c[0][2] + c[1][2] + c[2][2] + c[3][2];
        float r3v = c[0][3] + c[1][3] + c[2][3] + c[3][3];
        int row = q0 + mt2 + lr;
        int col = h * DHEAD + n0 + lk;
        g_CTX[row * DMODEL + col] = r0v;
        g_CTX[row * DMODEL + col + 1] = r1v;
        g_CTX[(row + 8) * DMODEL + col] = r2v;
        g_CTX[(row + 8) * DMODEL + col + 1] = r3v;
    }
}

// ============================================================================
// Kernel 4: O-proj + residual + LN1 — fp16x1 mma.sync (unchanged)
// ============================================================================
__global__ __launch_bounds__(256) void oproj_mma_kernel(
    const float* __restrict__ src, const int* __restrict__ vinds,
    const float* __restrict__ bo,
    const float* __restrict__ ln1g, const float* __restrict__ ln1b)
{
    extern __shared__ char smc[];
    __half* Ah = (__half*)smc;
    __half* Bs = (__half*)(smc + 25600);
    int* gI = (int*)(smc + 102400);
    float* Ys = (float*)(smc + 25600);
    const int t = threadIdx.x;
    const int r0g = blockIdx.x * 64;
    if (t < 64) gI[t] = vinds[r0g + t];
    for (int i = t; i < 64 * DMODEL; i += 256) {
        int r = i / DMODEL, c = i % DMODEL;
        Ah[r * SA + c] = __float2half(g_CTX[(r0g + r) * DMODEL + c]);
    }
    for (int i = t; i < DMODEL * 96; i += 256) {
        int d = i / 96, kp = i % 96;
        *(uint32_t*)&Bs[d * SA + kp * 2] = ((const uint32_t*)g_Wo16)[d * 96 + kp];
    }
    __syncthreads();

    const int w = t >> 5, lane = t & 31;
    const int r0 = (w & 3) * 16, c0 = (w >> 2) * 96;
    const int lr = lane >> 2, lk = (lane & 3) * 2;
    float acc[12][4];
#pragma unroll
    for (int n = 0; n < 12; n++)
#pragma unroll
        for (int q = 0; q < 4; q++) acc[n][q] = 0.f;

#pragma unroll
    for (int kk = 0; kk < 12; kk++) {
        int kb = kk * 16;
        uint32_t a0 = ld_u32h(&Ah[(r0 + lr) * SA + kb + lk]);
        uint32_t a1 = ld_u32h(&Ah[(r0 + lr + 8) * SA + kb + lk]);
        uint32_t a2 = ld_u32h(&Ah[(r0 + lr) * SA + kb + lk + 8]);
        uint32_t a3 = ld_u32h(&Ah[(r0 + lr + 8) * SA + kb + lk + 8]);
#pragma unroll
        for (int nt = 0; nt < 12; nt++) {
            uint32_t b0 = ld_u32h(&Bs[(c0 + nt * 8 + lr) * SA + kb + lk]);
            uint32_t b1 = ld_u32h(&Bs[(c0 + nt * 8 + lr) * SA + kb + lk + 8]);
            mma16816h(acc[nt], a0, a1, a2, a3, b0, b1);
        }
    }
    __syncthreads();
#pragma unroll
    for (int nt = 0; nt < 12; nt++) {
        int col = c0 + nt * 8 + lk;
        int row = r0 + lr;
        Ys[row * SA + col]           = nan_to_num_f(acc[nt][0] + bo[col]);
        Ys[row * SA + col + 1]       = nan_to_num_f(acc[nt][1] + bo[col + 1]);
        Ys[(row + 8) * SA + col]     = nan_to_num_f(acc[nt][2] + bo[col]);
        Ys[(row + 8) * SA + col + 1] = nan_to_num_f(acc[nt][3] + bo[col + 1]);
    }
    __syncthreads();
    for (int rr = 0; rr < 8; rr++) {
        int r = w * 8 + rr;
        int g = gI[r];
        float v[6];
#pragma unroll
        for (int c = 0; c < 6; c++)
            v[c] = Ys[r * SA + lane * 6 + c] + src[g * DMODEL + lane * 6 + c];
        float s = 0.f;
#pragma unroll
        for (int c = 0; c < 6; c++) s += v[c];
#pragma unroll
        for (int o = 16; o; o >>= 1) s += __shfl_xor_sync(0xffffffffu, s, o);
        float mean = s * (1.0f / 192.0f);
        float vs = 0.f;
#pragma unroll
        for (int c = 0; c < 6; c++) { float d0 = v[c] - mean; vs += d0 * d0; }
#pragma unroll
        for (int o = 16; o; o >>= 1) vs += __shfl_xor_sync(0xffffffffu, vs, o);
        float inv = rsqrtf(vs * (1.0f / 192.0f) + LN_EPS);
#pragma unroll
        for (int c = 0; c < 6; c++) {
            int d = lane * 6 + c;
            g_X1[g * DMODEL + d] = (v[c] - mean) * inv * ln1g[d] + ln1b[d];
        }
    }
}

// ============================================================================
// Kernel 5: FFN + residual + LN2 — fp16x1 mma.sync, 512 threads / 128 rows
// grid 360. 16 warps = 8 row-groups x 2 col-groups.
// smem: Xh [128][200] fp16 @0 (51200) | WU @51200 (27648: W1 [64][200] 25600
//       or W2 [192][72] 27648) | Hh [128][72] fp16 @78848 (18432) -> 97280 live
//       Ys f32 [128][200] overlays @0 after mainloop -> opt-in 102400
// ============================================================================
#define SH 72
__global__ __launch_bounds__(512) void ffn_mma_kernel(
    const float* __restrict__ b1, const float* __restrict__ b2,
    const float* __restrict__ ln2g, const float* __restrict__ ln2b,
    float* __restrict__ out)
{
    extern __shared__ char smc[];
    __half* Xh = (__half*)smc;                  // [128][200]
    char* WU = smc + 51200;
    __half* W1s = (__half*)WU;                  // [64][200]
    __half* W2s = (__half*)WU;                  // [192][72]
    __half* Hh = (__half*)(smc + 78848);        // [128][72]
    float* Ys = (float*)smc;                    // [128][200] f32, overlays X after loop
    const int t = threadIdx.x, w = t >> 5, lane = t & 31;
    const int r0g = blockIdx.x * 128;
    const int lr = lane >> 2, lk = (lane & 3) * 2;
    const int r0 = (w & 7) * 16;      // 8 row groups
    const int cw = w >> 3;            // 2 col groups
    const int c0h = cw * 32;
    const int c0y = cw * 96;

    for (int i = t; i < 128 * DMODEL; i += 512) {
        int r = i / DMODEL, c = i % DMODEL;
        Xh[r * SA + c] = __float2half(g_X1[(r0g + r) * DMODEL + c]);
    }

    float y[12][4];
#pragma unroll
    for (int n = 0; n < 12; n++)
#pragma unroll
        for (int q = 0; q < 4; q++) y[n][q] = 0.f;

#pragma unroll 1
    for (int fc = 0; fc < DFFN; fc += 64) {
        __syncthreads();
        for (int i = t; i < 64 * 96; i += 512) {
            int f = i / 96, kp = i % 96;
            *(uint32_t*)&W1s[f * SA + kp * 2] = ((const uint32_t*)g_W116)[(fc + f) * 96 + kp];
        }
        __syncthreads();
        // ---- phase 1: H = relu(X @ W1c^T + b1) ----
        float hacc[4][4];
#pragma unroll
        for (int n = 0; n < 4; n++)
#pragma unroll
            for (int q = 0; q < 4; q++) hacc[n][q] = 0.f;
#pragma unroll
        for (int kk = 0; kk < 12; kk++) {
            int kb = kk * 16;
            uint32_t a0 = ld_u32h(&Xh[(r0 + lr) * SA + kb + lk]);
            uint32_t a1 = ld_u32h(&Xh[(r0 + lr + 8) * SA + kb + lk]);
            uint32_t a2 = ld_u32h(&Xh[(r0 + lr) * SA + kb + lk + 8]);
            uint32_t a3 = ld_u32h(&Xh[(r0 + lr + 8) * SA + kb + lk + 8]);
#pragma unroll
            for (int nt = 0; nt < 4; nt++) {
                uint32_t b0 = ld_u32h(&W1s[(c0h + nt * 8 + lr) * SA + kb + lk]);
                uint32_t b1r = ld_u32h(&W1s[(c0h + nt * 8 + lr) * SA + kb + lk + 8]);
                mma16816h(hacc[nt], a0, a1, a2, a3, b0, b1r);
            }
        }
#pragma unroll
        for (int nt = 0; nt < 4; nt++) {
            int col = c0h + nt * 8 + lk;
            int fg = fc + col;
            float bv0 = b1[fg], bv1 = b1[fg + 1];
            *(uint32_t*)&Hh[(r0 + lr) * SH + col] =
                pack_h2f(fmaxf(hacc[nt][0] + bv0, 0.f), fmaxf(hacc[nt][1] + bv1, 0.f));
            *(uint32_t*)&Hh[(r0 + lr + 8) * SH + col] =
                pack_h2f(fmaxf(hacc[nt][2] + bv0, 0.f), fmaxf(hacc[nt][3] + bv1, 0.f));
        }
        __syncthreads();
        for (int i = t; i < DMODEL * 32; i += 512) {
            int d = i / 32, kp = i % 32;
            *(uint32_t*)&W2s[d * SH + kp * 2] = ((const uint32_t*)g_W216)[d * (DFFN / 2) + (fc >> 1) + kp];
        }
        __syncthreads();
        // ---- phase 2: Y += H @ W2c^T ----
#pragma unroll
        for (int kk = 0; kk < 4; kk++) {
            int kb = kk * 16;
            uint32_t a0 = ld_u32h(&Hh[(r0 + lr) * SH + kb + lk]);
            uint32_t a1 = ld_u32h(&Hh[(r0 + lr + 8) * SH + kb + lk]);
            uint32_t a2 = ld_u32h(&Hh[(r0 + lr) * SH + kb + lk + 8]);
            uint32_t a3 = ld_u32h(&Hh[(r0 + lr + 8) * SH + kb + lk + 8]);
#pragma unroll
            for (int nt = 0; nt < 12; nt++) {
                uint32_t b0 = ld_u32h(&W2s[(c0y + nt * 8 + lr) * SH + kb + lk]);
                uint32_t b1r = ld_u32h(&W2s[(c0y + nt * 8 + lr) * SH + kb + lk + 8]);
                mma16816h(y[nt], a0, a1, a2, a3, b0, b1r);
            }
        }
    }
    __syncthreads();   // X/W dead -> Ys overlay
#pragma unroll
    for (int nt = 0; nt < 12; nt++) {
        int col = c0y + nt * 8 + lk;
        int row = r0 + lr;
        Ys[row * SA + col]           = y[nt][0];
        Ys[row * SA + col + 1]       = y[nt][1];
        Ys[(row + 8) * SA + col]     = y[nt][2];
        Ys[(row + 8) * SA + col + 1] = y[nt][3];
    }
    __syncthreads();
    for (int rr = 0; rr < 8; rr++) {
        int r = w * 8 + rr;
        float v[6];
#pragma unroll
        for (int c = 0; c < 6; c++) {
            int d = lane * 6 + c;
            v[c] = Ys[r * SA + d] + b2[d] + g_X1[(r0g + r) * DMODEL + d];
        }
        float s = 0.f;
#pragma unroll
        for (int c = 0; c < 6; c++) s += v[c];
#pragma unroll
        for (int o = 16; o; o >>= 1) s += __shfl_xor_sync(0xffffffffu, s, o);
        float mean = s * (1.0f / 192.0f);
        float vs = 0.f;
#pragma unroll
        for (int c = 0; c < 6; c++) { float d0 = v[c] - mean; vs += d0 * d0; }
#pragma unroll
        for (int o = 16; o; o >>= 1) vs += __shfl_xor_sync(0xffffffffu, vs, o);
        float inv = rsqrtf(vs * (1.0f / 192.0f) + LN_EPS);
#pragma unroll
        for (int c = 0; c < 6; c++) {
            int d = lane * 6 + c;
            out[(r0g + r) * DMODEL + d] = (v[c] - mean) * inv * ln2g[d] + ln2b[d];
        }
    }
}

// ============================================================================
extern "C" void kernel_launch(void* const* d_in, const int* in_sizes, int n_in,
                              void* d_out, int out_size)
{
    const float* src  = (const float*)d_in[0];
    const int*   vcrd = (const int*)d_in[1];
    const float* boxf = (const float*)d_in[2];
    const int*   bcrd = (const int*)d_in[3];
    const float* pos  = (const float*)d_in[4];
    const float* boxp = (const float*)d_in[5];
    const int*   vind = (const int*)d_in[6];
    const float* Wq = (const float*)d_in[7];
    const float* bq = (const float*)d_in[8];
    const float* Wk = (const float*)d_in[9];
    const float* bk = (const float*)d_in[10];
    const float* Wv = (const float*)d_in[11];
    const float* bv = (const float*)d_in[12];
    const float* Wo = (const float*)d_in[13];
    const float* bo = (const float*)d_in[14];
    const float* W1 = (const float*)d_in[15];
    const float* b1 = (const float*)d_in[16];
    const float* W2 = (const float*)d_in[17];
    const float* b2 = (const float*)d_in[18];
    const float* g1 = (const float*)d_in[19];
    const float* lb1 = (const float*)d_in[20];
    const float* g2 = (const float*)d_in[21];
    const float* lb2 = (const float*)d_in[22];
    float* out = (float*)d_out;

    const int SMEM_PROJ = 102656;
    const int SMEM_ATTN = 75392;
    const int SMEM_FFN  = 102400;

    cudaFuncSetAttribute(qproj_mma_kernel, cudaFuncAttributeMaxDynamicSharedMemorySize, SMEM_PROJ);
    cudaFuncSetAttribute(oproj_mma_kernel, cudaFuncAttributeMaxDynamicSharedMemorySize, SMEM_PROJ);
    cudaFuncSetAttribute(attn_mma_kernel, cudaFuncAttributeMaxDynamicSharedMemorySize, SMEM_ATTN);
    cudaFuncSetAttribute(ffn_mma_kernel, cudaFuncAttributeMaxDynamicSharedMemorySize, SMEM_FFN);

    split_weights_kernel<<<3360, 256>>>(Wq, Wo, W1, W2);
    kv_kernel<<<MTOK / 64, 256>>>(boxf, boxp, Wk, bk, Wv, bv);
    qproj_mma_kernel<<<NTOT / 64, 256, SMEM_PROJ>>>(src, pos, vind, bq);
    attn_mma_kernel<<<dim3(NTOT / 64, NHEAD), 256, SMEM_ATTN>>>(vind, vcrd, bcrd);
    oproj_mma_kernel<<<NTOT / 64, 256, SMEM_PROJ>>>(src, vind, bo, g1, lb1);
    ffn_mma_kernel<<<NTOT / 128, 512, SMEM_FFN>>>(b1, b2, g2, lb2, out);
}

// round 16
// speedup vs baseline: 2.9684x; 1.0154x over previous
#include <cuda_runtime.h>
#include <cuda_fp16.h>
#include <math.h>
#include <stdint.h>

#define NTOT 46080
#define DMODEL 192
#define MTOK 256
#define BDIM 256
#define NHEAD 8
#define DHEAD 24
#define DFFN 2048
#define LN_EPS 1e-5f

__device__ float g_K[MTOK * DMODEL];
__device__ float g_V[MTOK * DMODEL];
__device__ float g_Q[NTOT * DMODEL];
__device__ float g_CTX[NTOT * DMODEL];
__device__ float g_X1[NTOT * DMODEL];

__device__ __half g_Wq16[DMODEL * DMODEL];
__device__ __half g_Wo16[DMODEL * DMODEL];
__device__ __half g_W116[DFFN * DMODEL];
__device__ __half g_W216[DMODEL * DFFN];

__device__ __forceinline__ float nan_to_num_f(float x) {
    if (isnan(x)) return 0.0f;
    if (isinf(x)) return x > 0.0f ? 3.402823466e38f : -3.402823466e38f;
    return x;
}

__device__ __forceinline__ void mma16816h(float* d,
    uint32_t a0, uint32_t a1, uint32_t a2, uint32_t a3,
    uint32_t b0, uint32_t b1)
{
    asm volatile(
        "mma.sync.aligned.m16n8k16.row.col.f32.f16.f16.f32 "
        "{%0,%1,%2,%3}, {%4,%5,%6,%7}, {%8,%9}, {%0,%1,%2,%3};\n"
        : "+f"(d[0]), "+f"(d[1]), "+f"(d[2]), "+f"(d[3])
        : "r"(a0), "r"(a1), "r"(a2), "r"(a3), "r"(b0), "r"(b1));
}

__device__ __forceinline__ uint32_t ld_u32h(const __half* p) {
    return *(const uint32_t*)p;
}
__device__ __forceinline__ uint32_t pack_h2f(float lo, float hi) {
    uint32_t a = (uint32_t)__half_as_ushort(__float2half(lo));
    uint32_t b = (uint32_t)__half_as_ushort(__float2half(hi));
    return a | (b << 16);
}

// ============================================================================
// Kernel 0: convert fp32 weights to fp16
// ============================================================================
__global__ __launch_bounds__(256) void split_weights_kernel(
    const float* __restrict__ Wq, const float* __restrict__ Wo,
    const float* __restrict__ W1, const float* __restrict__ W2)
{
    const int NQ = DMODEL * DMODEL;
    const int N1 = DFFN * DMODEL;
    int i = blockIdx.x * 256 + threadIdx.x;
    if (i < NQ)               g_Wq16[i] = __float2half(Wq[i]);
    else if (i < 2*NQ)        g_Wo16[i - NQ] = __float2half(Wo[i - NQ]);
    else if (i < 2*NQ + N1)   g_W116[i - 2*NQ] = __float2half(W1[i - 2*NQ]);
    else if (i < 2*NQ + 2*N1) g_W216[i - 2*NQ - N1] = __float2half(W2[i - 2*NQ - N1]);
}

// ============================================================================
// Kernel 1: K/V projections (fp32 SIMT, unchanged)
// ============================================================================
__global__ __launch_bounds__(256) void kv_kernel(
    const float* __restrict__ boxf, const float* __restrict__ boxp,
    const float* __restrict__ Wk, const float* __restrict__ bk,
    const float* __restrict__ Wv, const float* __restrict__ bv)
{
    __shared__ float Asf[64 * 17];
    __shared__ float Asp[64 * 17];
    __shared__ float Bsk[16 * 193];
    __shared__ float Bsv[16 * 193];
    const int t = threadIdx.x;
    const int m0 = blockIdx.x * 64;
    const int tx = t & 15, ty = t >> 4;

    float ak[4][12], av[4][12];
#pragma unroll
    for (int i = 0; i < 4; i++)
#pragma unroll
        for (int j = 0; j < 12; j++) { ak[i][j] = 0.f; av[i][j] = 0.f; }

    for (int kt = 0; kt < BDIM; kt += 16) {
        __syncthreads();
        for (int i = t; i < 64 * 16; i += 256) {
            int r = i >> 4, k = i & 15;
            Asf[r * 17 + k] = boxf[(m0 + r) * BDIM + kt + k];
            Asp[r * 17 + k] = boxp[(m0 + r) * BDIM + kt + k];
        }
        for (int i = t; i < 16 * DMODEL; i += 256) {
            int d = i >> 4, k = i & 15;
            Bsk[k * 193 + d] = Wk[d * BDIM + kt + k];
            Bsv[k * 193 + d] = Wv[d * BDIM + kt + k];
        }
        __syncthreads();
#pragma unroll
        for (int k = 0; k < 16; k++) {
            float af[4], aa[4], wkr[12], wvr[12];
#pragma unroll
            for (int i = 0; i < 4; i++) {
                af[i] = Asf[(ty * 4 + i) * 17 + k];
                aa[i] = af[i] + Asp[(ty * 4 + i) * 17 + k];
            }
#pragma unroll
            for (int j = 0; j < 12; j++) {
                wkr[j] = Bsk[k * 193 + tx * 12 + j];
                wvr[j] = Bsv[k * 193 + tx * 12 + j];
            }
#pragma unroll
            for (int i = 0; i < 4; i++)
#pragma unroll
                for (int j = 0; j < 12; j++) {
                    ak[i][j] = fmaf(aa[i], wkr[j], ak[i][j]);
                    av[i][j] = fmaf(af[i], wvr[j], av[i][j]);
                }
        }
    }
#pragma unroll
    for (int i = 0; i < 4; i++) {
        int m = m0 + ty * 4 + i;
#pragma unroll
        for (int j = 0; j < 12; j++) {
            int d = tx * 12 + j;
            g_K[m * DMODEL + d] = ak[i][j] + bk[d];
            g_V[m * DMODEL + d] = av[i][j] + bv[d];
        }
    }
}

// ============================================================================
// Kernel 2: Q-proj — fp16x1 mma.sync, 64 rows (unchanged)
// ============================================================================
#define SA 200
__global__ __launch_bounds__(256) void qproj_mma_kernel(
    const float* __restrict__ src, const float* __restrict__ pos,
    const int* __restrict__ vinds, const float* __restrict__ bq)
{
    extern __shared__ char smc[];
    __half* Ah = (__half*)smc;
    __half* Bs = (__half*)(smc + 25600);
    int* gI = (int*)(smc + 102400);
    const int t = threadIdx.x;
    const int r0g = blockIdx.x * 64;
    if (t < 64) gI[t] = vinds[r0g + t];
    __syncthreads();
    for (int i = t; i < 64 * DMODEL; i += 256) {
        int r = i / DMODEL, c = i % DMODEL;
        int g = gI[r];
        Ah[r * SA + c] = __float2half(src[g * DMODEL + c] + pos[g * DMODEL + c]);
    }
    for (int i = t; i < DMODEL * 96; i += 256) {
        int d = i / 96, kp = i % 96;
        *(uint32_t*)&Bs[d * SA + kp * 2] = ((const uint32_t*)g_Wq16)[d * 96 + kp];
    }
    __syncthreads();

    const int w = t >> 5, lane = t & 31;
    const int r0 = (w & 3) * 16, c0 = (w >> 2) * 96;
    const int lr = lane >> 2, lk = (lane & 3) * 2;
    float acc[12][4];
#pragma unroll
    for (int n = 0; n < 12; n++)
#pragma unroll
        for (int q = 0; q < 4; q++) acc[n][q] = 0.f;

#pragma unroll
    for (int kk = 0; kk < 12; kk++) {
        int kb = kk * 16;
        uint32_t a0 = ld_u32h(&Ah[(r0 + lr) * SA + kb + lk]);
        uint32_t a1 = ld_u32h(&Ah[(r0 + lr + 8) * SA + kb + lk]);
        uint32_t a2 = ld_u32h(&Ah[(r0 + lr) * SA + kb + lk + 8]);
        uint32_t a3 = ld_u32h(&Ah[(r0 + lr + 8) * SA + kb + lk + 8]);
#pragma unroll
        for (int nt = 0; nt < 12; nt++) {
            uint32_t b0 = ld_u32h(&Bs[(c0 + nt * 8 + lr) * SA + kb + lk]);
            uint32_t b1 = ld_u32h(&Bs[(c0 + nt * 8 + lr) * SA + kb + lk + 8]);
            mma16816h(acc[nt], a0, a1, a2, a3, b0, b1);
        }
    }
#pragma unroll
    for (int nt = 0; nt < 12; nt++) {
        int col = c0 + nt * 8 + lk;
        int row = r0g + r0 + lr;
        float2 v0 = make_float2(acc[nt][0] + bq[col], acc[nt][1] + bq[col + 1]);
        float2 v1 = make_float2(acc[nt][2] + bq[col], acc[nt][3] + bq[col + 1]);
        *(float2*)&g_Q[row * DMODEL + col] = v0;
        *(float2*)&g_Q[(row + 8) * DMODEL + col] = v1;
    }
}

// ============================================================================
// Kernel 3: attention v4 — register S->P fragment reuse (no Pt buffer)
// grid (720, 8) x 256. smem: Qs@0 Ks@5120 Vt@25600 Pp@38272
//   redmax@63872 redsum@64896 qb@65920 bb@66176 -> total 67200
// ============================================================================
__global__ __launch_bounds__(256) void attn_mma_kernel(
    const int* __restrict__ vinds, const int* __restrict__ vcrd,
    const int* __restrict__ bcrd)
{
    extern __shared__ char smc[];
    __half* Qs = (__half*)smc;
    __half* Ks = (__half*)(smc + 5120);
    __half* Vt = (__half*)(smc + 25600);
    float* Pp = (float*)(smc + 38272);          // [4][64][25]
    float* redmax = (float*)(smc + 63872);
    float* redsum = (float*)(smc + 64896);
    int* qb = (int*)(smc + 65920);
    int* bb = (int*)(smc + 66176);

    const int t = threadIdx.x;
    const int q0 = blockIdx.x * 64;
    const int h = blockIdx.y;

    if (t < 64) { int g = vinds[q0 + t]; qb[t] = vcrd[g * 4]; }
    bb[t] = bcrd[t * 4];
    for (int i = t; i < 64 * 16; i += 256) {
        int r = i >> 4, p = i & 15;
        uint32_t v = 0;
        if (p < 12) {
            float2 x = *(const float2*)&g_Q[(q0 + r) * DMODEL + h * DHEAD + p * 2];
            v = pack_h2f(x.x, x.y);
        }
        *(uint32_t*)&Qs[r * 40 + p * 2] = v;
    }
    for (int i = t; i < MTOK * 16; i += 256) {
        int m = i >> 4, p = i & 15;
        uint32_t v = 0;
        if (p < 12) {
            float2 x = *(const float2*)&g_K[m * DMODEL + h * DHEAD + p * 2];
            v = pack_h2f(x.x, x.y);
        }
        *(uint32_t*)&Ks[m * 40 + p * 2] = v;
    }
    for (int i = t; i < DHEAD * 128; i += 256) {
        int d = i >> 7, mp = i & 127;
        float v0 = g_V[(2 * mp) * DMODEL + h * DHEAD + d];
        float v1 = g_V[(2 * mp + 1) * DMODEL + h * DHEAD + d];
        *(uint32_t*)&Vt[d * 264 + 2 * mp] = pack_h2f(v0, v1);
    }
    __syncthreads();

    const int w = t >> 5, lane = t & 31;
    const int lr = lane >> 2, lk = (lane & 3) * 2;
    const float NEG_INF = -__int_as_float(0x7f800000);
    const int mg = w & 1, cg = w >> 1, c0 = cg * 64;

#pragma unroll 1
    for (int sub = 0; sub < 2; sub++) {
        const int mt = mg * 16 + sub * 32;
        float acc[8][4];
#pragma unroll
        for (int n = 0; n < 8; n++)
#pragma unroll
            for (int q = 0; q < 4; q++) acc[n][q] = 0.f;
#pragma unroll
        for (int ks = 0; ks < 2; ks++) {
            int kb = ks * 16;
            uint32_t a0 = ld_u32h(&Qs[(mt + lr) * 40 + kb + lk]);
            uint32_t a1 = ld_u32h(&Qs[(mt + lr + 8) * 40 + kb + lk]);
            uint32_t a2 = ld_u32h(&Qs[(mt + lr) * 40 + kb + lk + 8]);
            uint32_t a3 = ld_u32h(&Qs[(mt + lr + 8) * 40 + kb + lk + 8]);
#pragma unroll
            for (int nt = 0; nt < 8; nt++) {
                uint32_t b0 = ld_u32h(&Ks[(c0 + nt * 8 + lr) * 40 + kb + lk]);
                uint32_t b1 = ld_u32h(&Ks[(c0 + nt * 8 + lr) * 40 + kb + lk + 8]);
                mma16816h(acc[nt], a0, a1, a2, a3, b0, b1);
            }
        }
        {
            const float scale = 0.20412414523193154f;
            int qv0 = qb[mt + lr], qv1 = qb[mt + lr + 8];
#pragma unroll
            for (int nt = 0; nt < 8; nt++) {
                int col = c0 + nt * 8 + lk;
                int b0v = bb[col], b1v = bb[col + 1];
                acc[nt][0] = (qv0 == b0v) ? acc[nt][0] * scale : NEG_INF;
                acc[nt][1] = (qv0 == b1v) ? acc[nt][1] * scale : NEG_INF;
                acc[nt][2] = (qv1 == b0v) ? acc[nt][2] * scale : NEG_INF;
                acc[nt][3] = (qv1 == b1v) ? acc[nt][3] * scale : NEG_INF;
            }
        }
        float mx0 = NEG_INF, mx1 = NEG_INF;
#pragma unroll
        for (int nt = 0; nt < 8; nt++) {
            mx0 = fmaxf(mx0, fmaxf(acc[nt][0], acc[nt][1]));
            mx1 = fmaxf(mx1, fmaxf(acc[nt][2], acc[nt][3]));
        }
        mx0 = fmaxf(mx0, __shfl_xor_sync(0xffffffffu, mx0, 1));
        mx0 = fmaxf(mx0, __shfl_xor_sync(0xffffffffu, mx0, 2));
        mx1 = fmaxf(mx1, __shfl_xor_sync(0xffffffffu, mx1, 1));
        mx1 = fmaxf(mx1, __shfl_xor_sync(0xffffffffu, mx1, 2));
        if ((lane & 3) == 0) {
            redmax[(mt + lr) * 4 + cg] = mx0;
            redmax[(mt + lr + 8) * 4 + cg] = mx1;
        }
        __syncthreads();
        float gmx0 = fmaxf(fmaxf(redmax[(mt + lr) * 4 + 0], redmax[(mt + lr) * 4 + 1]),
                           fmaxf(redmax[(mt + lr) * 4 + 2], redmax[(mt + lr) * 4 + 3]));
        float gmx1 = fmaxf(fmaxf(redmax[(mt + lr + 8) * 4 + 0], redmax[(mt + lr + 8) * 4 + 1]),
                           fmaxf(redmax[(mt + lr + 8) * 4 + 2], redmax[(mt + lr + 8) * 4 + 3]));
        float s0 = 0.f, s1 = 0.f;
#pragma unroll
        for (int nt = 0; nt < 8; nt++) {
            acc[nt][0] = __expf(acc[nt][0] - gmx0);
            acc[nt][1] = __expf(acc[nt][1] - gmx0);
            acc[nt][2] = __expf(acc[nt][2] - gmx1);
            acc[nt][3] = __expf(acc[nt][3] - gmx1);
            s0 += acc[nt][0] + acc[nt][1];
            s1 += acc[nt][2] + acc[nt][3];
        }
        s0 += __shfl_xor_sync(0xffffffffu, s0, 1);
        s0 += __shfl_xor_sync(0xffffffffu, s0, 2);
        s1 += __shfl_xor_sync(0xffffffffu, s1, 1);
        s1 += __shfl_xor_sync(0xffffffffu, s1, 2);
        if ((lane & 3) == 0) {
            redsum[(mt + lr) * 4 + cg] = s0;
            redsum[(mt + lr + 8) * 4 + cg] = s1;
        }
        __syncthreads();
        float gs0 = redsum[(mt + lr) * 4 + 0] + redsum[(mt + lr) * 4 + 1]
                  + redsum[(mt + lr) * 4 + 2] + redsum[(mt + lr) * 4 + 3];
        float gs1 = redsum[(mt + lr + 8) * 4 + 0] + redsum[(mt + lr + 8) * 4 + 1]
                  + redsum[(mt + lr + 8) * 4 + 2] + redsum[(mt + lr + 8) * 4 + 3];
        float inv0 = 1.0f / gs0;   // all-masked -> NaN propagates (matches jax)
        float inv1 = 1.0f / gs1;

        // ---- phase D: partial ctx over this warp's 64-k slice (S->P reg reuse)
        float c[3][4];
#pragma unroll
        for (int nb = 0; nb < 3; nb++)
#pragma unroll
            for (int q = 0; q < 4; q++) c[nb][q] = 0.f;
#pragma unroll
        for (int j = 0; j < 4; j++) {
            uint32_t a0 = pack_h2f(acc[2 * j][0] * inv0, acc[2 * j][1] * inv0);
            uint32_t a1 = pack_h2f(acc[2 * j][2] * inv1, acc[2 * j][3] * inv1);
            uint32_t a2 = pack_h2f(acc[2 * j + 1][0] * inv0, acc[2 * j + 1][1] * inv0);
            uint32_t a3 = pack_h2f(acc[2 * j + 1][2] * inv1, acc[2 * j + 1][3] * inv1);
            int kb = c0 + j * 16;
#pragma unroll
            for (int nb = 0; nb < 3; nb++) {
                uint32_t b0 = ld_u32h(&Vt[(nb * 8 + lr) * 264 + kb + lk]);
                uint32_t b1 = ld_u32h(&Vt[(nb * 8 + lr) * 264 + kb + lk + 8]);
                mma16816h(c[nb], a0, a1, a2, a3, b0, b1);
            }
        }
#pragma unroll
        for (int nb = 0; nb < 3; nb++) {
            int col = nb * 8 + lk;
            Pp[(cg * 64 + mt + lr) * 25 + col]           = c[nb][0];
            Pp[(cg * 64 + mt + lr) * 25 + col + 1]       = c[nb][1];
            Pp[(cg * 64 + mt + lr + 8) * 25 + col]       = c[nb][2];
            Pp[(cg * 64 + mt + lr + 8) * 25 + col + 1]   = c[nb][3];
        }
    }
    __syncthreads();

    for (int i = t; i < 64 * 24; i += 256) {
        int row = i / 24, col = i % 24;
        float s = Pp[(0 * 64 + row) * 25 + col] + Pp[(1 * 64 + row) * 25 + col]
                + Pp[(2 * 64 + row) * 25 + col] + Pp[(3 * 64 + row) * 25 + col];
        g_CTX[(q0 + row) * DMODEL + h * DHEAD + col] = s;
    }
}

// ============================================================================
// Kernel 4: O-proj + residual + LN1 — fp16x1 mma.sync (unchanged)
// ============================================================================
__global__ __launch_bounds__(256) void oproj_mma_kernel(
    const float* __restrict__ src, const int* __restrict__ vinds,
    const float* __restrict__ bo,
    const float* __restrict__ ln1g, const float* __restrict__ ln1b)
{
    extern __shared__ char smc[];
    __half* Ah = (__half*)smc;
    __half* Bs = (__half*)(smc + 25600);
    int* gI = (int*)(smc + 102400);
    float* Ys = (float*)(smc + 25600);
    const int t = threadIdx.x;
    const int r0g = blockIdx.x * 64;
    if (t < 64) gI[t] = vinds[r0g + t];
    for (int i = t; i < 64 * DMODEL; i += 256) {
        int r = i / DMODEL, c = i % DMODEL;
        Ah[r * SA + c] = __float2half(g_CTX[(r0g + r) * DMODEL + c]);
    }
    for (int i = t; i < DMODEL * 96; i += 256) {
        int d = i / 96, kp = i % 96;
        *(uint32_t*)&Bs[d * SA + kp * 2] = ((const uint32_t*)g_Wo16)[d * 96 + kp];
    }
    __syncthreads();

    const int w = t >> 5, lane = t & 31;
    const int r0 = (w & 3) * 16, c0 = (w >> 2) * 96;
    const int lr = lane >> 2, lk = (lane & 3) * 2;
    float acc[12][4];
#pragma unroll
    for (int n = 0; n < 12; n++)
#pragma unroll
        for (int q = 0; q < 4; q++) acc[n][q] = 0.f;

#pragma unroll
    for (int kk = 0; kk < 12; kk++) {
        int kb = kk * 16;
        uint32_t a0 = ld_u32h(&Ah[(r0 + lr) * SA + kb + lk]);
        uint32_t a1 = ld_u32h(&Ah[(r0 + lr + 8) * SA + kb + lk]);
        uint32_t a2 = ld_u32h(&Ah[(r0 + lr) * SA + kb + lk + 8]);
        uint32_t a3 = ld_u32h(&Ah[(r0 + lr + 8) * SA + kb + lk + 8]);
#pragma unroll
        for (int nt = 0; nt < 12; nt++) {
            uint32_t b0 = ld_u32h(&Bs[(c0 + nt * 8 + lr) * SA + kb + lk]);
            uint32_t b1 = ld_u32h(&Bs[(c0 + nt * 8 + lr) * SA + kb + lk + 8]);
            mma16816h(acc[nt], a0, a1, a2, a3, b0, b1);
        }
    }
    __syncthreads();
#pragma unroll
    for (int nt = 0; nt < 12; nt++) {
        int col = c0 + nt * 8 + lk;
        int row = r0 + lr;
        Ys[row * SA + col]           = nan_to_num_f(acc[nt][0] + bo[col]);
        Ys[row * SA + col + 1]       = nan_to_num_f(acc[nt][1] + bo[col + 1]);
        Ys[(row + 8) * SA + col]     = nan_to_num_f(acc[nt][2] + bo[col]);
        Ys[(row + 8) * SA + col + 1] = nan_to_num_f(acc[nt][3] + bo[col + 1]);
    }
    __syncthreads();
    for (int rr = 0; rr < 8; rr++) {
        int r = w * 8 + rr;
        int g = gI[r];
        float v[6];
#pragma unroll
        for (int c = 0; c < 6; c++)
            v[c] = Ys[r * SA + lane * 6 + c] + src[g * DMODEL + lane * 6 + c];
        float s = 0.f;
#pragma unroll
        for (int c = 0; c < 6; c++) s += v[c];
#pragma unroll
        for (int o = 16; o; o >>= 1) s += __shfl_xor_sync(0xffffffffu, s, o);
        float mean = s * (1.0f / 192.0f);
        float vs = 0.f;
#pragma unroll
        for (int c = 0; c < 6; c++) { float d0 = v[c] - mean; vs += d0 * d0; }
#pragma unroll
        for (int o = 16; o; o >>= 1) vs += __shfl_xor_sync(0xffffffffu, vs, o);
        float inv = rsqrtf(vs * (1.0f / 192.0f) + LN_EPS);
#pragma unroll
        for (int c = 0; c < 6; c++) {
            int d = lane * 6 + c;
            g_X1[g * DMODEL + d] = (v[c] - mean) * inv * ln1g[d] + ln1b[d];
        }
    }
}

// ============================================================================
// Kernel 5: FFN + residual + LN2 — fp16x1 mma.sync, 512 threads / 128 rows
// ============================================================================
#define SH 72
__global__ __launch_bounds__(512) void ffn_mma_kernel(
    const float* __restrict__ b1, const float* __restrict__ b2,
    const float* __restrict__ ln2g, const float* __restrict__ ln2b,
    float* __restrict__ out)
{
    extern __shared__ char smc[];
    __half* Xh = (__half*)smc;
    char* WU = smc + 51200;
    __half* W1s = (__half*)WU;
    __half* W2s = (__half*)WU;
    __half* Hh = (__half*)(smc + 78848);
    float* Ys = (float*)smc;
    const int t = threadIdx.x, w = t >> 5, lane = t & 31;
    const int r0g = blockIdx.x * 128;
    const int lr = lane >> 2, lk = (lane & 3) * 2;
    const int r0 = (w & 7) * 16;
    const int cw = w >> 3;
    const int c0h = cw * 32;
    const int c0y = cw * 96;

    for (int i = t; i < 128 * DMODEL; i += 512) {
        int r = i / DMODEL, c = i % DMODEL;
        Xh[r * SA + c] = __float2half(g_X1[(r0g + r) * DMODEL + c]);
    }

    float y[12][4];
#pragma unroll
    for (int n = 0; n < 12; n++)
#pragma unroll
        for (int q = 0; q < 4; q++) y[n][q] = 0.f;

#pragma unroll 1
    for (int fc = 0; fc < DFFN; fc += 64) {
        __syncthreads();
        for (int i = t; i < 64 * 96; i += 512) {
            int f = i / 96, kp = i % 96;
            *(uint32_t*)&W1s[f * SA + kp * 2] = ((const uint32_t*)g_W116)[(fc + f) * 96 + kp];
        }
        __syncthreads();
        float hacc[4][4];
#pragma unroll
        for (int n = 0; n < 4; n++)
#pragma unroll
            for (int q = 0; q < 4; q++) hacc[n][q] = 0.f;
#pragma unroll
        for (int kk = 0; kk < 12; kk++) {
            int kb = kk * 16;
            uint32_t a0 = ld_u32h(&Xh[(r0 + lr) * SA + kb + lk]);
            uint32_t a1 = ld_u32h(&Xh[(r0 + lr + 8) * SA + kb + lk]);
            uint32_t a2 = ld_u32h(&Xh[(r0 + lr) * SA + kb + lk + 8]);
            uint32_t a3 = ld_u32h(&Xh[(r0 + lr + 8) * SA + kb + lk + 8]);
#pragma unroll
            for (int nt = 0; nt < 4; nt++) {
                uint32_t b0 = ld_u32h(&W1s[(c0h + nt * 8 + lr) * SA + kb + lk]);
                uint32_t b1r = ld_u32h(&W1s[(c0h + nt * 8 + lr) * SA + kb + lk + 8]);
                mma16816h(hacc[nt], a0, a1, a2, a3, b0, b1r);
            }
        }
#pragma unroll
        for (int nt = 0; nt < 4; nt++) {
            int col = c0h + nt * 8 + lk;
            int fg = fc + col;
            float bv0 = b1[fg], bv1 = b1[fg + 1];
            *(uint32_t*)&Hh[(r0 + lr) * SH + col] =
                pack_h2f(fmaxf(hacc[nt][0] + bv0, 0.f), fmaxf(hacc[nt][1] + bv1, 0.f));
            *(uint32_t*)&Hh[(r0 + lr + 8) * SH + col] =
                pack_h2f(fmaxf(hacc[nt][2] + bv0, 0.f), fmaxf(hacc[nt][3] + bv1, 0.f));
        }
        __syncthreads();
        for (int i = t; i < DMODEL * 32; i += 512) {
            int d = i / 32, kp = i % 32;
            *(uint32_t*)&W2s[d * SH + kp * 2] = ((const uint32_t*)g_W216)[d * (DFFN / 2) + (fc >> 1) + kp];
        }
        __syncthreads();
#pragma unroll
        for (int kk = 0; kk < 4; kk++) {
            int kb = kk * 16;
            uint32_t a0 = ld_u32h(&Hh[(r0 + lr) * SH + kb + lk]);
            uint32_t a1 = ld_u32h(&Hh[(r0 + lr + 8) * SH + kb + lk]);
            uint32_t a2 = ld_u32h(&Hh[(r0 + lr) * SH + kb + lk + 8]);
            uint32_t a3 = ld_u32h(&Hh[(r0 + lr + 8) * SH + kb + lk + 8]);
#pragma unroll
            for (int nt = 0; nt < 12; nt++) {
                uint32_t b0 = ld_u32h(&W2s[(c0y + nt * 8 + lr) * SH + kb + lk]);
                uint32_t b1r = ld_u32h(&W2s[(c0y + nt * 8 + lr) * SH + kb + lk + 8]);
                mma16816h(y[nt], a0, a1, a2, a3, b0, b1r);
            }
        }
    }
    __syncthreads();
#pragma unroll
    for (int nt = 0; nt < 12; nt++) {
        int col = c0y + nt * 8 + lk;
        int row = r0 + lr;
        Ys[row * SA + col]           = y[nt][0];
        Ys[row * SA + col + 1]       = y[nt][1];
        Ys[(row + 8) * SA + col]     = y[nt][2];
        Ys[(row + 8) * SA + col + 1] = y[nt][3];
    }
    __syncthreads();
    for (int rr = 0; rr < 8; rr++) {
        int r = w * 8 + rr;
        float v[6];
#pragma unroll
        for (int c = 0; c < 6; c++) {
            int d = lane * 6 + c;
            v[c] = Ys[r * SA + d] + b2[d] + g_X1[(r0g + r) * DMODEL + d];
        }
        float s = 0.f;
#pragma unroll
        for (int c = 0; c < 6; c++) s += v[c];
#pragma unroll
        for (int o = 16; o; o >>= 1) s += __shfl_xor_sync(0xffffffffu, s, o);
        float mean = s * (1.0f / 192.0f);
        float vs = 0.f;
#pragma unroll
        for (int c = 0; c < 6; c++) { float d0 = v[c] - mean; vs += d0 * d0; }
#pragma unroll
        for (int o = 16; o; o >>= 1) vs += __shfl_xor_sync(0xffffffffu, vs, o);
        float inv = rsqrtf(vs * (1.0f / 192.0f) + LN_EPS);
#pragma unroll
        for (int c = 0; c < 6; c++) {
            int d = lane * 6 + c;
            out[(r0g + r) * DMODEL + d] = (v[c] - mean) * inv * ln2g[d] + ln2b[d];
        }
    }
}

// ============================================================================
extern "C" void kernel_launch(void* const* d_in, const int* in_sizes, int n_in,
                              void* d_out, int out_size)
{
    const float* src  = (const float*)d_in[0];
    const int*   vcrd = (const int*)d_in[1];
    const float* boxf = (const float*)d_in[2];
    const int*   bcrd = (const int*)d_in[3];
    const float* pos  = (const float*)d_in[4];
    const float* boxp = (const float*)d_in[5];
    const int*   vind = (const int*)d_in[6];
    const float* Wq = (const float*)d_in[7];
    const float* bq = (const float*)d_in[8];
    const float* Wk = (const float*)d_in[9];
    const float* bk = (const float*)d_in[10];
    const float* Wv = (const float*)d_in[11];
    const float* bv = (const float*)d_in[12];
    const float* Wo = (const float*)d_in[13];
    const float* bo = (const float*)d_in[14];
    const float* W1 = (const float*)d_in[15];
    const float* b1 = (const float*)d_in[16];
    const float* W2 = (const float*)d_in[17];
    const float* b2 = (const float*)d_in[18];
    const float* g1 = (const float*)d_in[19];
    const float* lb1 = (const float*)d_in[20];
    const float* g2 = (const float*)d_in[21];
    const float* lb2 = (const float*)d_in[22];
    float* out = (float*)d_out;

    const int SMEM_PROJ = 102656;
    const int SMEM_ATTN = 67200;
    const int SMEM_FFN  = 102400;

    cudaFuncSetAttribute(qproj_mma_kernel, cudaFuncAttributeMaxDynamicSharedMemorySize, SMEM_PROJ);
    cudaFuncSetAttribute(oproj_mma_kernel, cudaFuncAttributeMaxDynamicSharedMemorySize, SMEM_PROJ);
    cudaFuncSetAttribute(attn_mma_kernel, cudaFuncAttributeMaxDynamicSharedMemorySize, SMEM_ATTN);
    cudaFuncSetAttribute(ffn_mma_kernel, cudaFuncAttributeMaxDynamicSharedMemorySize, SMEM_FFN);

    split_weights_kernel<<<3360, 256>>>(Wq, Wo, W1, W2);
    kv_kernel<<<MTOK / 64, 256>>>(boxf, boxp, Wk, bk, Wv, bv);
    qproj_mma_kernel<<<NTOT / 64, 256, SMEM_PROJ>>>(src, pos, vind, bq);
    attn_mma_kernel<<<dim3(NTOT / 64, NHEAD), 256, SMEM_ATTN>>>(vind, vcrd, bcrd);
    oproj_mma_kernel<<<NTOT / 64, 256, SMEM_PROJ>>>(src, vind, bo, g1, lb1);
    ffn_mma_kernel<<<NTOT / 128, 512, SMEM_FFN>>>(b1, b2, g2, lb2, out);
}

// round 17
// speedup vs baseline: 3.0029x; 1.0116x over previous
#include <cuda_runtime.h>
#include <cuda_fp16.h>
#include <math.h>
#include <stdint.h>

#define NTOT 46080
#define DMODEL 192
#define MTOK 256
#define BDIM 256
#define NHEAD 8
#define DHEAD 24
#define DFFN 2048
#define LN_EPS 1e-5f

__device__ float g_K[MTOK * DMODEL];
__device__ float g_V[MTOK * DMODEL];
__device__ float g_Q[NTOT * DMODEL];
__device__ float g_CTX[NTOT * DMODEL];
__device__ float g_X1[NTOT * DMODEL];

__device__ __half g_Wq16[DMODEL * DMODEL];
__device__ __half g_Wo16[DMODEL * DMODEL];
__device__ __half g_W116[DFFN * DMODEL];
__device__ __half g_W216[DMODEL * DFFN];

__device__ __forceinline__ float nan_to_num_f(float x) {
    if (isnan(x)) return 0.0f;
    if (isinf(x)) return x > 0.0f ? 3.402823466e38f : -3.402823466e38f;
    return x;
}

__device__ __forceinline__ void mma16816h(float* d,
    uint32_t a0, uint32_t a1, uint32_t a2, uint32_t a3,
    uint32_t b0, uint32_t b1)
{
    asm volatile(
        "mma.sync.aligned.m16n8k16.row.col.f32.f16.f16.f32 "
        "{%0,%1,%2,%3}, {%4,%5,%6,%7}, {%8,%9}, {%0,%1,%2,%3};\n"
        : "+f"(d[0]), "+f"(d[1]), "+f"(d[2]), "+f"(d[3])
        : "r"(a0), "r"(a1), "r"(a2), "r"(a3), "r"(b0), "r"(b1));
}

__device__ __forceinline__ uint32_t ld_u32h(const __half* p) {
    return *(const uint32_t*)p;
}
__device__ __forceinline__ uint32_t pack_h2f(float lo, float hi) {
    uint32_t a = (uint32_t)__half_as_ushort(__float2half(lo));
    uint32_t b = (uint32_t)__half_as_ushort(__float2half(hi));
    return a | (b << 16);
}

// ============================================================================
// Kernel 0: convert fp32 weights to fp16
// ============================================================================
__global__ __launch_bounds__(256) void split_weights_kernel(
    const float* __restrict__ Wq, const float* __restrict__ Wo,
    const float* __restrict__ W1, const float* __restrict__ W2)
{
    const int NQ = DMODEL * DMODEL;
    const int N1 = DFFN * DMODEL;
    int i = blockIdx.x * 256 + threadIdx.x;
    if (i < NQ)               g_Wq16[i] = __float2half(Wq[i]);
    else if (i < 2*NQ)        g_Wo16[i - NQ] = __float2half(Wo[i - NQ]);
    else if (i < 2*NQ + N1)   g_W116[i - 2*NQ] = __float2half(W1[i - 2*NQ]);
    else if (i < 2*NQ + 2*N1) g_W216[i - 2*NQ - N1] = __float2half(W2[i - 2*NQ - N1]);
}

// ============================================================================
// Kernel 1: K/V projections (fp32 SIMT, unchanged)
// ============================================================================
__global__ __launch_bounds__(256) void kv_kernel(
    const float* __restrict__ boxf, const float* __restrict__ boxp,
    const float* __restrict__ Wk, const float* __restrict__ bk,
    const float* __restrict__ Wv, const float* __restrict__ bv)
{
    __shared__ float Asf[64 * 17];
    __shared__ float Asp[64 * 17];
    __shared__ float Bsk[16 * 193];
    __shared__ float Bsv[16 * 193];
    const int t = threadIdx.x;
    const int m0 = blockIdx.x * 64;
    const int tx = t & 15, ty = t >> 4;

    float ak[4][12], av[4][12];
#pragma unroll
    for (int i = 0; i < 4; i++)
#pragma unroll
        for (int j = 0; j < 12; j++) { ak[i][j] = 0.f; av[i][j] = 0.f; }

    for (int kt = 0; kt < BDIM; kt += 16) {
        __syncthreads();
        for (int i = t; i < 64 * 16; i += 256) {
            int r = i >> 4, k = i & 15;
            Asf[r * 17 + k] = boxf[(m0 + r) * BDIM + kt + k];
            Asp[r * 17 + k] = boxp[(m0 + r) * BDIM + kt + k];
        }
        for (int i = t; i < 16 * DMODEL; i += 256) {
            int d = i >> 4, k = i & 15;
            Bsk[k * 193 + d] = Wk[d * BDIM + kt + k];
            Bsv[k * 193 + d] = Wv[d * BDIM + kt + k];
        }
        __syncthreads();
#pragma unroll
        for (int k = 0; k < 16; k++) {
            float af[4], aa[4], wkr[12], wvr[12];
#pragma unroll
            for (int i = 0; i < 4; i++) {
                af[i] = Asf[(ty * 4 + i) * 17 + k];
                aa[i] = af[i] + Asp[(ty * 4 + i) * 17 + k];
            }
#pragma unroll
            for (int j = 0; j < 12; j++) {
                wkr[j] = Bsk[k * 193 + tx * 12 + j];
                wvr[j] = Bsv[k * 193 + tx * 12 + j];
            }
#pragma unroll
            for (int i = 0; i < 4; i++)
#pragma unroll
                for (int j = 0; j < 12; j++) {
                    ak[i][j] = fmaf(aa[i], wkr[j], ak[i][j]);
                    av[i][j] = fmaf(af[i], wvr[j], av[i][j]);
                }
        }
    }
#pragma unroll
    for (int i = 0; i < 4; i++) {
        int m = m0 + ty * 4 + i;
#pragma unroll
        for (int j = 0; j < 12; j++) {
            int d = tx * 12 + j;
            g_K[m * DMODEL + d] = ak[i][j] + bk[d];
            g_V[m * DMODEL + d] = av[i][j] + bv[d];
        }
    }
}

// ============================================================================
// Kernel 2: Q-proj — fp16x1 mma.sync, 64 rows (unchanged)
// ============================================================================
#define SA 200
__global__ __launch_bounds__(256) void qproj_mma_kernel(
    const float* __restrict__ src, const float* __restrict__ pos,
    const int* __restrict__ vinds, const float* __restrict__ bq)
{
    extern __shared__ char smc[];
    __half* Ah = (__half*)smc;
    __half* Bs = (__half*)(smc + 25600);
    int* gI = (int*)(smc + 102400);
    const int t = threadIdx.x;
    const int r0g = blockIdx.x * 64;
    if (t < 64) gI[t] = vinds[r0g + t];
    __syncthreads();
    for (int i = t; i < 64 * DMODEL; i += 256) {
        int r = i / DMODEL, c = i % DMODEL;
        int g = gI[r];
        Ah[r * SA + c] = __float2half(src[g * DMODEL + c] + pos[g * DMODEL + c]);
    }
    for (int i = t; i < DMODEL * 96; i += 256) {
        int d = i / 96, kp = i % 96;
        *(uint32_t*)&Bs[d * SA + kp * 2] = ((const uint32_t*)g_Wq16)[d * 96 + kp];
    }
    __syncthreads();

    const int w = t >> 5, lane = t & 31;
    const int r0 = (w & 3) * 16, c0 = (w >> 2) * 96;
    const int lr = lane >> 2, lk = (lane & 3) * 2;
    float acc[12][4];
#pragma unroll
    for (int n = 0; n < 12; n++)
#pragma unroll
        for (int q = 0; q < 4; q++) acc[n][q] = 0.f;

#pragma unroll
    for (int kk = 0; kk < 12; kk++) {
        int kb = kk * 16;
        uint32_t a0 = ld_u32h(&Ah[(r0 + lr) * SA + kb + lk]);
        uint32_t a1 = ld_u32h(&Ah[(r0 + lr + 8) * SA + kb + lk]);
        uint32_t a2 = ld_u32h(&Ah[(r0 + lr) * SA + kb + lk + 8]);
        uint32_t a3 = ld_u32h(&Ah[(r0 + lr + 8) * SA + kb + lk + 8]);
#pragma unroll
        for (int nt = 0; nt < 12; nt++) {
            uint32_t b0 = ld_u32h(&Bs[(c0 + nt * 8 + lr) * SA + kb + lk]);
            uint32_t b1 = ld_u32h(&Bs[(c0 + nt * 8 + lr) * SA + kb + lk + 8]);
            mma16816h(acc[nt], a0, a1, a2, a3, b0, b1);
        }
    }
#pragma unroll
    for (int nt = 0; nt < 12; nt++) {
        int col = c0 + nt * 8 + lk;
        int row = r0g + r0 + lr;
        float2 v0 = make_float2(acc[nt][0] + bq[col], acc[nt][1] + bq[col + 1]);
        float2 v1 = make_float2(acc[nt][2] + bq[col], acc[nt][3] + bq[col + 1]);
        *(float2*)&g_Q[row * DMODEL + col] = v0;
        *(float2*)&g_Q[(row + 8) * DMODEL + col] = v1;
    }
}

// ============================================================================
// Kernel 3: attention v5 — single-barrier online softmax + atomic ctx reduce
// grid (720, 8) x 256. smem (bytes):
//   Qs fp16 [64][40]  @0      (5120)
//   Ks fp16 [256][40] @5120   (20480)
//   Vt fp16 [24][264] @25600  (12672)
//   Cp f32 [64][25]   @38272  (6400)   atomic ctx accumulator
//   redm f32 [2][64][4] @44672 (2048)
//   reds f32 [2][64][4] @46720 (2048)
//   qb int[64] @48768, bb int[256] @49024 -> total 50048 (4 blocks/SM)
// ============================================================================
__global__ __launch_bounds__(256) void attn_mma_kernel(
    const int* __restrict__ vinds, const int* __restrict__ vcrd,
    const int* __restrict__ bcrd)
{
    extern __shared__ char smc[];
    __half* Qs = (__half*)smc;
    __half* Ks = (__half*)(smc + 5120);
    __half* Vt = (__half*)(smc + 25600);
    float* Cp = (float*)(smc + 38272);
    float* redm = (float*)(smc + 44672);
    float* reds = (float*)(smc + 46720);
    int* qb = (int*)(smc + 48768);
    int* bb = (int*)(smc + 49024);

    const int t = threadIdx.x;
    const int q0 = blockIdx.x * 64;
    const int h = blockIdx.y;

    if (t < 64) { int g = vinds[q0 + t]; qb[t] = vcrd[g * 4]; }
    bb[t] = bcrd[t * 4];
    for (int i = t; i < 64 * 16; i += 256) {
        int r = i >> 4, p = i & 15;
        uint32_t v = 0;
        if (p < 12) {
            float2 x = *(const float2*)&g_Q[(q0 + r) * DMODEL + h * DHEAD + p * 2];
            v = pack_h2f(x.x, x.y);
        }
        *(uint32_t*)&Qs[r * 40 + p * 2] = v;
    }
    for (int i = t; i < MTOK * 16; i += 256) {
        int m = i >> 4, p = i & 15;
        uint32_t v = 0;
        if (p < 12) {
            float2 x = *(const float2*)&g_K[m * DMODEL + h * DHEAD + p * 2];
            v = pack_h2f(x.x, x.y);
        }
        *(uint32_t*)&Ks[m * 40 + p * 2] = v;
    }
    for (int i = t; i < DHEAD * 128; i += 256) {
        int d = i >> 7, mp = i & 127;
        float v0 = g_V[(2 * mp) * DMODEL + h * DHEAD + d];
        float v1 = g_V[(2 * mp + 1) * DMODEL + h * DHEAD + d];
        *(uint32_t*)&Vt[d * 264 + 2 * mp] = pack_h2f(v0, v1);
    }
    for (int i = t; i < 64 * 25; i += 256) Cp[i] = 0.f;
    __syncthreads();

    const int w = t >> 5, lane = t & 31;
    const int lr = lane >> 2, lk = (lane & 3) * 2;
    const float NEG_INF = -__int_as_float(0x7f800000);
    const int mg = w & 1, cg = w >> 1, c0 = cg * 64;

#pragma unroll 1
    for (int sub = 0; sub < 2; sub++) {
        const int mt = mg * 16 + sub * 32;
        float* rm = redm + sub * 256;
        float* rs = reds + sub * 256;
        float acc[8][4];
#pragma unroll
        for (int n = 0; n < 8; n++)
#pragma unroll
            for (int q = 0; q < 4; q++) acc[n][q] = 0.f;
#pragma unroll
        for (int ks = 0; ks < 2; ks++) {
            int kb = ks * 16;
            uint32_t a0 = ld_u32h(&Qs[(mt + lr) * 40 + kb + lk]);
            uint32_t a1 = ld_u32h(&Qs[(mt + lr + 8) * 40 + kb + lk]);
            uint32_t a2 = ld_u32h(&Qs[(mt + lr) * 40 + kb + lk + 8]);
            uint32_t a3 = ld_u32h(&Qs[(mt + lr + 8) * 40 + kb + lk + 8]);
#pragma unroll
            for (int nt = 0; nt < 8; nt++) {
                uint32_t b0 = ld_u32h(&Ks[(c0 + nt * 8 + lr) * 40 + kb + lk]);
                uint32_t b1 = ld_u32h(&Ks[(c0 + nt * 8 + lr) * 40 + kb + lk + 8]);
                mma16816h(acc[nt], a0, a1, a2, a3, b0, b1);
            }
        }
        {
            const float scale = 0.20412414523193154f;
            int qv0 = qb[mt + lr], qv1 = qb[mt + lr + 8];
#pragma unroll
            for (int nt = 0; nt < 8; nt++) {
                int col = c0 + nt * 8 + lk;
                int b0v = bb[col], b1v = bb[col + 1];
                acc[nt][0] = (qv0 == b0v) ? acc[nt][0] * scale : NEG_INF;
                acc[nt][1] = (qv0 == b1v) ? acc[nt][1] * scale : NEG_INF;
                acc[nt][2] = (qv1 == b0v) ? acc[nt][2] * scale : NEG_INF;
                acc[nt][3] = (qv1 == b1v) ? acc[nt][3] * scale : NEG_INF;
            }
        }
        // local max (clamped) over this warp's 64-col slice
        float mx0 = NEG_INF, mx1 = NEG_INF;
#pragma unroll
        for (int nt = 0; nt < 8; nt++) {
            mx0 = fmaxf(mx0, fmaxf(acc[nt][0], acc[nt][1]));
            mx1 = fmaxf(mx1, fmaxf(acc[nt][2], acc[nt][3]));
        }
        mx0 = fmaxf(mx0, __shfl_xor_sync(0xffffffffu, mx0, 1));
        mx0 = fmaxf(mx0, __shfl_xor_sync(0xffffffffu, mx0, 2));
        mx1 = fmaxf(mx1, __shfl_xor_sync(0xffffffffu, mx1, 1));
        mx1 = fmaxf(mx1, __shfl_xor_sync(0xffffffffu, mx1, 2));
        float mxc0 = fmaxf(mx0, -1e30f);
        float mxc1 = fmaxf(mx1, -1e30f);
        // exp against LOCAL max + local sum (single reduction round)
        float s0 = 0.f, s1 = 0.f;
#pragma unroll
        for (int nt = 0; nt < 8; nt++) {
            acc[nt][0] = __expf(acc[nt][0] - mxc0);
            acc[nt][1] = __expf(acc[nt][1] - mxc0);
            acc[nt][2] = __expf(acc[nt][2] - mxc1);
            acc[nt][3] = __expf(acc[nt][3] - mxc1);
            s0 += acc[nt][0] + acc[nt][1];
            s1 += acc[nt][2] + acc[nt][3];
        }
        s0 += __shfl_xor_sync(0xffffffffu, s0, 1);
        s0 += __shfl_xor_sync(0xffffffffu, s0, 2);
        s1 += __shfl_xor_sync(0xffffffffu, s1, 1);
        s1 += __shfl_xor_sync(0xffffffffu, s1, 2);
        if ((lane & 3) == 0) {
            rm[(mt + lr) * 4 + cg] = mxc0;
            rm[(mt + lr + 8) * 4 + cg] = mxc1;
            rs[(mt + lr) * 4 + cg] = s0;
            rs[(mt + lr + 8) * 4 + cg] = s1;
        }
        __syncthreads();
        // global combine: gs = sum_i s_i * exp(m_i - gmx)
        float f0, f1;
        {
            float m0a = rm[(mt + lr) * 4 + 0], m0b = rm[(mt + lr) * 4 + 1];
            float m0c = rm[(mt + lr) * 4 + 2], m0d = rm[(mt + lr) * 4 + 3];
            float gmx = fmaxf(fmaxf(m0a, m0b), fmaxf(m0c, m0d));
            float gs = rs[(mt + lr) * 4 + 0] * __expf(m0a - gmx)
                     + rs[(mt + lr) * 4 + 1] * __expf(m0b - gmx)
                     + rs[(mt + lr) * 4 + 2] * __expf(m0c - gmx)
                     + rs[(mt + lr) * 4 + 3] * __expf(m0d - gmx);
            f0 = __expf(mxc0 - gmx) / gs;   // all-masked row: gs=0 -> inf -> 0*inf=NaN (matches jax)
        }
        {
            float m1a = rm[(mt + lr + 8) * 4 + 0], m1b = rm[(mt + lr + 8) * 4 + 1];
            float m1c = rm[(mt + lr + 8) * 4 + 2], m1d = rm[(mt + lr + 8) * 4 + 3];
            float gmx = fmaxf(fmaxf(m1a, m1b), fmaxf(m1c, m1d));
            float gs = rs[(mt + lr + 8) * 4 + 0] * __expf(m1a - gmx)
                     + rs[(mt + lr + 8) * 4 + 1] * __expf(m1b - gmx)
                     + rs[(mt + lr + 8) * 4 + 2] * __expf(m1c - gmx)
                     + rs[(mt + lr + 8) * 4 + 3] * __expf(m1d - gmx);
            f1 = __expf(mxc1 - gmx) / gs;
        }

        // ---- phase D: partial ctx over this warp's 64-k slice (S->P reg reuse)
        float c[3][4];
#pragma unroll
        for (int nb = 0; nb < 3; nb++)
#pragma unroll
            for (int q = 0; q < 4; q++) c[nb][q] = 0.f;
#pragma unroll
        for (int j = 0; j < 4; j++) {
            uint32_t a0 = pack_h2f(acc[2 * j][0] * f0, acc[2 * j][1] * f0);
            uint32_t a1 = pack_h2f(acc[2 * j][2] * f1, acc[2 * j][3] * f1);
            uint32_t a2 = pack_h2f(acc[2 * j + 1][0] * f0, acc[2 * j + 1][1] * f0);
            uint32_t a3 = pack_h2f(acc[2 * j + 1][2] * f1, acc[2 * j + 1][3] * f1);
            int kb = c0 + j * 16;
#pragma unroll
            for (int nb = 0; nb < 3; nb++) {
                uint32_t b0 = ld_u32h(&Vt[(nb * 8 + lr) * 264 + kb + lk]);
                uint32_t b1 = ld_u32h(&Vt[(nb * 8 + lr) * 264 + kb + lk + 8]);
                mma16816h(c[nb], a0, a1, a2, a3, b0, b1);
            }
        }
#pragma unroll
        for (int nb = 0; nb < 3; nb++) {
            int col = nb * 8 + lk;
            atomicAdd(&Cp[(mt + lr) * 25 + col], c[nb][0]);
            atomicAdd(&Cp[(mt + lr) * 25 + col + 1], c[nb][1]);
            atomicAdd(&Cp[(mt + lr + 8) * 25 + col], c[nb][2]);
            atomicAdd(&Cp[(mt + lr + 8) * 25 + col + 1], c[nb][3]);
        }
    }
    __syncthreads();

    for (int i = t; i < 64 * 24; i += 256) {
        int row = i / 24, col = i % 24;
        g_CTX[(q0 + row) * DMODEL + h * DHEAD + col] = Cp[row * 25 + col];
    }
}

// ============================================================================
// Kernel 4: O-proj + residual + LN1 — fp16x1 mma.sync (unchanged)
// ============================================================================
__global__ __launch_bounds__(256) void oproj_mma_kernel(
    const float* __restrict__ src, const int* __restrict__ vinds,
    const float* __restrict__ bo,
    const float* __restrict__ ln1g, const float* __restrict__ ln1b)
{
    extern __shared__ char smc[];
    __half* Ah = (__half*)smc;
    __half* Bs = (__half*)(smc + 25600);
    int* gI = (int*)(smc + 102400);
    float* Ys = (float*)(smc + 25600);
    const int t = threadIdx.x;
    const int r0g = blockIdx.x * 64;
    if (t < 64) gI[t] = vinds[r0g + t];
    for (int i = t; i < 64 * DMODEL; i += 256) {
        int r = i / DMODEL, c = i % DMODEL;
        Ah[r * SA + c] = __float2half(g_CTX[(r0g + r) * DMODEL + c]);
    }
    for (int i = t; i < DMODEL * 96; i += 256) {
        int d = i / 96, kp = i % 96;
        *(uint32_t*)&Bs[d * SA + kp * 2] = ((const uint32_t*)g_Wo16)[d * 96 + kp];
    }
    __syncthreads();

    const int w = t >> 5, lane = t & 31;
    const int r0 = (w & 3) * 16, c0 = (w >> 2) * 96;
    const int lr = lane >> 2, lk = (lane & 3) * 2;
    float acc[12][4];
#pragma unroll
    for (int n = 0; n < 12; n++)
#pragma unroll
        for (int q = 0; q < 4; q++) acc[n][q] = 0.f;

#pragma unroll
    for (int kk = 0; kk < 12; kk++) {
        int kb = kk * 16;
        uint32_t a0 = ld_u32h(&Ah[(r0 + lr) * SA + kb + lk]);
        uint32_t a1 = ld_u32h(&Ah[(r0 + lr + 8) * SA + kb + lk]);
        uint32_t a2 = ld_u32h(&Ah[(r0 + lr) * SA + kb + lk + 8]);
        uint32_t a3 = ld_u32h(&Ah[(r0 + lr + 8) * SA + kb + lk + 8]);
#pragma unroll
        for (int nt = 0; nt < 12; nt++) {
            uint32_t b0 = ld_u32h(&Bs[(c0 + nt * 8 + lr) * SA + kb + lk]);
            uint32_t b1 = ld_u32h(&Bs[(c0 + nt * 8 + lr) * SA + kb + lk + 8]);
            mma16816h(acc[nt], a0, a1, a2, a3, b0, b1);
        }
    }
    __syncthreads();
#pragma unroll
    for (int nt = 0; nt < 12; nt++) {
        int col = c0 + nt * 8 + lk;
        int row = r0 + lr;
        Ys[row * SA + col]           = nan_to_num_f(acc[nt][0] + bo[col]);
        Ys[row * SA + col + 1]       = nan_to_num_f(acc[nt][1] + bo[col + 1]);
        Ys[(row + 8) * SA + col]     = nan_to_num_f(acc[nt][2] + bo[col]);
        Ys[(row + 8) * SA + col + 1] = nan_to_num_f(acc[nt][3] + bo[col + 1]);
    }
    __syncthreads();
    for (int rr = 0; rr < 8; rr++) {
        int r = w * 8 + rr;
        int g = gI[r];
        float v[6];
#pragma unroll
        for (int c = 0; c < 6; c++)
            v[c] = Ys[r * SA + lane * 6 + c] + src[g * DMODEL + lane * 6 + c];
        float s = 0.f;
#pragma unroll
        for (int c = 0; c < 6; c++) s += v[c];
#pragma unroll
        for (int o = 16; o; o >>= 1) s += __shfl_xor_sync(0xffffffffu, s, o);
        float mean = s * (1.0f / 192.0f);
        float vs = 0.f;
#pragma unroll
        for (int c = 0; c < 6; c++) { float d0 = v[c] - mean; vs += d0 * d0; }
#pragma unroll
        for (int o = 16; o; o >>= 1) vs += __shfl_xor_sync(0xffffffffu, vs, o);
        float inv = rsqrtf(vs * (1.0f / 192.0f) + LN_EPS);
#pragma unroll
        for (int c = 0; c < 6; c++) {
            int d = lane * 6 + c;
            g_X1[g * DMODEL + d] = (v[c] - mean) * inv * ln1g[d] + ln1b[d];
        }
    }
}

// ============================================================================
// Kernel 5: FFN + residual + LN2 — fp16x1 mma.sync, 512 threads / 128 rows
// ============================================================================
#define SH 72
__global__ __launch_bounds__(512) void ffn_mma_kernel(
    const float* __restrict__ b1, const float* __restrict__ b2,
    const float* __restrict__ ln2g, const float* __restrict__ ln2b,
    float* __restrict__ out)
{
    extern __shared__ char smc[];
    __half* Xh = (__half*)smc;
    char* WU = smc + 51200;
    __half* W1s = (__half*)WU;
    __half* W2s = (__half*)WU;
    __half* Hh = (__half*)(smc + 78848);
    float* Ys = (float*)smc;
    const int t = threadIdx.x, w = t >> 5, lane = t & 31;
    const int r0g = blockIdx.x * 128;
    const int lr = lane >> 2, lk = (lane & 3) * 2;
    const int r0 = (w & 7) * 16;
    const int cw = w >> 3;
    const int c0h = cw * 32;
    const int c0y = cw * 96;

    for (int i = t; i < 128 * DMODEL; i += 512) {
        int r = i / DMODEL, c = i % DMODEL;
        Xh[r * SA + c] = __float2half(g_X1[(r0g + r) * DMODEL + c]);
    }

    float y[12][4];
#pragma unroll
    for (int n = 0; n < 12; n++)
#pragma unroll
        for (int q = 0; q < 4; q++) y[n][q] = 0.f;

#pragma unroll 1
    for (int fc = 0; fc < DFFN; fc += 64) {
        __syncthreads();
        for (int i = t; i < 64 * 96; i += 512) {
            int f = i / 96, kp = i % 96;
            *(uint32_t*)&W1s[f * SA + kp * 2] = ((const uint32_t*)g_W116)[(fc + f) * 96 + kp];
        }
        __syncthreads();
        float hacc[4][4];
#pragma unroll
        for (int n = 0; n < 4; n++)
#pragma unroll
            for (int q = 0; q < 4; q++) hacc[n][q] = 0.f;
#pragma unroll
        for (int kk = 0; kk < 12; kk++) {
            int kb = kk * 16;
            uint32_t a0 = ld_u32h(&Xh[(r0 + lr) * SA + kb + lk]);
            uint32_t a1 = ld_u32h(&Xh[(r0 + lr + 8) * SA + kb + lk]);
            uint32_t a2 = ld_u32h(&Xh[(r0 + lr) * SA + kb + lk + 8]);
            uint32_t a3 = ld_u32h(&Xh[(r0 + lr + 8) * SA + kb + lk + 8]);
#pragma unroll
            for (int nt = 0; nt < 4; nt++) {
                uint32_t b0 = ld_u32h(&W1s[(c0h + nt * 8 + lr) * SA + kb + lk]);
                uint32_t b1r = ld_u32h(&W1s[(c0h + nt * 8 + lr) * SA + kb + lk + 8]);
                mma16816h(hacc[nt], a0, a1, a2, a3, b0, b1r);
            }
        }
#pragma unroll
        for (int nt = 0; nt < 4; nt++) {
            int col = c0h + nt * 8 + lk;
            int fg = fc + col;
            float bv0 = b1[fg], bv1 = b1[fg + 1];
            *(uint32_t*)&Hh[(r0 + lr) * SH + col] =
                pack_h2f(fmaxf(hacc[nt][0] + bv0, 0.f), fmaxf(hacc[nt][1] + bv1, 0.f));
            *(uint32_t*)&Hh[(r0 + lr + 8) * SH + col] =
                pack_h2f(fmaxf(hacc[nt][2] + bv0, 0.f), fmaxf(hacc[nt][3] + bv1, 0.f));
        }
        __syncthreads();
        for (int i = t; i < DMODEL * 32; i += 512) {
            int d = i / 32, kp = i % 32;
            *(uint32_t*)&W2s[d * SH + kp * 2] = ((const uint32_t*)g_W216)[d * (DFFN / 2) + (fc >> 1) + kp];
        }
        __syncthreads();
#pragma unroll
        for (int kk = 0; kk < 4; kk++) {
            int kb = kk * 16;
            uint32_t a0 = ld_u32h(&Hh[(r0 + lr) * SH + kb + lk]);
            uint32_t a1 = ld_u32h(&Hh[(r0 + lr + 8) * SH + kb + lk]);
            uint32_t a2 = ld_u32h(&Hh[(r0 + lr) * SH + kb + lk + 8]);
            uint32_t a3 = ld_u32h(&Hh[(r0 + lr + 8) * SH + kb + lk + 8]);
#pragma unroll
            for (int nt = 0; nt < 12; nt++) {
                uint32_t b0 = ld_u32h(&W2s[(c0y + nt * 8 + lr) * SH + kb + lk]);
                uint32_t b1r = ld_u32h(&W2s[(c0y + nt * 8 + lr) * SH + kb + lk + 8]);
                mma16816h(y[nt], a0, a1, a2, a3, b0, b1r);
            }
        }
    }
    __syncthreads();
#pragma unroll
    for (int nt = 0; nt < 12; nt++) {
        int col = c0y + nt * 8 + lk;
        int row = r0 + lr;
        Ys[row * SA + col]           = y[nt][0];
        Ys[row * SA + col + 1]       = y[nt][1];
        Ys[(row + 8) * SA + col]     = y[nt][2];
        Ys[(row + 8) * SA + col + 1] = y[nt][3];
    }
    __syncthreads();
    for (int rr = 0; rr < 8; rr++) {
        int r = w * 8 + rr;
        float v[6];
#pragma unroll
        for (int c = 0; c < 6; c++) {
            int d = lane * 6 + c;
            v[c] = Ys[r * SA + d] + b2[d] + g_X1[(r0g + r) * DMODEL + d];
        }
        float s = 0.f;
#pragma unroll
        for (int c = 0; c < 6; c++) s += v[c];
#pragma unroll
        for (int o = 16; o; o >>= 1) s += __shfl_xor_sync(0xffffffffu, s, o);
        float mean = s * (1.0f / 192.0f);
        float vs = 0.f;
#pragma unroll
        for (int c = 0; c < 6; c++) { float d0 = v[c] - mean; vs += d0 * d0; }
#pragma unroll
        for (int o = 16; o; o >>= 1) vs += __shfl_xor_sync(0xffffffffu, vs, o);
        float inv = rsqrtf(vs * (1.0f / 192.0f) + LN_EPS);
#pragma unroll
        for (int c = 0; c < 6; c++) {
            int d = lane * 6 + c;
            out[(r0g + r) * DMODEL + d] = (v[c] - mean) * inv * ln2g[d] + ln2b[d];
        }
    }
}

// ============================================================================
extern "C" void kernel_launch(void* const* d_in, const int* in_sizes, int n_in,
                              void* d_out, int out_size)
{
    const float* src  = (const float*)d_in[0];
    const int*   vcrd = (const int*)d_in[1];
    const float* boxf = (const float*)d_in[2];
    const int*   bcrd = (const int*)d_in[3];
    const float* pos  = (const float*)d_in[4];
    const float* boxp = (const float*)d_in[5];
    const int*   vind = (const int*)d_in[6];
    const float* Wq = (const float*)d_in[7];
    const float* bq = (const float*)d_in[8];
    const float* Wk = (const float*)d_in[9];
    const float* bk = (const float*)d_in[10];
    const float* Wv = (const float*)d_in[11];
    const float* bv = (const float*)d_in[12];
    const float* Wo = (const float*)d_in[13];
    const float* bo = (const float*)d_in[14];
    const float* W1 = (const float*)d_in[15];
    const float* b1 = (const float*)d_in[16];
    const float* W2 = (const float*)d_in[17];
    const float* b2 = (const float*)d_in[18];
    const float* g1 = (const float*)d_in[19];
    const float* lb1 = (const float*)d_in[20];
    const float* g2 = (const float*)d_in[21];
    const float* lb2 = (const float*)d_in[22];
    float* out = (float*)d_out;

    const int SMEM_PROJ = 102656;
    const int SMEM_ATTN = 50048;
    const int SMEM_FFN  = 102400;

    cudaFuncSetAttribute(qproj_mma_kernel, cudaFuncAttributeMaxDynamicSharedMemorySize, SMEM_PROJ);
    cudaFuncSetAttribute(oproj_mma_kernel, cudaFuncAttributeMaxDynamicSharedMemorySize, SMEM_PROJ);
    cudaFuncSetAttribute(attn_mma_kernel, cudaFuncAttributeMaxDynamicSharedMemorySize, SMEM_ATTN);
    cudaFuncSetAttribute(ffn_mma_kernel, cudaFuncAttributeMaxDynamicSharedMemorySize, SMEM_FFN);

    split_weights_kernel<<<3360, 256>>>(Wq, Wo, W1, W2);
    kv_kernel<<<MTOK / 64, 256>>>(boxf, boxp, Wk, bk, Wv, bv);
    qproj_mma_kernel<<<NTOT / 64, 256, SMEM_PROJ>>>(src, pos, vind, bq);
    attn_mma_kernel<<<dim3(NTOT / 64, NHEAD), 256, SMEM_ATTN>>>(vind, vcrd, bcrd);
    oproj_mma_kernel<<<NTOT / 64, 256, SMEM_PROJ>>>(src, vind, bo, g1, lb1);
    ffn_mma_kernel<<<NTOT / 128, 512, SMEM_FFN>>>(b1, b2, g2, lb2, out);
}